// round 10
// baseline (speedup 1.0000x reference)
#include <cuda_runtime.h>
#include <cuda_bf16.h>
#include <cstddef>
#include <cstdint>

// Problem constants
#define cH   128
#define cNU  200000
#define cNM  80000
#define cE   2000000
#define cEL  500000
#define cFD  512

#define TILE 1024
#define TU   ((cNU + TILE - 1) / TILE)   // 196
#define TM   ((cNM + TILE - 1) / TILE)   // 79

// ---------------- scratch (device globals) ----------------
__device__ float g_movie_x[(size_t)cNM * cH];
__device__ float g_movie_h[(size_t)cNM * cH];
__device__ float g_P1[(size_t)cNM * cH];      // movie_x @ Wl1_mu
__device__ float g_P2[(size_t)cNM * cH];      // movie_h @ Wl2_mu
__device__ float g_Q9[(size_t)cNM * cH];      // movie_h @ Wr2_um + bl2_um
__device__ float g_user_h [(size_t)cNU * cH];
__device__ float g_aggP2 [(size_t)cNU * cH];
__device__ float g_aggM2 [(size_t)cNM * cH];
__device__ float g_movie_o[(size_t)cNM * cH];
__device__ float g_user_o [(size_t)cNU * cH];
__device__ int   g_deg_u[cNU];
__device__ int   g_deg_m[cNM];
__device__ int   g_offU[cNU + 1];
__device__ int   g_offM[cNM + 1];
__device__ int   g_curU[cNU];
__device__ int   g_curM[cNM];
__device__ int   g_csrU[cE];
__device__ int   g_csrM[cE];
__device__ int   g_partU[TU];
__device__ int   g_partM[TM];
__device__ float g_vecs[2 * cH];
__device__ float g_zero[cH];

// ---------------- utility ----------------
__global__ void zero2_kernel(int* p1, int n1, int* p2, int n2) {
    int i = blockIdx.x * blockDim.x + threadIdx.x;
    int stride = gridDim.x * blockDim.x;
    for (int k = i; k < n1; k += stride) p1[k] = 0;
    for (int k = i; k < n2; k += stride) p2[k] = 0;
}

// ---- device bodies ----
__device__ __forceinline__ void deg_body(const int* __restrict__ src, const int* __restrict__ dst,
                                         int* __restrict__ du, int* __restrict__ dm,
                                         int E, int vbid, int vgrid) {
    int i = vbid * 256 + threadIdx.x;
    int stride = vgrid * 256;
    for (; i < E; i += stride) {
        atomicAdd(&du[src[i]], 1);
        atomicAdd(&dm[dst[i]], 1);
    }
}

__device__ __forceinline__ void scatter_body(const int* __restrict__ src, const int* __restrict__ dst,
                                             int* __restrict__ curU, int* __restrict__ curM,
                                             int* __restrict__ csrU, int* __restrict__ csrM,
                                             int E, int vbid, int vgrid) {
    int i = vbid * 256 + threadIdx.x;
    int stride = vgrid * 256;
    for (; i < E; i += stride) {
        int s = src[i];
        int d = dst[i];
        int p = atomicAdd(&curU[s], 1);
        csrU[p] = d;
        int q = atomicAdd(&curM[d], 1);
        csrM[q] = s;
    }
}

__device__ __forceinline__ void vec_body(const float* __restrict__ user_init,
                                         const float* __restrict__ Wl1_um,
                                         const float* __restrict__ Wr1_mu,
                                         const float* __restrict__ bl1_mu,
                                         float* __restrict__ vecs) {
    int j = threadIdx.x;
    if (j >= cH) return;
    float s1 = 0.f, s2 = 0.f;
    for (int k = 0; k < cH; k++) {
        float u = user_init[k];
        s1 = fmaf(u, Wl1_um[k * cH + j], s1);
        s2 = fmaf(u, Wr1_mu[k * cH + j], s2);
    }
    vecs[j]      = s1;
    vecs[cH + j] = bl1_mu[j] + s2;
}

// single-matrix CSR mean aggregation; optional (bias + relu) epilogue
template<bool RELUB>
__device__ __forceinline__ void agg_one_body(const int* __restrict__ off, const int* __restrict__ csr,
                                             const float* __restrict__ X, const float* __restrict__ addv,
                                             float* __restrict__ outp, int N, int vbid, int vgrid) {
    int w    = vbid * 8 + (threadIdx.x >> 5);
    int lane = threadIdx.x & 31;
    int nw   = vgrid * 8;
    float4 cv = make_float4(0.f, 0.f, 0.f, 0.f);
    if (RELUB) cv = ((const float4*)addv)[lane];
    for (int u = w; u < N; u += nw) {
        int s = off[u], e = off[u + 1];
        float4 a1 = make_float4(0.f, 0.f, 0.f, 0.f);
        float4 a2 = make_float4(0.f, 0.f, 0.f, 0.f);
        int i = s;
        for (; i + 1 < e; i += 2) {
            int d0 = csr[i];
            int d1 = csr[i + 1];
            float4 v0 = ((const float4*)(X + (size_t)d0 * 128))[lane];
            float4 v1 = ((const float4*)(X + (size_t)d1 * 128))[lane];
            a1.x += v0.x; a1.y += v0.y; a1.z += v0.z; a1.w += v0.w;
            a2.x += v1.x; a2.y += v1.y; a2.z += v1.z; a2.w += v1.w;
        }
        if (i < e) {
            int d0 = csr[i];
            float4 v0 = ((const float4*)(X + (size_t)d0 * 128))[lane];
            a1.x += v0.x; a1.y += v0.y; a1.z += v0.z; a1.w += v0.w;
        }
        float sc = (e > s) ? 1.f / (float)(e - s) : 0.f;
        float4 o;
        o.x = (a1.x + a2.x) * sc + cv.x;
        o.y = (a1.y + a2.y) * sc + cv.y;
        o.z = (a1.z + a2.z) * sc + cv.z;
        o.w = (a1.w + a2.w) * sc + cv.w;
        if (RELUB) {
            o.x = fmaxf(o.x, 0.f); o.y = fmaxf(o.y, 0.f);
            o.z = fmaxf(o.z, 0.f); o.w = fmaxf(o.w, 0.f);
        }
        ((float4*)(outp + (size_t)u * 128))[lane] = o;
    }
}

__device__ __forceinline__ void agg_movie_body(const int* __restrict__ off, const int* __restrict__ csr,
                                               const float* __restrict__ uh,
                                               float* __restrict__ aM2, int NM, int vbid, int vgrid) {
    agg_one_body<false>(off, csr, uh, nullptr, aM2, NM, vbid, vgrid);
}

// ---- parallel scan ----
__global__ void partial_kernel(const int* __restrict__ degU, const int* __restrict__ degM,
                               int* __restrict__ partU, int* __restrict__ partM) {
    int b = blockIdx.x;
    const int* deg; int* part; int n, tile;
    if (b < TU) { deg = degU; part = partU; n = cNU; tile = b; }
    else        { deg = degM; part = partM; n = cNM; tile = b - TU; }

    int tid = threadIdx.x;
    int base = tile * TILE + tid * 4;
    int s = 0;
    #pragma unroll
    for (int j = 0; j < 4; j++) {
        int i = base + j;
        if (i < n) s += deg[i];
    }
    __shared__ int wsum[8];
    int lane = tid & 31, wid = tid >> 5;
    #pragma unroll
    for (int o = 16; o > 0; o >>= 1) s += __shfl_down_sync(0xffffffffu, s, o);
    if (lane == 0) wsum[wid] = s;
    __syncthreads();
    if (tid == 0) {
        int t = 0;
        #pragma unroll
        for (int w = 0; w < 8; w++) t += wsum[w];
        part[tile] = t;
    }
}

__global__ void scanpart_kernel(int* __restrict__ partU, int* __restrict__ partM) {
    int* part = (blockIdx.x == 0) ? partU : partM;
    int cnt   = (blockIdx.x == 0) ? TU : TM;
    int tid = threadIdx.x, lane = tid & 31, wid = tid >> 5;
    __shared__ int wsum[8];
    int v = (tid < cnt) ? part[tid] : 0;
    int x = v;
    #pragma unroll
    for (int o = 1; o < 32; o <<= 1) {
        int t = __shfl_up_sync(0xffffffffu, x, o);
        if (lane >= o) x += t;
    }
    if (lane == 31) wsum[wid] = x;
    __syncthreads();
    if (wid == 0) {
        int s = (lane < 8) ? wsum[lane] : 0;
        #pragma unroll
        for (int o = 1; o < 8; o <<= 1) {
            int t = __shfl_up_sync(0xffffffffu, s, o);
            if (lane >= o) s += t;
        }
        if (lane < 8) wsum[lane] = s;
    }
    __syncthreads();
    int incl = x + ((wid > 0) ? wsum[wid - 1] : 0);
    if (tid < cnt) part[tid] = incl - v;
}

__global__ void phase3_kernel(const int* __restrict__ degU, const int* __restrict__ degM,
                              const int* __restrict__ partU, const int* __restrict__ partM,
                              int* __restrict__ offU, int* __restrict__ curU,
                              int* __restrict__ offM, int* __restrict__ curM) {
    int b = blockIdx.x;
    const int* deg; const int* part; int* off; int* cur; int n, tile;
    if (b < TU) { deg = degU; part = partU; off = offU; cur = curU; n = cNU; tile = b; }
    else        { deg = degM; part = partM; off = offM; cur = curM; n = cNM; tile = b - TU; }

    int tid = threadIdx.x, lane = tid & 31, wid = tid >> 5;
    if (b == 0 && tid == 0) { offU[cNU] = cE; offM[cNM] = cE; }

    int base = tile * TILE + tid * 4;
    int v[4];
    int s = 0;
    #pragma unroll
    for (int j = 0; j < 4; j++) {
        int i = base + j;
        v[j] = (i < n) ? deg[i] : 0;
        s += v[j];
    }
    __shared__ int wsum[8];
    int x = s;
    #pragma unroll
    for (int o = 1; o < 32; o <<= 1) {
        int t = __shfl_up_sync(0xffffffffu, x, o);
        if (lane >= o) x += t;
    }
    if (lane == 31) wsum[wid] = x;
    __syncthreads();
    if (wid == 0) {
        int t = (lane < 8) ? wsum[lane] : 0;
        #pragma unroll
        for (int o = 1; o < 8; o <<= 1) {
            int u = __shfl_up_sync(0xffffffffu, t, o);
            if (lane >= o) t += u;
        }
        if (lane < 8) wsum[lane] = t;
    }
    __syncthreads();
    int excl = x - s + ((wid > 0) ? wsum[wid - 1] : 0);
    int run = part[tile] + excl;
    #pragma unroll
    for (int j = 0; j < 4; j++) {
        int i = base + j;
        if (i < n) { off[i] = run; cur[i] = run; run += v[j]; }
    }
}

// ---------------- tensor-core SGEMM via split-bf16 ----------------
#define BK   16
#define ASTR 24
#define BSTR 136

__device__ __forceinline__ unsigned pack_bf16(__nv_bfloat16 a, __nv_bfloat16 b) {
    __nv_bfloat162 t = __halves2bfloat162(a, b);
    return reinterpret_cast<unsigned&>(t);
}
__device__ __forceinline__ void split_f32(float x, __nv_bfloat16& h, __nv_bfloat16& l) {
    h = __float2bfloat16(x);
    l = __float2bfloat16(x - __bfloat162float(h));
}
__device__ __forceinline__ void ldsm_x4(uint32_t* r, uint32_t addr) {
    asm volatile("ldmatrix.sync.aligned.m8n8.x4.shared.b16 {%0,%1,%2,%3}, [%4];"
                 : "=r"(r[0]), "=r"(r[1]), "=r"(r[2]), "=r"(r[3]) : "r"(addr));
}
__device__ __forceinline__ void ldsm_x4_t(uint32_t* r, uint32_t addr) {
    asm volatile("ldmatrix.sync.aligned.m8n8.x4.trans.shared.b16 {%0,%1,%2,%3}, [%4];"
                 : "=r"(r[0]), "=r"(r[1]), "=r"(r[2]), "=r"(r[3]) : "r"(addr));
}
__device__ __forceinline__ void mma_bf16(float* d, const uint32_t* a, const uint32_t* b) {
    asm volatile("mma.sync.aligned.m16n8k16.row.col.f32.bf16.bf16.f32 "
                 "{%0,%1,%2,%3}, {%4,%5,%6,%7}, {%8,%9}, {%0,%1,%2,%3};"
                 : "+f"(d[0]), "+f"(d[1]), "+f"(d[2]), "+f"(d[3])
                 : "r"(a[0]), "r"(a[1]), "r"(a[2]), "r"(a[3]), "r"(b[0]), "r"(b[1]));
}

template<bool BIAS_SEL, bool RELU, bool ADD_D>
__device__ __forceinline__ void gemm128_body(
    const float* __restrict__ A1, const float* __restrict__ A2,
    const float* __restrict__ B1, const float* __restrict__ B2,
    float* __restrict__ C,
    const float* __restrict__ bias, const float* __restrict__ vsel,
    const int* __restrict__ deg, const float* __restrict__ Dm,
    int M, int KT1, int KT2, int bid) {
    __shared__ __nv_bfloat16 Ah[2][128][ASTR];
    __shared__ __nv_bfloat16 Al[2][128][ASTR];
    __shared__ __nv_bfloat16 Bh[2][BK][BSTR];
    __shared__ __nv_bfloat16 Bl[2][BK][BSTR];
    __shared__ float sBias[128];
    __shared__ float sVsel[128];

    const int tid  = threadIdx.x;
    const int lane = tid & 31;
    const int wid  = tid >> 5;
    const int wm   = wid & 3;
    const int wn   = wid >> 2;
    const int m0   = bid * 128;
    const int lda1 = KT1 * BK;
    const int lda2 = KT2 * BK;
    const int KT   = KT1 + KT2;

    if (tid < 128) {
        sBias[tid] = bias[tid];
        if (BIAS_SEL) sVsel[tid] = vsel[tid];
    }

    const int arow0 = tid >> 2;
    const int ac4   = (tid & 3) << 2;
    const int brow0 = tid >> 5;
    const int bn4   = (tid & 31) << 2;

    float4 rA[2], rB[2];

    auto loadTile = [&](int t) {
        const bool first = (t < KT1);
        #pragma unroll
        for (int i = 0; i < 2; i++) {
            int row = arow0 + i * 64;
            int m = m0 + row;
            float4 v = make_float4(0.f, 0.f, 0.f, 0.f);
            if (m < M) {
                const float* p = first ? (A1 + (size_t)m * lda1 + t * BK + ac4)
                                       : (A2 + (size_t)m * lda2 + (t - KT1) * BK + ac4);
                v = *(const float4*)p;
            }
            rA[i] = v;
        }
        #pragma unroll
        for (int i = 0; i < 2; i++) {
            int row = brow0 + i * 8;
            const float* p = first ? (B1 + (size_t)(t * BK + row) * 128 + bn4)
                                   : (B2 + (size_t)((t - KT1) * BK + row) * 128 + bn4);
            rB[i] = *(const float4*)p;
        }
    };
    auto storeTile = [&](int buf) {
        #pragma unroll
        for (int i = 0; i < 2; i++) {
            int row = arow0 + i * 64;
            const float* v = &rA[i].x;
            __nv_bfloat16 h[4], l[4];
            #pragma unroll
            for (int j = 0; j < 4; j++) split_f32(v[j], h[j], l[j]);
            *(uint2*)&Ah[buf][row][ac4] = make_uint2(pack_bf16(h[0], h[1]), pack_bf16(h[2], h[3]));
            *(uint2*)&Al[buf][row][ac4] = make_uint2(pack_bf16(l[0], l[1]), pack_bf16(l[2], l[3]));
        }
        #pragma unroll
        for (int i = 0; i < 2; i++) {
            int row = brow0 + i * 8;
            const float* v = &rB[i].x;
            __nv_bfloat16 h[4], l[4];
            #pragma unroll
            for (int j = 0; j < 4; j++) split_f32(v[j], h[j], l[j]);
            *(uint2*)&Bh[buf][row][bn4] = make_uint2(pack_bf16(h[0], h[1]), pack_bf16(h[2], h[3]));
            *(uint2*)&Bl[buf][row][bn4] = make_uint2(pack_bf16(l[0], l[1]), pack_bf16(l[2], l[3]));
        }
    };

    float d[2][8][4];
    #pragma unroll
    for (int mt = 0; mt < 2; mt++)
        #pragma unroll
        for (int nt = 0; nt < 8; nt++)
            #pragma unroll
            for (int j = 0; j < 4; j++) d[mt][nt][j] = 0.f;

    const int ar = lane & 15;
    const int ac = (lane >> 4) << 3;
    const int br = lane & 15;
    const int bc = wn * 64 + ((lane >> 4) << 3);

    loadTile(0);
    storeTile(0);
    __syncthreads();

    for (int t = 0; t < KT; t++) {
        const int cb = t & 1;
        if (t + 1 < KT) loadTile(t + 1);

        uint32_t fah[2][4], fal[2][4];
        #pragma unroll
        for (int mt = 0; mt < 2; mt++) {
            int row = wm * 32 + mt * 16 + ar;
            ldsm_x4(fah[mt], (uint32_t)__cvta_generic_to_shared(&Ah[cb][row][ac]));
            ldsm_x4(fal[mt], (uint32_t)__cvta_generic_to_shared(&Al[cb][row][ac]));
        }
        #pragma unroll
        for (int ntp = 0; ntp < 4; ntp++) {
            uint32_t fbh[4], fbl[4];
            ldsm_x4_t(fbh, (uint32_t)__cvta_generic_to_shared(&Bh[cb][br][bc + ntp * 16]));
            ldsm_x4_t(fbl, (uint32_t)__cvta_generic_to_shared(&Bl[cb][br][bc + ntp * 16]));
            #pragma unroll
            for (int mt = 0; mt < 2; mt++) {
                mma_bf16(d[mt][2 * ntp],     fah[mt], fbh);
                mma_bf16(d[mt][2 * ntp],     fal[mt], fbh);
                mma_bf16(d[mt][2 * ntp],     fah[mt], fbl);
                mma_bf16(d[mt][2 * ntp + 1], fah[mt], fbh + 2);
                mma_bf16(d[mt][2 * ntp + 1], fal[mt], fbh + 2);
                mma_bf16(d[mt][2 * ntp + 1], fah[mt], fbl + 2);
            }
        }
        if (t + 1 < KT) storeTile((t + 1) & 1);
        __syncthreads();
    }

    const int rb  = m0 + wm * 32 + (lane >> 2);
    const int cb0 = wn * 64 + (lane & 3) * 2;
    #pragma unroll
    for (int mt = 0; mt < 2; mt++) {
        #pragma unroll
        for (int h = 0; h < 2; h++) {
            int m = rb + mt * 16 + h * 8;
            if (m >= M) continue;
            float sel = 0.f;
            if (BIAS_SEL) sel = (deg[m] > 0) ? 1.f : 0.f;
            #pragma unroll
            for (int nt = 0; nt < 8; nt++) {
                int col = cb0 + nt * 8;
                float x = d[mt][nt][h * 2 + 0] + sBias[col];
                float y = d[mt][nt][h * 2 + 1] + sBias[col + 1];
                if (BIAS_SEL) { x += sel * sVsel[col]; y += sel * sVsel[col + 1]; }
                if (ADD_D) {
                    float2 dv = *(const float2*)&Dm[(size_t)m * 128 + col];
                    x += dv.x; y += dv.y;
                }
                if (RELU) { x = fmaxf(x, 0.f); y = fmaxf(y, 0.f); }
                *(float2*)&C[(size_t)m * 128 + col] = make_float2(x, y);
            }
        }
    }
}

template<bool BIAS_SEL, bool RELU, bool ADD_D>
__global__ void __launch_bounds__(256)
gemm128_kernel(const float* A1, const float* A2, const float* B1, const float* B2,
               float* C, const float* bias, const float* vsel, const int* deg,
               const float* Dm, int M, int KT1, int KT2) {
    gemm128_body<BIAS_SEL, RELU, ADD_D>(A1, A2, B1, B2, C, bias, vsel, deg, Dm, M, KT1, KT2, blockIdx.x);
}

// ---------------- fused kernels ----------------
// fusedA: GEMM4 (movie_x) || deg || vec.
__global__ void __launch_bounds__(256)
fusedA_kernel(const float* __restrict__ movie_feats, const float* __restrict__ Wm, const float* __restrict__ bm,
              float* __restrict__ movie_x,
              const int* __restrict__ src, const int* __restrict__ dst,
              int* __restrict__ du, int* __restrict__ dm,
              const float* __restrict__ user_init, const float* __restrict__ Wl1_um,
              const float* __restrict__ Wr1_mu, const float* __restrict__ bl1_mu,
              float* __restrict__ vecs,
              int GA, int DEGB) {
    int bid = blockIdx.x;
    int q = bid >> 2, r = bid & 3;
    if (r == 0 && q < GA) {
        gemm128_body<false, false, false>(movie_feats, nullptr, Wm, nullptr, movie_x,
                                          bm, nullptr, nullptr, nullptr, cNM, cFD / BK, 0, q);
    } else {
        int before = min((bid + 3) >> 2, GA);
        int did = bid - before;
        if (did < DEGB) deg_body(src, dst, du, dm, cE, did, DEGB);
        else            vec_body(user_init, Wl1_um, Wr1_mu, bl1_mu, vecs);
    }
}

// fusedB: GEMM5 (movie_h) || P1 || scatter.
__global__ void __launch_bounds__(256)
fusedB_kernel(const float* __restrict__ movie_x,
              const float* __restrict__ Wr1_um, const float* __restrict__ Wl1_mu,
              float* __restrict__ movie_h, float* __restrict__ P1,
              const float* __restrict__ bl1_um, const float* __restrict__ vsel, const int* __restrict__ deg_m,
              const float* __restrict__ zero,
              const int* __restrict__ src, const int* __restrict__ dst,
              int* __restrict__ curU, int* __restrict__ curM,
              int* __restrict__ csrU, int* __restrict__ csrM,
              int GM_, int GA, int SCB) {
    int bid = blockIdx.x;
    int q = bid >> 2, r = bid & 3;
    if (r == 0 && q < GA) {
        if (q < GM_) {
            gemm128_body<true, true, false>(movie_x, nullptr, Wr1_um, nullptr, movie_h,
                                            bl1_um, vsel, deg_m, nullptr, cNM, cH / BK, 0, q);
        } else {
            gemm128_body<false, false, false>(movie_x, nullptr, Wl1_mu, nullptr, P1,
                                              zero, nullptr, nullptr, nullptr, cNM, cH / BK, 0, q - GM_);
        }
    } else {
        int before = min((bid + 3) >> 2, GA);
        int did = bid - before;
        if (did < SCB) scatter_body(src, dst, curU, curM, csrU, csrM, cE, did, SCB);
    }
}

// fusedP: P2-GEMM (movie_h@Wl2_mu) || agg_userH (P1 -> user_h).  mod-8 interleave.
__global__ void __launch_bounds__(256)
fusedP_kernel(const float* __restrict__ movie_h, const float* __restrict__ Wl2_mu,
              float* __restrict__ P2, const float* __restrict__ zero,
              const int* __restrict__ offU, const int* __restrict__ csrU,
              const float* __restrict__ P1, const float* __restrict__ vecs,
              float* __restrict__ user_h,
              int GA, int AGB) {
    int bid = blockIdx.x;
    int q = bid >> 3, r = bid & 7;
    if (r == 0 && q < GA) {
        gemm128_body<false, false, false>(movie_h, nullptr, Wl2_mu, nullptr, P2,
                                          zero, nullptr, nullptr, nullptr, cNM, cH / BK, 0, q);
    } else {
        int before = min((bid + 7) >> 3, GA);
        int aid = bid - before;
        if (aid < AGB) agg_one_body<true>(offU, csrU, P1, vecs + cH, user_h, cNU, aid, AGB);
    }
}

// fusedQ: Q9-GEMM (movie_h@Wr2_um + bl2_um) || agg_userP2 (P2 -> aggP2).  mod-8 interleave.
__global__ void __launch_bounds__(256)
fusedQ_kernel(const float* __restrict__ movie_h, const float* __restrict__ Wr2_um,
              float* __restrict__ Q9, const float* __restrict__ bl2_um,
              const int* __restrict__ offU, const int* __restrict__ csrU,
              const float* __restrict__ P2, float* __restrict__ aggP2,
              int GA, int AGB) {
    int bid = blockIdx.x;
    int q = bid >> 3, r = bid & 7;
    if (r == 0 && q < GA) {
        gemm128_body<false, false, false>(movie_h, nullptr, Wr2_um, nullptr, Q9,
                                          bl2_um, nullptr, nullptr, nullptr, cNM, cH / BK, 0, q);
    } else {
        int before = min((bid + 7) >> 3, GA);
        int aid = bid - before;
        if (aid < AGB) agg_one_body<false>(offU, csrU, P2, nullptr, aggP2, cNU, aid, AGB);
    }
}

// fusedC: GEMM10' (user_o = user_h@Wr2_mu + bl2_mu + aggP2) || agg_movie.
__global__ void __launch_bounds__(256)
fusedC_kernel(const float* __restrict__ user_h, const float* __restrict__ Wr2_mu,
              float* __restrict__ user_o, const float* __restrict__ bl2_mu,
              const float* __restrict__ aggP2,
              const int* __restrict__ offM, const int* __restrict__ csrM,
              float* __restrict__ aggM2,
              int GA, int AGB) {
    int bid = blockIdx.x;
    int q = bid >> 1, r = bid & 1;
    if (r == 0 && q < GA) {
        gemm128_body<false, false, true>(user_h, nullptr, Wr2_mu, nullptr, user_o,
                                         bl2_mu, nullptr, nullptr, aggP2, cNU, cH / BK, 0, q);
    } else {
        int before = min((bid + 1) >> 1, GA);
        int aid = bid - before;
        if (aid < AGB) agg_movie_body(offM, csrM, user_h, aggM2, cNM, aid, AGB);
    }
}

// ---------------- final edge dot products (2-edge unroll) ----------------
__global__ void dot_kernel(const int* __restrict__ lu, const int* __restrict__ lm,
                           const float* __restrict__ U, const float* __restrict__ Mo,
                           float* __restrict__ out, int EL) {
    int w    = (blockIdx.x * blockDim.x + threadIdx.x) >> 5;
    int lane = threadIdx.x & 31;
    int nw   = (gridDim.x * blockDim.x) >> 5;
    for (int i = w; i < EL; i += 2 * nw) {
        int i2 = i + nw;
        bool has2 = (i2 < EL);
        int u0 = lu[i], m0 = lm[i];
        float4 a0 = ((const float4*)(U  + (size_t)u0 * 128))[lane];
        float4 b0 = ((const float4*)(Mo + (size_t)m0 * 128))[lane];
        float p0 = a0.x * b0.x + a0.y * b0.y + a0.z * b0.z + a0.w * b0.w;
        float p1 = 0.f;
        if (has2) {
            int u1 = lu[i2], m1 = lm[i2];
            float4 a1 = ((const float4*)(U  + (size_t)u1 * 128))[lane];
            float4 b1 = ((const float4*)(Mo + (size_t)m1 * 128))[lane];
            p1 = a1.x * b1.x + a1.y * b1.y + a1.z * b1.z + a1.w * b1.w;
        }
        #pragma unroll
        for (int off = 16; off > 0; off >>= 1) {
            p0 += __shfl_xor_sync(0xFFFFFFFFu, p0, off);
            p1 += __shfl_xor_sync(0xFFFFFFFFu, p1, off);
        }
        if (lane == 0) {
            out[i] = p0;
            if (has2) out[i2] = p1;
        }
    }
}

// ---------------- launch ----------------
extern "C" void kernel_launch(void* const* d_in, const int* in_sizes, int n_in,
                              void* d_out, int out_size) {
    const float* movie_feats = (const float*)d_in[0];
    const float* user_init   = (const float*)d_in[1];
    const int*   edge_src    = (const int*)d_in[2];
    const int*   edge_dst    = (const int*)d_in[3];
    const int*   lbl_user    = (const int*)d_in[4];
    const int*   lbl_movie   = (const int*)d_in[5];
    const int wi = (n_in >= 21) ? 7 : 6;
    const float* Wm     = (const float*)d_in[wi + 0];
    const float* bm     = (const float*)d_in[wi + 1];
    const float* Wl1_um = (const float*)d_in[wi + 2];
    const float* bl1_um = (const float*)d_in[wi + 3];
    const float* Wr1_um = (const float*)d_in[wi + 4];
    const float* Wl1_mu = (const float*)d_in[wi + 5];
    const float* bl1_mu = (const float*)d_in[wi + 6];
    const float* Wr1_mu = (const float*)d_in[wi + 7];
    const float* Wl2_um = (const float*)d_in[wi + 8];
    const float* bl2_um = (const float*)d_in[wi + 9];
    const float* Wr2_um = (const float*)d_in[wi + 10];
    const float* Wl2_mu = (const float*)d_in[wi + 11];
    const float* bl2_mu = (const float*)d_in[wi + 12];
    const float* Wr2_mu = (const float*)d_in[wi + 13];
    float* out = (float*)d_out;

    float *movie_x, *movie_h, *P1, *P2, *Q9, *user_h, *aggP2, *aggM2, *movie_o, *user_o, *vecs, *zero;
    int *deg_u, *deg_m, *offU, *offM, *curU, *curM, *csrU, *csrM, *partU, *partM;
    cudaGetSymbolAddress((void**)&movie_x, g_movie_x);
    cudaGetSymbolAddress((void**)&movie_h, g_movie_h);
    cudaGetSymbolAddress((void**)&P1,      g_P1);
    cudaGetSymbolAddress((void**)&P2,      g_P2);
    cudaGetSymbolAddress((void**)&Q9,      g_Q9);
    cudaGetSymbolAddress((void**)&user_h,  g_user_h);
    cudaGetSymbolAddress((void**)&aggP2,   g_aggP2);
    cudaGetSymbolAddress((void**)&aggM2,   g_aggM2);
    cudaGetSymbolAddress((void**)&movie_o, g_movie_o);
    cudaGetSymbolAddress((void**)&user_o,  g_user_o);
    cudaGetSymbolAddress((void**)&vecs,    g_vecs);
    cudaGetSymbolAddress((void**)&zero,    g_zero);
    cudaGetSymbolAddress((void**)&deg_u,   g_deg_u);
    cudaGetSymbolAddress((void**)&deg_m,   g_deg_m);
    cudaGetSymbolAddress((void**)&offU,    g_offU);
    cudaGetSymbolAddress((void**)&offM,    g_offM);
    cudaGetSymbolAddress((void**)&curU,    g_curU);
    cudaGetSymbolAddress((void**)&curM,    g_curM);
    cudaGetSymbolAddress((void**)&csrU,    g_csrU);
    cudaGetSymbolAddress((void**)&csrM,    g_csrM);
    cudaGetSymbolAddress((void**)&partU,   g_partU);
    cudaGetSymbolAddress((void**)&partM,   g_partM);

    const int GM = (cNM + 127) / 128;   // 625
    const int GU = (cNU + 127) / 128;   // 1563

    // 1) zero degree counters
    zero2_kernel<<<384, 256>>>(deg_u, cNU, deg_m, cNM);

    // 2) fusedA: GEMM4 || deg || vec
    const int DEGB = 2048;
    fusedA_kernel<<<GM + DEGB + 1, 256>>>(movie_feats, Wm, bm, movie_x,
                                          edge_src, edge_dst, deg_u, deg_m,
                                          user_init, Wl1_um, Wr1_mu, bl1_mu, vecs,
                                          GM, DEGB);

    // 3) CSR offsets
    partial_kernel<<<TU + TM, 256>>>(deg_u, deg_m, partU, partM);
    scanpart_kernel<<<2, 256>>>(partU, partM);
    phase3_kernel<<<TU + TM, 256>>>(deg_u, deg_m, partU, partM, offU, curU, offM, curM);

    // 4) fusedB: GEMM5 || P1 || scatter
    {
        const int GA = 2 * GM;            // 1250 gemm virtual blocks
        const int grid = 4 * GA;          // 5000
        const int SCB = grid - GA;        // 3750 scatter virtual blocks
        fusedB_kernel<<<grid, 256>>>(movie_x, Wr1_um, Wl1_mu, movie_h, P1,
                                     bl1_um, vecs, deg_m, zero,
                                     edge_src, edge_dst, curU, curM, csrU, csrM,
                                     GM, GA, SCB);
    }

    // 5) fusedP: P2 GEMM || agg_userH (P1 -> user_h)
    {
        const int GA = GM;                // 625
        const int grid = 8 * GA;          // 5000
        const int AGB = grid - GA;        // 4375 agg virtual blocks
        fusedP_kernel<<<grid, 256>>>(movie_h, Wl2_mu, P2, zero,
                                     offU, csrU, P1, vecs, user_h, GA, AGB);
    }

    // 6) fusedQ: Q9 GEMM || agg_userP2 (P2 -> aggP2)
    {
        const int GA = GM;                // 625
        const int grid = 8 * GA;          // 5000
        const int AGB = grid - GA;        // 4375
        fusedQ_kernel<<<grid, 256>>>(movie_h, Wr2_um, Q9, bl2_um,
                                     offU, csrU, P2, aggP2, GA, AGB);
    }

    // 7) fusedC: GEMM10' (user_o) || agg_movie
    {
        const int gridC = 2 * GU;
        const int AGB = gridC - GU;
        fusedC_kernel<<<gridC, 256>>>(user_h, Wr2_mu, user_o, bl2_mu, aggP2,
                                      offM, csrM, aggM2, GU, AGB);
    }

    // 8) GEMM9': movie_o = aggM2 @ Wl2_um + Q9   (K=128, ADD_D; Q9 already has bl2_um)
    gemm128_kernel<false, false, true><<<GM, 256>>>(
        aggM2, nullptr, Wl2_um, nullptr, movie_o, zero, nullptr, nullptr, Q9,
        cNM, cH / BK, 0);

    // 9) final dot products
    dot_kernel<<<4736, 256>>>(lbl_user, lbl_movie, user_o, movie_o, out, cEL);

    (void)in_sizes; (void)out_size;
}

// round 11
// speedup vs baseline: 1.1162x; 1.1162x over previous
#include <cuda_runtime.h>
#include <cuda_bf16.h>
#include <cstddef>
#include <cstdint>

// Problem constants
#define cH   128
#define cNU  200000
#define cNM  80000
#define cE   2000000
#define cEL  500000
#define cFD  512

#define TILE 1024
#define TU   ((cNU + TILE - 1) / TILE)   // 196
#define TM   ((cNM + TILE - 1) / TILE)   // 79

// ---------------- scratch (device globals) ----------------
__device__ float g_movie_x[(size_t)cNM * cH];
__device__ float g_movie_h[(size_t)cNM * cH];
__device__ float g_P1[(size_t)cNM * cH];      // movie_x @ Wl1_mu
__device__ float g_P2[(size_t)cNM * cH];      // movie_h @ Wl2_mu
__device__ float g_user_h [(size_t)cNU * cH];
__device__ float g_aggP2 [(size_t)cNU * cH];
__device__ float g_aggM2 [(size_t)cNM * cH];
__device__ float g_movie_o[(size_t)cNM * cH];
__device__ float g_user_o [(size_t)cNU * cH];
__device__ int   g_deg_u[cNU];
__device__ int   g_deg_m[cNM];
__device__ int   g_offU[cNU + 1];
__device__ int   g_offM[cNM + 1];
__device__ int   g_curU[cNU];
__device__ int   g_curM[cNM];
__device__ int   g_csrU[cE];
__device__ int   g_csrM[cE];
__device__ int   g_partU[TU];
__device__ int   g_partM[TM];
__device__ float g_vecs[2 * cH];
__device__ float g_zero[cH];

// ---------------- utility ----------------
__global__ void zero2_kernel(int* p1, int n1, int* p2, int n2) {
    int i = blockIdx.x * blockDim.x + threadIdx.x;
    int stride = gridDim.x * blockDim.x;
    for (int k = i; k < n1; k += stride) p1[k] = 0;
    for (int k = i; k < n2; k += stride) p2[k] = 0;
}

// ---- device bodies ----
__device__ __forceinline__ void deg_body(const int* __restrict__ src, const int* __restrict__ dst,
                                         int* __restrict__ du, int* __restrict__ dm,
                                         int E, int vbid, int vgrid) {
    int i = vbid * 256 + threadIdx.x;
    int stride = vgrid * 256;
    for (; i < E; i += stride) {
        atomicAdd(&du[src[i]], 1);
        atomicAdd(&dm[dst[i]], 1);
    }
}

__device__ __forceinline__ void scatter_body(const int* __restrict__ src, const int* __restrict__ dst,
                                             int* __restrict__ curU, int* __restrict__ curM,
                                             int* __restrict__ csrU, int* __restrict__ csrM,
                                             int E, int vbid, int vgrid) {
    int i = vbid * 256 + threadIdx.x;
    int stride = vgrid * 256;
    for (; i < E; i += stride) {
        int s = src[i];
        int d = dst[i];
        int p = atomicAdd(&curU[s], 1);
        csrU[p] = d;
        int q = atomicAdd(&curM[d], 1);
        csrM[q] = s;
    }
}

__device__ __forceinline__ void vec_body(const float* __restrict__ user_init,
                                         const float* __restrict__ Wl1_um,
                                         const float* __restrict__ Wr1_mu,
                                         const float* __restrict__ bl1_mu,
                                         float* __restrict__ vecs) {
    int j = threadIdx.x;
    if (j >= cH) return;
    float s1 = 0.f, s2 = 0.f;
    for (int k = 0; k < cH; k++) {
        float u = user_init[k];
        s1 = fmaf(u, Wl1_um[k * cH + j], s1);
        s2 = fmaf(u, Wr1_mu[k * cH + j], s2);
    }
    vecs[j]      = s1;
    vecs[cH + j] = bl1_mu[j] + s2;
}

__device__ __forceinline__ void agg_movie_body(const int* __restrict__ off, const int* __restrict__ csr,
                                               const float* __restrict__ uh,
                                               float* __restrict__ aM2, int NM, int vbid, int vgrid) {
    int w    = vbid * 8 + (threadIdx.x >> 5);
    int lane = threadIdx.x & 31;
    int nw   = vgrid * 8;
    for (int m = w; m < NM; m += nw) {
        int s = off[m], e = off[m + 1];
        float4 a1 = make_float4(0.f, 0.f, 0.f, 0.f);
        float4 a2 = make_float4(0.f, 0.f, 0.f, 0.f);
        float4 a3 = make_float4(0.f, 0.f, 0.f, 0.f);
        float4 a4 = make_float4(0.f, 0.f, 0.f, 0.f);
        int i = s;
        for (; i + 3 < e; i += 4) {
            int d0 = csr[i];
            int d1 = csr[i + 1];
            int d2 = csr[i + 2];
            int d3 = csr[i + 3];
            float4 v0 = ((const float4*)(uh + (size_t)d0 * 128))[lane];
            float4 v1 = ((const float4*)(uh + (size_t)d1 * 128))[lane];
            float4 v2 = ((const float4*)(uh + (size_t)d2 * 128))[lane];
            float4 v3 = ((const float4*)(uh + (size_t)d3 * 128))[lane];
            a1.x += v0.x; a1.y += v0.y; a1.z += v0.z; a1.w += v0.w;
            a2.x += v1.x; a2.y += v1.y; a2.z += v1.z; a2.w += v1.w;
            a3.x += v2.x; a3.y += v2.y; a3.z += v2.z; a3.w += v2.w;
            a4.x += v3.x; a4.y += v3.y; a4.z += v3.z; a4.w += v3.w;
        }
        for (; i < e; i++) {
            int d0 = csr[i];
            float4 v0 = ((const float4*)(uh + (size_t)d0 * 128))[lane];
            a1.x += v0.x; a1.y += v0.y; a1.z += v0.z; a1.w += v0.w;
        }
        float sc = (e > s) ? 1.f / (float)(e - s) : 0.f;
        float4 o = make_float4((a1.x + a2.x + a3.x + a4.x) * sc,
                               (a1.y + a2.y + a3.y + a4.y) * sc,
                               (a1.z + a2.z + a3.z + a4.z) * sc,
                               (a1.w + a2.w + a3.w + a4.w) * sc);
        ((float4*)(aM2 + (size_t)m * 128))[lane] = o;
    }
}

// ---- parallel scan ----
__global__ void partial_kernel(const int* __restrict__ degU, const int* __restrict__ degM,
                               int* __restrict__ partU, int* __restrict__ partM) {
    int b = blockIdx.x;
    const int* deg; int* part; int n, tile;
    if (b < TU) { deg = degU; part = partU; n = cNU; tile = b; }
    else        { deg = degM; part = partM; n = cNM; tile = b - TU; }

    int tid = threadIdx.x;
    int base = tile * TILE + tid * 4;
    int s = 0;
    #pragma unroll
    for (int j = 0; j < 4; j++) {
        int i = base + j;
        if (i < n) s += deg[i];
    }
    __shared__ int wsum[8];
    int lane = tid & 31, wid = tid >> 5;
    #pragma unroll
    for (int o = 16; o > 0; o >>= 1) s += __shfl_down_sync(0xffffffffu, s, o);
    if (lane == 0) wsum[wid] = s;
    __syncthreads();
    if (tid == 0) {
        int t = 0;
        #pragma unroll
        for (int w = 0; w < 8; w++) t += wsum[w];
        part[tile] = t;
    }
}

__global__ void scanpart_kernel(int* __restrict__ partU, int* __restrict__ partM) {
    int* part = (blockIdx.x == 0) ? partU : partM;
    int cnt   = (blockIdx.x == 0) ? TU : TM;
    int tid = threadIdx.x, lane = tid & 31, wid = tid >> 5;
    __shared__ int wsum[8];
    int v = (tid < cnt) ? part[tid] : 0;
    int x = v;
    #pragma unroll
    for (int o = 1; o < 32; o <<= 1) {
        int t = __shfl_up_sync(0xffffffffu, x, o);
        if (lane >= o) x += t;
    }
    if (lane == 31) wsum[wid] = x;
    __syncthreads();
    if (wid == 0) {
        int s = (lane < 8) ? wsum[lane] : 0;
        #pragma unroll
        for (int o = 1; o < 8; o <<= 1) {
            int t = __shfl_up_sync(0xffffffffu, s, o);
            if (lane >= o) s += t;
        }
        if (lane < 8) wsum[lane] = s;
    }
    __syncthreads();
    int incl = x + ((wid > 0) ? wsum[wid - 1] : 0);
    if (tid < cnt) part[tid] = incl - v;
}

__global__ void phase3_kernel(const int* __restrict__ degU, const int* __restrict__ degM,
                              const int* __restrict__ partU, const int* __restrict__ partM,
                              int* __restrict__ offU, int* __restrict__ curU,
                              int* __restrict__ offM, int* __restrict__ curM) {
    int b = blockIdx.x;
    const int* deg; const int* part; int* off; int* cur; int n, tile;
    if (b < TU) { deg = degU; part = partU; off = offU; cur = curU; n = cNU; tile = b; }
    else        { deg = degM; part = partM; off = offM; cur = curM; n = cNM; tile = b - TU; }

    int tid = threadIdx.x, lane = tid & 31, wid = tid >> 5;
    if (b == 0 && tid == 0) { offU[cNU] = cE; offM[cNM] = cE; }

    int base = tile * TILE + tid * 4;
    int v[4];
    int s = 0;
    #pragma unroll
    for (int j = 0; j < 4; j++) {
        int i = base + j;
        v[j] = (i < n) ? deg[i] : 0;
        s += v[j];
    }
    __shared__ int wsum[8];
    int x = s;
    #pragma unroll
    for (int o = 1; o < 32; o <<= 1) {
        int t = __shfl_up_sync(0xffffffffu, x, o);
        if (lane >= o) x += t;
    }
    if (lane == 31) wsum[wid] = x;
    __syncthreads();
    if (wid == 0) {
        int t = (lane < 8) ? wsum[lane] : 0;
        #pragma unroll
        for (int o = 1; o < 8; o <<= 1) {
            int u = __shfl_up_sync(0xffffffffu, t, o);
            if (lane >= o) t += u;
        }
        if (lane < 8) wsum[lane] = t;
    }
    __syncthreads();
    int excl = x - s + ((wid > 0) ? wsum[wid - 1] : 0);
    int run = part[tile] + excl;
    #pragma unroll
    for (int j = 0; j < 4; j++) {
        int i = base + j;
        if (i < n) { off[i] = run; cur[i] = run; run += v[j]; }
    }
}

// ---------------- fused user-side aggregation (P1+P2, 4-edge unroll) ----------------
__global__ void agg_user_kernel(const int* __restrict__ off, const int* __restrict__ csr,
                                const float* __restrict__ P1, const float* __restrict__ P2,
                                const float* __restrict__ vecs,
                                float* __restrict__ user_h, float* __restrict__ aggP2, int NU) {
    int w    = (blockIdx.x * blockDim.x + threadIdx.x) >> 5;
    int lane = threadIdx.x & 31;
    int nw   = (gridDim.x * blockDim.x) >> 5;
    float4 c1 = ((const float4*)(vecs + cH))[lane];
    for (int u = w; u < NU; u += nw) {
        int s = off[u], e = off[u + 1];
        float4 a1 = make_float4(0.f, 0.f, 0.f, 0.f);   // P1 even
        float4 a2 = make_float4(0.f, 0.f, 0.f, 0.f);   // P2 even
        float4 a3 = make_float4(0.f, 0.f, 0.f, 0.f);   // P1 odd
        float4 a4 = make_float4(0.f, 0.f, 0.f, 0.f);   // P2 odd
        int i = s;
        for (; i + 3 < e; i += 4) {
            int d0 = csr[i];
            int d1 = csr[i + 1];
            int d2 = csr[i + 2];
            int d3 = csr[i + 3];
            float4 v0 = ((const float4*)(P1 + (size_t)d0 * 128))[lane];
            float4 w0 = ((const float4*)(P2 + (size_t)d0 * 128))[lane];
            float4 v1 = ((const float4*)(P1 + (size_t)d1 * 128))[lane];
            float4 w1 = ((const float4*)(P2 + (size_t)d1 * 128))[lane];
            float4 v2 = ((const float4*)(P1 + (size_t)d2 * 128))[lane];
            float4 w2 = ((const float4*)(P2 + (size_t)d2 * 128))[lane];
            float4 v3 = ((const float4*)(P1 + (size_t)d3 * 128))[lane];
            float4 w3 = ((const float4*)(P2 + (size_t)d3 * 128))[lane];
            a1.x += v0.x; a1.y += v0.y; a1.z += v0.z; a1.w += v0.w;
            a2.x += w0.x; a2.y += w0.y; a2.z += w0.z; a2.w += w0.w;
            a3.x += v1.x; a3.y += v1.y; a3.z += v1.z; a3.w += v1.w;
            a4.x += w1.x; a4.y += w1.y; a4.z += w1.z; a4.w += w1.w;
            a1.x += v2.x; a1.y += v2.y; a1.z += v2.z; a1.w += v2.w;
            a2.x += w2.x; a2.y += w2.y; a2.z += w2.z; a2.w += w2.w;
            a3.x += v3.x; a3.y += v3.y; a3.z += v3.z; a3.w += v3.w;
            a4.x += w3.x; a4.y += w3.y; a4.z += w3.z; a4.w += w3.w;
        }
        for (; i < e; i++) {
            int d0 = csr[i];
            float4 v0 = ((const float4*)(P1 + (size_t)d0 * 128))[lane];
            float4 w0 = ((const float4*)(P2 + (size_t)d0 * 128))[lane];
            a1.x += v0.x; a1.y += v0.y; a1.z += v0.z; a1.w += v0.w;
            a2.x += w0.x; a2.y += w0.y; a2.z += w0.z; a2.w += w0.w;
        }
        float sc = (e > s) ? 1.f / (float)(e - s) : 0.f;
        float4 o1 = make_float4(fmaxf((a1.x + a3.x) * sc + c1.x, 0.f),
                                fmaxf((a1.y + a3.y) * sc + c1.y, 0.f),
                                fmaxf((a1.z + a3.z) * sc + c1.z, 0.f),
                                fmaxf((a1.w + a3.w) * sc + c1.w, 0.f));
        float4 o2 = make_float4((a2.x + a4.x) * sc, (a2.y + a4.y) * sc, (a2.z + a4.z) * sc, (a2.w + a4.w) * sc);
        ((float4*)(user_h + (size_t)u * 128))[lane] = o1;
        ((float4*)(aggP2 + (size_t)u * 128))[lane] = o2;
    }
}

// ---------------- tensor-core SGEMM via split-bf16 ----------------
#define BK   16
#define ASTR 24
#define BSTR 136

__device__ __forceinline__ unsigned pack_bf16(__nv_bfloat16 a, __nv_bfloat16 b) {
    __nv_bfloat162 t = __halves2bfloat162(a, b);
    return reinterpret_cast<unsigned&>(t);
}
__device__ __forceinline__ void split_f32(float x, __nv_bfloat16& h, __nv_bfloat16& l) {
    h = __float2bfloat16(x);
    l = __float2bfloat16(x - __bfloat162float(h));
}
__device__ __forceinline__ void ldsm_x4(uint32_t* r, uint32_t addr) {
    asm volatile("ldmatrix.sync.aligned.m8n8.x4.shared.b16 {%0,%1,%2,%3}, [%4];"
                 : "=r"(r[0]), "=r"(r[1]), "=r"(r[2]), "=r"(r[3]) : "r"(addr));
}
__device__ __forceinline__ void ldsm_x4_t(uint32_t* r, uint32_t addr) {
    asm volatile("ldmatrix.sync.aligned.m8n8.x4.trans.shared.b16 {%0,%1,%2,%3}, [%4];"
                 : "=r"(r[0]), "=r"(r[1]), "=r"(r[2]), "=r"(r[3]) : "r"(addr));
}
__device__ __forceinline__ void mma_bf16(float* d, const uint32_t* a, const uint32_t* b) {
    asm volatile("mma.sync.aligned.m16n8k16.row.col.f32.bf16.bf16.f32 "
                 "{%0,%1,%2,%3}, {%4,%5,%6,%7}, {%8,%9}, {%0,%1,%2,%3};"
                 : "+f"(d[0]), "+f"(d[1]), "+f"(d[2]), "+f"(d[3])
                 : "r"(a[0]), "r"(a[1]), "r"(a[2]), "r"(a[3]), "r"(b[0]), "r"(b[1]));
}

template<bool BIAS_SEL, bool RELU, bool ADD_D>
__device__ __forceinline__ void gemm128_body(
    const float* __restrict__ A1, const float* __restrict__ A2,
    const float* __restrict__ B1, const float* __restrict__ B2,
    float* __restrict__ C,
    const float* __restrict__ bias, const float* __restrict__ vsel,
    const int* __restrict__ deg, const float* __restrict__ Dm,
    int M, int KT1, int KT2, int bid) {
    __shared__ __nv_bfloat16 Ah[2][128][ASTR];
    __shared__ __nv_bfloat16 Al[2][128][ASTR];
    __shared__ __nv_bfloat16 Bh[2][BK][BSTR];
    __shared__ __nv_bfloat16 Bl[2][BK][BSTR];
    __shared__ float sBias[128];
    __shared__ float sVsel[128];

    const int tid  = threadIdx.x;
    const int lane = tid & 31;
    const int wid  = tid >> 5;
    const int wm   = wid & 3;
    const int wn   = wid >> 2;
    const int m0   = bid * 128;
    const int lda1 = KT1 * BK;
    const int lda2 = KT2 * BK;
    const int KT   = KT1 + KT2;

    if (tid < 128) {
        sBias[tid] = bias[tid];
        if (BIAS_SEL) sVsel[tid] = vsel[tid];
    }

    const int arow0 = tid >> 2;
    const int ac4   = (tid & 3) << 2;
    const int brow0 = tid >> 5;
    const int bn4   = (tid & 31) << 2;

    float4 rA[2], rB[2];

    auto loadTile = [&](int t) {
        const bool first = (t < KT1);
        #pragma unroll
        for (int i = 0; i < 2; i++) {
            int row = arow0 + i * 64;
            int m = m0 + row;
            float4 v = make_float4(0.f, 0.f, 0.f, 0.f);
            if (m < M) {
                const float* p = first ? (A1 + (size_t)m * lda1 + t * BK + ac4)
                                       : (A2 + (size_t)m * lda2 + (t - KT1) * BK + ac4);
                v = *(const float4*)p;
            }
            rA[i] = v;
        }
        #pragma unroll
        for (int i = 0; i < 2; i++) {
            int row = brow0 + i * 8;
            const float* p = first ? (B1 + (size_t)(t * BK + row) * 128 + bn4)
                                   : (B2 + (size_t)((t - KT1) * BK + row) * 128 + bn4);
            rB[i] = *(const float4*)p;
        }
    };
    auto storeTile = [&](int buf) {
        #pragma unroll
        for (int i = 0; i < 2; i++) {
            int row = arow0 + i * 64;
            const float* v = &rA[i].x;
            __nv_bfloat16 h[4], l[4];
            #pragma unroll
            for (int j = 0; j < 4; j++) split_f32(v[j], h[j], l[j]);
            *(uint2*)&Ah[buf][row][ac4] = make_uint2(pack_bf16(h[0], h[1]), pack_bf16(h[2], h[3]));
            *(uint2*)&Al[buf][row][ac4] = make_uint2(pack_bf16(l[0], l[1]), pack_bf16(l[2], l[3]));
        }
        #pragma unroll
        for (int i = 0; i < 2; i++) {
            int row = brow0 + i * 8;
            const float* v = &rB[i].x;
            __nv_bfloat16 h[4], l[4];
            #pragma unroll
            for (int j = 0; j < 4; j++) split_f32(v[j], h[j], l[j]);
            *(uint2*)&Bh[buf][row][bn4] = make_uint2(pack_bf16(h[0], h[1]), pack_bf16(h[2], h[3]));
            *(uint2*)&Bl[buf][row][bn4] = make_uint2(pack_bf16(l[0], l[1]), pack_bf16(l[2], l[3]));
        }
    };

    float d[2][8][4];
    #pragma unroll
    for (int mt = 0; mt < 2; mt++)
        #pragma unroll
        for (int nt = 0; nt < 8; nt++)
            #pragma unroll
            for (int j = 0; j < 4; j++) d[mt][nt][j] = 0.f;

    const int ar = lane & 15;
    const int ac = (lane >> 4) << 3;
    const int br = lane & 15;
    const int bc = wn * 64 + ((lane >> 4) << 3);

    loadTile(0);
    storeTile(0);
    __syncthreads();

    for (int t = 0; t < KT; t++) {
        const int cb = t & 1;
        if (t + 1 < KT) loadTile(t + 1);

        uint32_t fah[2][4], fal[2][4];
        #pragma unroll
        for (int mt = 0; mt < 2; mt++) {
            int row = wm * 32 + mt * 16 + ar;
            ldsm_x4(fah[mt], (uint32_t)__cvta_generic_to_shared(&Ah[cb][row][ac]));
            ldsm_x4(fal[mt], (uint32_t)__cvta_generic_to_shared(&Al[cb][row][ac]));
        }
        #pragma unroll
        for (int ntp = 0; ntp < 4; ntp++) {
            uint32_t fbh[4], fbl[4];
            ldsm_x4_t(fbh, (uint32_t)__cvta_generic_to_shared(&Bh[cb][br][bc + ntp * 16]));
            ldsm_x4_t(fbl, (uint32_t)__cvta_generic_to_shared(&Bl[cb][br][bc + ntp * 16]));
            #pragma unroll
            for (int mt = 0; mt < 2; mt++) {
                mma_bf16(d[mt][2 * ntp],     fah[mt], fbh);
                mma_bf16(d[mt][2 * ntp],     fal[mt], fbh);
                mma_bf16(d[mt][2 * ntp],     fah[mt], fbl);
                mma_bf16(d[mt][2 * ntp + 1], fah[mt], fbh + 2);
                mma_bf16(d[mt][2 * ntp + 1], fal[mt], fbh + 2);
                mma_bf16(d[mt][2 * ntp + 1], fah[mt], fbl + 2);
            }
        }
        if (t + 1 < KT) storeTile((t + 1) & 1);
        __syncthreads();
    }

    const int rb  = m0 + wm * 32 + (lane >> 2);
    const int cb0 = wn * 64 + (lane & 3) * 2;
    #pragma unroll
    for (int mt = 0; mt < 2; mt++) {
        #pragma unroll
        for (int h = 0; h < 2; h++) {
            int m = rb + mt * 16 + h * 8;
            if (m >= M) continue;
            float sel = 0.f;
            if (BIAS_SEL) sel = (deg[m] > 0) ? 1.f : 0.f;
            #pragma unroll
            for (int nt = 0; nt < 8; nt++) {
                int col = cb0 + nt * 8;
                float x = d[mt][nt][h * 2 + 0] + sBias[col];
                float y = d[mt][nt][h * 2 + 1] + sBias[col + 1];
                if (BIAS_SEL) { x += sel * sVsel[col]; y += sel * sVsel[col + 1]; }
                if (ADD_D) {
                    float2 dv = *(const float2*)&Dm[(size_t)m * 128 + col];
                    x += dv.x; y += dv.y;
                }
                if (RELU) { x = fmaxf(x, 0.f); y = fmaxf(y, 0.f); }
                *(float2*)&C[(size_t)m * 128 + col] = make_float2(x, y);
            }
        }
    }
}

template<bool BIAS_SEL, bool RELU, bool ADD_D>
__global__ void __launch_bounds__(256)
gemm128_kernel(const float* A1, const float* A2, const float* B1, const float* B2,
               float* C, const float* bias, const float* vsel, const int* deg,
               const float* Dm, int M, int KT1, int KT2) {
    gemm128_body<BIAS_SEL, RELU, ADD_D>(A1, A2, B1, B2, C, bias, vsel, deg, Dm, M, KT1, KT2, blockIdx.x);
}

// ---------------- fused kernels ----------------
// fusedA: GEMM4 (movie_x) || deg || vec.
__global__ void __launch_bounds__(256)
fusedA_kernel(const float* __restrict__ movie_feats, const float* __restrict__ Wm, const float* __restrict__ bm,
              float* __restrict__ movie_x,
              const int* __restrict__ src, const int* __restrict__ dst,
              int* __restrict__ du, int* __restrict__ dm,
              const float* __restrict__ user_init, const float* __restrict__ Wl1_um,
              const float* __restrict__ Wr1_mu, const float* __restrict__ bl1_mu,
              float* __restrict__ vecs,
              int GA, int DEGB) {
    int bid = blockIdx.x;
    int q = bid >> 2, r = bid & 3;
    if (r == 0 && q < GA) {
        gemm128_body<false, false, false>(movie_feats, nullptr, Wm, nullptr, movie_x,
                                          bm, nullptr, nullptr, nullptr, cNM, cFD / BK, 0, q);
    } else {
        int before = min((bid + 3) >> 2, GA);
        int did = bid - before;
        if (did < DEGB) deg_body(src, dst, du, dm, cE, did, DEGB);
        else            vec_body(user_init, Wl1_um, Wr1_mu, bl1_mu, vecs);
    }
}

// fusedB: GEMM5 (movie_h) || P1 || scatter.
__global__ void __launch_bounds__(256)
fusedB_kernel(const float* __restrict__ movie_x,
              const float* __restrict__ Wr1_um, const float* __restrict__ Wl1_mu,
              float* __restrict__ movie_h, float* __restrict__ P1,
              const float* __restrict__ bl1_um, const float* __restrict__ vsel, const int* __restrict__ deg_m,
              const float* __restrict__ zero,
              const int* __restrict__ src, const int* __restrict__ dst,
              int* __restrict__ curU, int* __restrict__ curM,
              int* __restrict__ csrU, int* __restrict__ csrM,
              int GM_, int GA, int SCB) {
    int bid = blockIdx.x;
    int q = bid >> 2, r = bid & 3;
    if (r == 0 && q < GA) {
        if (q < GM_) {
            gemm128_body<true, true, false>(movie_x, nullptr, Wr1_um, nullptr, movie_h,
                                            bl1_um, vsel, deg_m, nullptr, cNM, cH / BK, 0, q);
        } else {
            gemm128_body<false, false, false>(movie_x, nullptr, Wl1_mu, nullptr, P1,
                                              zero, nullptr, nullptr, nullptr, cNM, cH / BK, 0, q - GM_);
        }
    } else {
        int before = min((bid + 3) >> 2, GA);
        int did = bid - before;
        if (did < SCB) scatter_body(src, dst, curU, curM, csrU, csrM, cE, did, SCB);
    }
}

// fusedC: GEMM10' (user_o = user_h@Wr2_mu + bl2_mu + aggP2) || agg_movie.
__global__ void __launch_bounds__(256)
fusedC_kernel(const float* __restrict__ user_h, const float* __restrict__ Wr2_mu,
              float* __restrict__ user_o, const float* __restrict__ bl2_mu,
              const float* __restrict__ aggP2,
              const int* __restrict__ offM, const int* __restrict__ csrM,
              float* __restrict__ aggM2,
              int GA, int AGB) {
    int bid = blockIdx.x;
    int q = bid >> 1, r = bid & 1;
    if (r == 0 && q < GA) {
        gemm128_body<false, false, true>(user_h, nullptr, Wr2_mu, nullptr, user_o,
                                         bl2_mu, nullptr, nullptr, aggP2, cNU, cH / BK, 0, q);
    } else {
        int before = min((bid + 1) >> 1, GA);
        int aid = bid - before;
        if (aid < AGB) agg_movie_body(offM, csrM, user_h, aggM2, cNM, aid, AGB);
    }
}

// ---------------- final edge dot products (2-edge unroll) ----------------
__global__ void dot_kernel(const int* __restrict__ lu, const int* __restrict__ lm,
                           const float* __restrict__ U, const float* __restrict__ Mo,
                           float* __restrict__ out, int EL) {
    int w    = (blockIdx.x * blockDim.x + threadIdx.x) >> 5;
    int lane = threadIdx.x & 31;
    int nw   = (gridDim.x * blockDim.x) >> 5;
    for (int i = w; i < EL; i += 2 * nw) {
        int i2 = i + nw;
        bool has2 = (i2 < EL);
        int u0 = lu[i], m0 = lm[i];
        float4 a0 = ((const float4*)(U  + (size_t)u0 * 128))[lane];
        float4 b0 = ((const float4*)(Mo + (size_t)m0 * 128))[lane];
        float p0 = a0.x * b0.x + a0.y * b0.y + a0.z * b0.z + a0.w * b0.w;
        float p1 = 0.f;
        if (has2) {
            int u1 = lu[i2], m1 = lm[i2];
            float4 a1 = ((const float4*)(U  + (size_t)u1 * 128))[lane];
            float4 b1 = ((const float4*)(Mo + (size_t)m1 * 128))[lane];
            p1 = a1.x * b1.x + a1.y * b1.y + a1.z * b1.z + a1.w * b1.w;
        }
        #pragma unroll
        for (int off = 16; off > 0; off >>= 1) {
            p0 += __shfl_xor_sync(0xFFFFFFFFu, p0, off);
            p1 += __shfl_xor_sync(0xFFFFFFFFu, p1, off);
        }
        if (lane == 0) {
            out[i] = p0;
            if (has2) out[i2] = p1;
        }
    }
}

// ---------------- launch ----------------
extern "C" void kernel_launch(void* const* d_in, const int* in_sizes, int n_in,
                              void* d_out, int out_size) {
    const float* movie_feats = (const float*)d_in[0];
    const float* user_init   = (const float*)d_in[1];
    const int*   edge_src    = (const int*)d_in[2];
    const int*   edge_dst    = (const int*)d_in[3];
    const int*   lbl_user    = (const int*)d_in[4];
    const int*   lbl_movie   = (const int*)d_in[5];
    const int wi = (n_in >= 21) ? 7 : 6;
    const float* Wm     = (const float*)d_in[wi + 0];
    const float* bm     = (const float*)d_in[wi + 1];
    const float* Wl1_um = (const float*)d_in[wi + 2];
    const float* bl1_um = (const float*)d_in[wi + 3];
    const float* Wr1_um = (const float*)d_in[wi + 4];
    const float* Wl1_mu = (const float*)d_in[wi + 5];
    const float* bl1_mu = (const float*)d_in[wi + 6];
    const float* Wr1_mu = (const float*)d_in[wi + 7];
    const float* Wl2_um = (const float*)d_in[wi + 8];
    const float* bl2_um = (const float*)d_in[wi + 9];
    const float* Wr2_um = (const float*)d_in[wi + 10];
    const float* Wl2_mu = (const float*)d_in[wi + 11];
    const float* bl2_mu = (const float*)d_in[wi + 12];
    const float* Wr2_mu = (const float*)d_in[wi + 13];
    float* out = (float*)d_out;

    float *movie_x, *movie_h, *P1, *P2, *user_h, *aggP2, *aggM2, *movie_o, *user_o, *vecs, *zero;
    int *deg_u, *deg_m, *offU, *offM, *curU, *curM, *csrU, *csrM, *partU, *partM;
    cudaGetSymbolAddress((void**)&movie_x, g_movie_x);
    cudaGetSymbolAddress((void**)&movie_h, g_movie_h);
    cudaGetSymbolAddress((void**)&P1,      g_P1);
    cudaGetSymbolAddress((void**)&P2,      g_P2);
    cudaGetSymbolAddress((void**)&user_h,  g_user_h);
    cudaGetSymbolAddress((void**)&aggP2,   g_aggP2);
    cudaGetSymbolAddress((void**)&aggM2,   g_aggM2);
    cudaGetSymbolAddress((void**)&movie_o, g_movie_o);
    cudaGetSymbolAddress((void**)&user_o,  g_user_o);
    cudaGetSymbolAddress((void**)&vecs,    g_vecs);
    cudaGetSymbolAddress((void**)&zero,    g_zero);
    cudaGetSymbolAddress((void**)&deg_u,   g_deg_u);
    cudaGetSymbolAddress((void**)&deg_m,   g_deg_m);
    cudaGetSymbolAddress((void**)&offU,    g_offU);
    cudaGetSymbolAddress((void**)&offM,    g_offM);
    cudaGetSymbolAddress((void**)&curU,    g_curU);
    cudaGetSymbolAddress((void**)&curM,    g_curM);
    cudaGetSymbolAddress((void**)&csrU,    g_csrU);
    cudaGetSymbolAddress((void**)&csrM,    g_csrM);
    cudaGetSymbolAddress((void**)&partU,   g_partU);
    cudaGetSymbolAddress((void**)&partM,   g_partM);

    const int GM = (cNM + 127) / 128;   // 625
    const int GU = (cNU + 127) / 128;   // 1563

    // 1) zero degree counters
    zero2_kernel<<<384, 256>>>(deg_u, cNU, deg_m, cNM);

    // 2) fusedA: GEMM4 || deg || vec
    const int DEGB = 2048;
    fusedA_kernel<<<GM + DEGB + 1, 256>>>(movie_feats, Wm, bm, movie_x,
                                          edge_src, edge_dst, deg_u, deg_m,
                                          user_init, Wl1_um, Wr1_mu, bl1_mu, vecs,
                                          GM, DEGB);

    // 3) CSR offsets
    partial_kernel<<<TU + TM, 256>>>(deg_u, deg_m, partU, partM);
    scanpart_kernel<<<2, 256>>>(partU, partM);
    phase3_kernel<<<TU + TM, 256>>>(deg_u, deg_m, partU, partM, offU, curU, offM, curM);

    // 4) fusedB: GEMM5 || P1 || scatter
    {
        const int GA = 2 * GM;            // 1250 gemm virtual blocks
        const int grid = 4 * GA;          // 5000
        const int SCB = grid - GA;        // 3750 scatter virtual blocks
        fusedB_kernel<<<grid, 256>>>(movie_x, Wr1_um, Wl1_mu, movie_h, P1,
                                     bl1_um, vecs, deg_m, zero,
                                     edge_src, edge_dst, curU, curM, csrU, csrM,
                                     GM, GA, SCB);
    }

    // 5) P2 = movie_h @ Wl2_mu
    gemm128_kernel<false, false, false><<<GM, 256>>>(
        movie_h, nullptr, Wl2_mu, nullptr, P2, zero, nullptr, nullptr, nullptr, cNM, cH / BK, 0);

    // 6) user-side aggregation: user_h = relu(meanP1 + cb1), aggP2 = meanP2
    agg_user_kernel<<<4736, 256>>>(offU, csrU, P1, P2, vecs, user_h, aggP2, cNU);

    // 7) fusedC: GEMM10' (user_o) || agg_movie
    {
        const int gridC = 2 * GU;
        const int AGB = gridC - GU;
        fusedC_kernel<<<gridC, 256>>>(user_h, Wr2_mu, user_o, bl2_mu, aggP2,
                                      offM, csrM, aggM2, GU, AGB);
    }

    // 8) GEMM9: movie_o = aggM2 @ Wl2_um + bl2_um + movie_h @ Wr2_um
    gemm128_kernel<false, false, false><<<GM, 256>>>(
        aggM2, movie_h, Wl2_um, Wr2_um, movie_o, bl2_um, nullptr, nullptr, nullptr,
        cNM, cH / BK, cH / BK);

    // 9) final dot products
    dot_kernel<<<4736, 256>>>(lbl_user, lbl_movie, user_o, movie_o, out, cEL);

    (void)in_sizes; (void)out_size;
}

// round 12
// speedup vs baseline: 1.1172x; 1.0009x over previous
#include <cuda_runtime.h>
#include <cuda_bf16.h>
#include <cstddef>
#include <cstdint>

// Problem constants
#define cH   128
#define cNU  200000
#define cNM  80000
#define cE   2000000
#define cEL  500000
#define cFD  512

#define TILE 1024
#define TU   ((cNU + TILE - 1) / TILE)   // 196
#define TM   ((cNM + TILE - 1) / TILE)   // 79

// ---------------- scratch (device globals) ----------------
__device__ float g_movie_x[(size_t)cNM * cH];
__device__ float g_movie_h[(size_t)cNM * cH];
__device__ float g_P1[(size_t)cNM * cH];      // movie_x @ Wl1_mu
__device__ float g_P2[(size_t)cNM * cH];      // movie_h @ Wl2_mu
__device__ float g_user_h [(size_t)cNU * cH];
__device__ float g_aggP2 [(size_t)cNU * cH];
__device__ float g_aggM2 [(size_t)cNM * cH];
__device__ float g_movie_o[(size_t)cNM * cH];
__device__ float g_user_o [(size_t)cNU * cH];
__device__ int   g_deg_u[cNU];
__device__ int   g_deg_m[cNM];
__device__ int   g_offU[cNU + 1];
__device__ int   g_offM[cNM + 1];
__device__ int   g_curU[cNU];
__device__ int   g_curM[cNM];
__device__ int   g_csrU[cE];
__device__ int   g_csrM[cE];
__device__ int   g_partU[TU];
__device__ int   g_partM[TM];
__device__ float g_vecs[2 * cH];
__device__ float g_zero[cH];

// ---------------- utility ----------------
__global__ void zero2_kernel(int* p1, int n1, int* p2, int n2) {
    int i = blockIdx.x * blockDim.x + threadIdx.x;
    int stride = gridDim.x * blockDim.x;
    for (int k = i; k < n1; k += stride) p1[k] = 0;
    for (int k = i; k < n2; k += stride) p2[k] = 0;
}

// ---- device bodies ----
__device__ __forceinline__ void deg_body(const int* __restrict__ src, const int* __restrict__ dst,
                                         int* __restrict__ du, int* __restrict__ dm,
                                         int E, int vbid, int vgrid) {
    int i = vbid * 256 + threadIdx.x;
    int stride = vgrid * 256;
    for (; i < E; i += stride) {
        atomicAdd(&du[src[i]], 1);
        atomicAdd(&dm[dst[i]], 1);
    }
}

__device__ __forceinline__ void scatter_body(const int* __restrict__ src, const int* __restrict__ dst,
                                             int* __restrict__ curU, int* __restrict__ curM,
                                             int* __restrict__ csrU, int* __restrict__ csrM,
                                             int E, int vbid, int vgrid) {
    int i = vbid * 256 + threadIdx.x;
    int stride = vgrid * 256;
    for (; i < E; i += stride) {
        int s = src[i];
        int d = dst[i];
        int p = atomicAdd(&curU[s], 1);
        csrU[p] = d;
        int q = atomicAdd(&curM[d], 1);
        csrM[q] = s;
    }
}

__device__ __forceinline__ void vec_body(const float* __restrict__ user_init,
                                         const float* __restrict__ Wl1_um,
                                         const float* __restrict__ Wr1_mu,
                                         const float* __restrict__ bl1_mu,
                                         float* __restrict__ vecs) {
    int j = threadIdx.x;
    if (j >= cH) return;
    float s1 = 0.f, s2 = 0.f;
    for (int k = 0; k < cH; k++) {
        float u = user_init[k];
        s1 = fmaf(u, Wl1_um[k * cH + j], s1);
        s2 = fmaf(u, Wr1_mu[k * cH + j], s2);
    }
    vecs[j]      = s1;
    vecs[cH + j] = bl1_mu[j] + s2;
}

__device__ __forceinline__ void agg_movie_body(const int* __restrict__ off, const int* __restrict__ csr,
                                               const float* __restrict__ uh,
                                               float* __restrict__ aM2, int NM, int vbid, int vgrid) {
    int w    = vbid * 8 + (threadIdx.x >> 5);
    int lane = threadIdx.x & 31;
    int nw   = vgrid * 8;
    for (int m = w; m < NM; m += nw) {
        int s = off[m], e = off[m + 1];
        float4 a1 = make_float4(0.f, 0.f, 0.f, 0.f);
        float4 a2 = make_float4(0.f, 0.f, 0.f, 0.f);
        float4 a3 = make_float4(0.f, 0.f, 0.f, 0.f);
        float4 a4 = make_float4(0.f, 0.f, 0.f, 0.f);
        int i = s;
        for (; i + 3 < e; i += 4) {
            int d0 = csr[i];
            int d1 = csr[i + 1];
            int d2 = csr[i + 2];
            int d3 = csr[i + 3];
            float4 v0 = ((const float4*)(uh + (size_t)d0 * 128))[lane];
            float4 v1 = ((const float4*)(uh + (size_t)d1 * 128))[lane];
            float4 v2 = ((const float4*)(uh + (size_t)d2 * 128))[lane];
            float4 v3 = ((const float4*)(uh + (size_t)d3 * 128))[lane];
            a1.x += v0.x; a1.y += v0.y; a1.z += v0.z; a1.w += v0.w;
            a2.x += v1.x; a2.y += v1.y; a2.z += v1.z; a2.w += v1.w;
            a3.x += v2.x; a3.y += v2.y; a3.z += v2.z; a3.w += v2.w;
            a4.x += v3.x; a4.y += v3.y; a4.z += v3.z; a4.w += v3.w;
        }
        for (; i < e; i++) {
            int d0 = csr[i];
            float4 v0 = ((const float4*)(uh + (size_t)d0 * 128))[lane];
            a1.x += v0.x; a1.y += v0.y; a1.z += v0.z; a1.w += v0.w;
        }
        float sc = (e > s) ? 1.f / (float)(e - s) : 0.f;
        float4 o = make_float4((a1.x + a2.x + a3.x + a4.x) * sc,
                               (a1.y + a2.y + a3.y + a4.y) * sc,
                               (a1.z + a2.z + a3.z + a4.z) * sc,
                               (a1.w + a2.w + a3.w + a4.w) * sc);
        ((float4*)(aM2 + (size_t)m * 128))[lane] = o;
    }
}

// ---- parallel scan ----
__global__ void partial_kernel(const int* __restrict__ degU, const int* __restrict__ degM,
                               int* __restrict__ partU, int* __restrict__ partM) {
    int b = blockIdx.x;
    const int* deg; int* part; int n, tile;
    if (b < TU) { deg = degU; part = partU; n = cNU; tile = b; }
    else        { deg = degM; part = partM; n = cNM; tile = b - TU; }

    int tid = threadIdx.x;
    int base = tile * TILE + tid * 4;
    int s = 0;
    #pragma unroll
    for (int j = 0; j < 4; j++) {
        int i = base + j;
        if (i < n) s += deg[i];
    }
    __shared__ int wsum[8];
    int lane = tid & 31, wid = tid >> 5;
    #pragma unroll
    for (int o = 16; o > 0; o >>= 1) s += __shfl_down_sync(0xffffffffu, s, o);
    if (lane == 0) wsum[wid] = s;
    __syncthreads();
    if (tid == 0) {
        int t = 0;
        #pragma unroll
        for (int w = 0; w < 8; w++) t += wsum[w];
        part[tile] = t;
    }
}

__global__ void scanpart_kernel(int* __restrict__ partU, int* __restrict__ partM) {
    int* part = (blockIdx.x == 0) ? partU : partM;
    int cnt   = (blockIdx.x == 0) ? TU : TM;
    int tid = threadIdx.x, lane = tid & 31, wid = tid >> 5;
    __shared__ int wsum[8];
    int v = (tid < cnt) ? part[tid] : 0;
    int x = v;
    #pragma unroll
    for (int o = 1; o < 32; o <<= 1) {
        int t = __shfl_up_sync(0xffffffffu, x, o);
        if (lane >= o) x += t;
    }
    if (lane == 31) wsum[wid] = x;
    __syncthreads();
    if (wid == 0) {
        int s = (lane < 8) ? wsum[lane] : 0;
        #pragma unroll
        for (int o = 1; o < 8; o <<= 1) {
            int t = __shfl_up_sync(0xffffffffu, s, o);
            if (lane >= o) s += t;
        }
        if (lane < 8) wsum[lane] = s;
    }
    __syncthreads();
    int incl = x + ((wid > 0) ? wsum[wid - 1] : 0);
    if (tid < cnt) part[tid] = incl - v;
}

__global__ void phase3_kernel(const int* __restrict__ degU, const int* __restrict__ degM,
                              const int* __restrict__ partU, const int* __restrict__ partM,
                              int* __restrict__ offU, int* __restrict__ curU,
                              int* __restrict__ offM, int* __restrict__ curM) {
    int b = blockIdx.x;
    const int* deg; const int* part; int* off; int* cur; int n, tile;
    if (b < TU) { deg = degU; part = partU; off = offU; cur = curU; n = cNU; tile = b; }
    else        { deg = degM; part = partM; off = offM; cur = curM; n = cNM; tile = b - TU; }

    int tid = threadIdx.x, lane = tid & 31, wid = tid >> 5;
    if (b == 0 && tid == 0) { offU[cNU] = cE; offM[cNM] = cE; }

    int base = tile * TILE + tid * 4;
    int v[4];
    int s = 0;
    #pragma unroll
    for (int j = 0; j < 4; j++) {
        int i = base + j;
        v[j] = (i < n) ? deg[i] : 0;
        s += v[j];
    }
    __shared__ int wsum[8];
    int x = s;
    #pragma unroll
    for (int o = 1; o < 32; o <<= 1) {
        int t = __shfl_up_sync(0xffffffffu, x, o);
        if (lane >= o) x += t;
    }
    if (lane == 31) wsum[wid] = x;
    __syncthreads();
    if (wid == 0) {
        int t = (lane < 8) ? wsum[lane] : 0;
        #pragma unroll
        for (int o = 1; o < 8; o <<= 1) {
            int u = __shfl_up_sync(0xffffffffu, t, o);
            if (lane >= o) t += u;
        }
        if (lane < 8) wsum[lane] = t;
    }
    __syncthreads();
    int excl = x - s + ((wid > 0) ? wsum[wid - 1] : 0);
    int run = part[tile] + excl;
    #pragma unroll
    for (int j = 0; j < 4; j++) {
        int i = base + j;
        if (i < n) { off[i] = run; cur[i] = run; run += v[j]; }
    }
}

// ---------------- fused user-side aggregation (P1+P2, 4-edge unroll) ----------------
__global__ void agg_user_kernel(const int* __restrict__ off, const int* __restrict__ csr,
                                const float* __restrict__ P1, const float* __restrict__ P2,
                                const float* __restrict__ vecs,
                                float* __restrict__ user_h, float* __restrict__ aggP2, int NU) {
    int w    = (blockIdx.x * blockDim.x + threadIdx.x) >> 5;
    int lane = threadIdx.x & 31;
    int nw   = (gridDim.x * blockDim.x) >> 5;
    float4 c1 = ((const float4*)(vecs + cH))[lane];
    for (int u = w; u < NU; u += nw) {
        int s = off[u], e = off[u + 1];
        float4 a1 = make_float4(0.f, 0.f, 0.f, 0.f);   // P1 even
        float4 a2 = make_float4(0.f, 0.f, 0.f, 0.f);   // P2 even
        float4 a3 = make_float4(0.f, 0.f, 0.f, 0.f);   // P1 odd
        float4 a4 = make_float4(0.f, 0.f, 0.f, 0.f);   // P2 odd
        int i = s;
        for (; i + 3 < e; i += 4) {
            int d0 = csr[i];
            int d1 = csr[i + 1];
            int d2 = csr[i + 2];
            int d3 = csr[i + 3];
            float4 v0 = ((const float4*)(P1 + (size_t)d0 * 128))[lane];
            float4 w0 = ((const float4*)(P2 + (size_t)d0 * 128))[lane];
            float4 v1 = ((const float4*)(P1 + (size_t)d1 * 128))[lane];
            float4 w1 = ((const float4*)(P2 + (size_t)d1 * 128))[lane];
            float4 v2 = ((const float4*)(P1 + (size_t)d2 * 128))[lane];
            float4 w2 = ((const float4*)(P2 + (size_t)d2 * 128))[lane];
            float4 v3 = ((const float4*)(P1 + (size_t)d3 * 128))[lane];
            float4 w3 = ((const float4*)(P2 + (size_t)d3 * 128))[lane];
            a1.x += v0.x; a1.y += v0.y; a1.z += v0.z; a1.w += v0.w;
            a2.x += w0.x; a2.y += w0.y; a2.z += w0.z; a2.w += w0.w;
            a3.x += v1.x; a3.y += v1.y; a3.z += v1.z; a3.w += v1.w;
            a4.x += w1.x; a4.y += w1.y; a4.z += w1.z; a4.w += w1.w;
            a1.x += v2.x; a1.y += v2.y; a1.z += v2.z; a1.w += v2.w;
            a2.x += w2.x; a2.y += w2.y; a2.z += w2.z; a2.w += w2.w;
            a3.x += v3.x; a3.y += v3.y; a3.z += v3.z; a3.w += v3.w;
            a4.x += w3.x; a4.y += w3.y; a4.z += w3.z; a4.w += w3.w;
        }
        for (; i < e; i++) {
            int d0 = csr[i];
            float4 v0 = ((const float4*)(P1 + (size_t)d0 * 128))[lane];
            float4 w0 = ((const float4*)(P2 + (size_t)d0 * 128))[lane];
            a1.x += v0.x; a1.y += v0.y; a1.z += v0.z; a1.w += v0.w;
            a2.x += w0.x; a2.y += w0.y; a2.z += w0.z; a2.w += w0.w;
        }
        float sc = (e > s) ? 1.f / (float)(e - s) : 0.f;
        float4 o1 = make_float4(fmaxf((a1.x + a3.x) * sc + c1.x, 0.f),
                                fmaxf((a1.y + a3.y) * sc + c1.y, 0.f),
                                fmaxf((a1.z + a3.z) * sc + c1.z, 0.f),
                                fmaxf((a1.w + a3.w) * sc + c1.w, 0.f));
        float4 o2 = make_float4((a2.x + a4.x) * sc, (a2.y + a4.y) * sc, (a2.z + a4.z) * sc, (a2.w + a4.w) * sc);
        ((float4*)(user_h + (size_t)u * 128))[lane] = o1;
        ((float4*)(aggP2 + (size_t)u * 128))[lane] = o2;
    }
}

// ---------------- tensor-core SGEMM via split-bf16 ----------------
#define BK   16
#define ASTR 24
#define BSTR 136

__device__ __forceinline__ unsigned pack_bf16(__nv_bfloat16 a, __nv_bfloat16 b) {
    __nv_bfloat162 t = __halves2bfloat162(a, b);
    return reinterpret_cast<unsigned&>(t);
}
__device__ __forceinline__ void split_f32(float x, __nv_bfloat16& h, __nv_bfloat16& l) {
    h = __float2bfloat16(x);
    l = __float2bfloat16(x - __bfloat162float(h));
}
__device__ __forceinline__ void ldsm_x4(uint32_t* r, uint32_t addr) {
    asm volatile("ldmatrix.sync.aligned.m8n8.x4.shared.b16 {%0,%1,%2,%3}, [%4];"
                 : "=r"(r[0]), "=r"(r[1]), "=r"(r[2]), "=r"(r[3]) : "r"(addr));
}
__device__ __forceinline__ void ldsm_x4_t(uint32_t* r, uint32_t addr) {
    asm volatile("ldmatrix.sync.aligned.m8n8.x4.trans.shared.b16 {%0,%1,%2,%3}, [%4];"
                 : "=r"(r[0]), "=r"(r[1]), "=r"(r[2]), "=r"(r[3]) : "r"(addr));
}
__device__ __forceinline__ void mma_bf16(float* d, const uint32_t* a, const uint32_t* b) {
    asm volatile("mma.sync.aligned.m16n8k16.row.col.f32.bf16.bf16.f32 "
                 "{%0,%1,%2,%3}, {%4,%5,%6,%7}, {%8,%9}, {%0,%1,%2,%3};"
                 : "+f"(d[0]), "+f"(d[1]), "+f"(d[2]), "+f"(d[3])
                 : "r"(a[0]), "r"(a[1]), "r"(a[2]), "r"(a[3]), "r"(b[0]), "r"(b[1]));
}

template<bool BIAS_SEL, bool RELU, bool ADD_D>
__device__ __forceinline__ void gemm128_body(
    const float* __restrict__ A1, const float* __restrict__ A2,
    const float* __restrict__ B1, const float* __restrict__ B2,
    float* __restrict__ C,
    const float* __restrict__ bias, const float* __restrict__ vsel,
    const int* __restrict__ deg, const float* __restrict__ Dm,
    int M, int KT1, int KT2, int bid) {
    __shared__ __nv_bfloat16 Ah[2][128][ASTR];
    __shared__ __nv_bfloat16 Al[2][128][ASTR];
    __shared__ __nv_bfloat16 Bh[2][BK][BSTR];
    __shared__ __nv_bfloat16 Bl[2][BK][BSTR];
    __shared__ float sBias[128];
    __shared__ float sVsel[128];

    const int tid  = threadIdx.x;
    const int lane = tid & 31;
    const int wid  = tid >> 5;
    const int wm   = wid & 3;
    const int wn   = wid >> 2;
    const int m0   = bid * 128;
    const int lda1 = KT1 * BK;
    const int lda2 = KT2 * BK;
    const int KT   = KT1 + KT2;

    if (tid < 128) {
        sBias[tid] = bias[tid];
        if (BIAS_SEL) sVsel[tid] = vsel[tid];
    }

    const int arow0 = tid >> 2;
    const int ac4   = (tid & 3) << 2;
    const int brow0 = tid >> 5;
    const int bn4   = (tid & 31) << 2;

    float4 rA[2], rB[2];

    auto loadTile = [&](int t) {
        const bool first = (t < KT1);
        #pragma unroll
        for (int i = 0; i < 2; i++) {
            int row = arow0 + i * 64;
            int m = m0 + row;
            float4 v = make_float4(0.f, 0.f, 0.f, 0.f);
            if (m < M) {
                const float* p = first ? (A1 + (size_t)m * lda1 + t * BK + ac4)
                                       : (A2 + (size_t)m * lda2 + (t - KT1) * BK + ac4);
                v = *(const float4*)p;
            }
            rA[i] = v;
        }
        #pragma unroll
        for (int i = 0; i < 2; i++) {
            int row = brow0 + i * 8;
            const float* p = first ? (B1 + (size_t)(t * BK + row) * 128 + bn4)
                                   : (B2 + (size_t)((t - KT1) * BK + row) * 128 + bn4);
            rB[i] = *(const float4*)p;
        }
    };
    auto storeTile = [&](int buf) {
        #pragma unroll
        for (int i = 0; i < 2; i++) {
            int row = arow0 + i * 64;
            const float* v = &rA[i].x;
            __nv_bfloat16 h[4], l[4];
            #pragma unroll
            for (int j = 0; j < 4; j++) split_f32(v[j], h[j], l[j]);
            *(uint2*)&Ah[buf][row][ac4] = make_uint2(pack_bf16(h[0], h[1]), pack_bf16(h[2], h[3]));
            *(uint2*)&Al[buf][row][ac4] = make_uint2(pack_bf16(l[0], l[1]), pack_bf16(l[2], l[3]));
        }
        #pragma unroll
        for (int i = 0; i < 2; i++) {
            int row = brow0 + i * 8;
            const float* v = &rB[i].x;
            __nv_bfloat16 h[4], l[4];
            #pragma unroll
            for (int j = 0; j < 4; j++) split_f32(v[j], h[j], l[j]);
            *(uint2*)&Bh[buf][row][bn4] = make_uint2(pack_bf16(h[0], h[1]), pack_bf16(h[2], h[3]));
            *(uint2*)&Bl[buf][row][bn4] = make_uint2(pack_bf16(l[0], l[1]), pack_bf16(l[2], l[3]));
        }
    };

    float d[2][8][4];
    #pragma unroll
    for (int mt = 0; mt < 2; mt++)
        #pragma unroll
        for (int nt = 0; nt < 8; nt++)
            #pragma unroll
            for (int j = 0; j < 4; j++) d[mt][nt][j] = 0.f;

    const int ar = lane & 15;
    const int ac = (lane >> 4) << 3;
    const int br = lane & 15;
    const int bc = wn * 64 + ((lane >> 4) << 3);

    loadTile(0);
    storeTile(0);
    __syncthreads();

    for (int t = 0; t < KT; t++) {
        const int cb = t & 1;
        if (t + 1 < KT) loadTile(t + 1);

        uint32_t fah[2][4], fal[2][4];
        #pragma unroll
        for (int mt = 0; mt < 2; mt++) {
            int row = wm * 32 + mt * 16 + ar;
            ldsm_x4(fah[mt], (uint32_t)__cvta_generic_to_shared(&Ah[cb][row][ac]));
            ldsm_x4(fal[mt], (uint32_t)__cvta_generic_to_shared(&Al[cb][row][ac]));
        }
        #pragma unroll
        for (int ntp = 0; ntp < 4; ntp++) {
            uint32_t fbh[4], fbl[4];
            ldsm_x4_t(fbh, (uint32_t)__cvta_generic_to_shared(&Bh[cb][br][bc + ntp * 16]));
            ldsm_x4_t(fbl, (uint32_t)__cvta_generic_to_shared(&Bl[cb][br][bc + ntp * 16]));
            #pragma unroll
            for (int mt = 0; mt < 2; mt++) {
                mma_bf16(d[mt][2 * ntp],     fah[mt], fbh);
                mma_bf16(d[mt][2 * ntp],     fal[mt], fbh);
                mma_bf16(d[mt][2 * ntp],     fah[mt], fbl);
                mma_bf16(d[mt][2 * ntp + 1], fah[mt], fbh + 2);
                mma_bf16(d[mt][2 * ntp + 1], fal[mt], fbh + 2);
                mma_bf16(d[mt][2 * ntp + 1], fah[mt], fbl + 2);
            }
        }
        if (t + 1 < KT) storeTile((t + 1) & 1);
        __syncthreads();
    }

    const int rb  = m0 + wm * 32 + (lane >> 2);
    const int cb0 = wn * 64 + (lane & 3) * 2;
    #pragma unroll
    for (int mt = 0; mt < 2; mt++) {
        #pragma unroll
        for (int h = 0; h < 2; h++) {
            int m = rb + mt * 16 + h * 8;
            if (m >= M) continue;
            float sel = 0.f;
            if (BIAS_SEL) sel = (deg[m] > 0) ? 1.f : 0.f;
            #pragma unroll
            for (int nt = 0; nt < 8; nt++) {
                int col = cb0 + nt * 8;
                float x = d[mt][nt][h * 2 + 0] + sBias[col];
                float y = d[mt][nt][h * 2 + 1] + sBias[col + 1];
                if (BIAS_SEL) { x += sel * sVsel[col]; y += sel * sVsel[col + 1]; }
                if (ADD_D) {
                    float2 dv = *(const float2*)&Dm[(size_t)m * 128 + col];
                    x += dv.x; y += dv.y;
                }
                if (RELU) { x = fmaxf(x, 0.f); y = fmaxf(y, 0.f); }
                *(float2*)&C[(size_t)m * 128 + col] = make_float2(x, y);
            }
        }
    }
}

template<bool BIAS_SEL, bool RELU, bool ADD_D>
__global__ void __launch_bounds__(256)
gemm128_kernel(const float* A1, const float* A2, const float* B1, const float* B2,
               float* C, const float* bias, const float* vsel, const int* deg,
               const float* Dm, int M, int KT1, int KT2) {
    gemm128_body<BIAS_SEL, RELU, ADD_D>(A1, A2, B1, B2, C, bias, vsel, deg, Dm, M, KT1, KT2, blockIdx.x);
}

// ---------------- fused kernels ----------------
// fusedA: GEMM4 (movie_x) || deg || vec.
__global__ void __launch_bounds__(256)
fusedA_kernel(const float* __restrict__ movie_feats, const float* __restrict__ Wm, const float* __restrict__ bm,
              float* __restrict__ movie_x,
              const int* __restrict__ src, const int* __restrict__ dst,
              int* __restrict__ du, int* __restrict__ dm,
              const float* __restrict__ user_init, const float* __restrict__ Wl1_um,
              const float* __restrict__ Wr1_mu, const float* __restrict__ bl1_mu,
              float* __restrict__ vecs,
              int GA, int DEGB) {
    int bid = blockIdx.x;
    int q = bid >> 2, r = bid & 3;
    if (r == 0 && q < GA) {
        gemm128_body<false, false, false>(movie_feats, nullptr, Wm, nullptr, movie_x,
                                          bm, nullptr, nullptr, nullptr, cNM, cFD / BK, 0, q);
    } else {
        int before = min((bid + 3) >> 2, GA);
        int did = bid - before;
        if (did < DEGB) deg_body(src, dst, du, dm, cE, did, DEGB);
        else            vec_body(user_init, Wl1_um, Wr1_mu, bl1_mu, vecs);
    }
}

// fusedB: GEMM5 (movie_h) || P1 || scatter.
__global__ void __launch_bounds__(256)
fusedB_kernel(const float* __restrict__ movie_x,
              const float* __restrict__ Wr1_um, const float* __restrict__ Wl1_mu,
              float* __restrict__ movie_h, float* __restrict__ P1,
              const float* __restrict__ bl1_um, const float* __restrict__ vsel, const int* __restrict__ deg_m,
              const float* __restrict__ zero,
              const int* __restrict__ src, const int* __restrict__ dst,
              int* __restrict__ curU, int* __restrict__ curM,
              int* __restrict__ csrU, int* __restrict__ csrM,
              int GM_, int GA, int SCB) {
    int bid = blockIdx.x;
    int q = bid >> 2, r = bid & 3;
    if (r == 0 && q < GA) {
        if (q < GM_) {
            gemm128_body<true, true, false>(movie_x, nullptr, Wr1_um, nullptr, movie_h,
                                            bl1_um, vsel, deg_m, nullptr, cNM, cH / BK, 0, q);
        } else {
            gemm128_body<false, false, false>(movie_x, nullptr, Wl1_mu, nullptr, P1,
                                              zero, nullptr, nullptr, nullptr, cNM, cH / BK, 0, q - GM_);
        }
    } else {
        int before = min((bid + 3) >> 2, GA);
        int did = bid - before;
        if (did < SCB) scatter_body(src, dst, curU, curM, csrU, csrM, cE, did, SCB);
    }
}

// fusedC: GEMM10' (user_o = user_h@Wr2_mu + bl2_mu + aggP2) || agg_movie.
__global__ void __launch_bounds__(256)
fusedC_kernel(const float* __restrict__ user_h, const float* __restrict__ Wr2_mu,
              float* __restrict__ user_o, const float* __restrict__ bl2_mu,
              const float* __restrict__ aggP2,
              const int* __restrict__ offM, const int* __restrict__ csrM,
              float* __restrict__ aggM2,
              int GA, int AGB) {
    int bid = blockIdx.x;
    int q = bid >> 1, r = bid & 1;
    if (r == 0 && q < GA) {
        gemm128_body<false, false, true>(user_h, nullptr, Wr2_mu, nullptr, user_o,
                                         bl2_mu, nullptr, nullptr, aggP2, cNU, cH / BK, 0, q);
    } else {
        int before = min((bid + 1) >> 1, GA);
        int aid = bid - before;
        if (aid < AGB) agg_movie_body(offM, csrM, user_h, aggM2, cNM, aid, AGB);
    }
}

// ---------------- final edge dot products (2-edge unroll) ----------------
__global__ void dot_kernel(const int* __restrict__ lu, const int* __restrict__ lm,
                           const float* __restrict__ U, const float* __restrict__ Mo,
                           float* __restrict__ out, int EL) {
    int w    = (blockIdx.x * blockDim.x + threadIdx.x) >> 5;
    int lane = threadIdx.x & 31;
    int nw   = (gridDim.x * blockDim.x) >> 5;
    for (int i = w; i < EL; i += 2 * nw) {
        int i2 = i + nw;
        bool has2 = (i2 < EL);
        int u0 = lu[i], m0 = lm[i];
        float4 a0 = ((const float4*)(U  + (size_t)u0 * 128))[lane];
        float4 b0 = ((const float4*)(Mo + (size_t)m0 * 128))[lane];
        float p0 = a0.x * b0.x + a0.y * b0.y + a0.z * b0.z + a0.w * b0.w;
        float p1 = 0.f;
        if (has2) {
            int u1 = lu[i2], m1 = lm[i2];
            float4 a1 = ((const float4*)(U  + (size_t)u1 * 128))[lane];
            float4 b1 = ((const float4*)(Mo + (size_t)m1 * 128))[lane];
            p1 = a1.x * b1.x + a1.y * b1.y + a1.z * b1.z + a1.w * b1.w;
        }
        #pragma unroll
        for (int off = 16; off > 0; off >>= 1) {
            p0 += __shfl_xor_sync(0xFFFFFFFFu, p0, off);
            p1 += __shfl_xor_sync(0xFFFFFFFFu, p1, off);
        }
        if (lane == 0) {
            out[i] = p0;
            if (has2) out[i2] = p1;
        }
    }
}

// ---------------- launch ----------------
extern "C" void kernel_launch(void* const* d_in, const int* in_sizes, int n_in,
                              void* d_out, int out_size) {
    const float* movie_feats = (const float*)d_in[0];
    const float* user_init   = (const float*)d_in[1];
    const int*   edge_src    = (const int*)d_in[2];
    const int*   edge_dst    = (const int*)d_in[3];
    const int*   lbl_user    = (const int*)d_in[4];
    const int*   lbl_movie   = (const int*)d_in[5];
    const int wi = (n_in >= 21) ? 7 : 6;
    const float* Wm     = (const float*)d_in[wi + 0];
    const float* bm     = (const float*)d_in[wi + 1];
    const float* Wl1_um = (const float*)d_in[wi + 2];
    const float* bl1_um = (const float*)d_in[wi + 3];
    const float* Wr1_um = (const float*)d_in[wi + 4];
    const float* Wl1_mu = (const float*)d_in[wi + 5];
    const float* bl1_mu = (const float*)d_in[wi + 6];
    const float* Wr1_mu = (const float*)d_in[wi + 7];
    const float* Wl2_um = (const float*)d_in[wi + 8];
    const float* bl2_um = (const float*)d_in[wi + 9];
    const float* Wr2_um = (const float*)d_in[wi + 10];
    const float* Wl2_mu = (const float*)d_in[wi + 11];
    const float* bl2_mu = (const float*)d_in[wi + 12];
    const float* Wr2_mu = (const float*)d_in[wi + 13];
    float* out = (float*)d_out;

    float *movie_x, *movie_h, *P1, *P2, *user_h, *aggP2, *aggM2, *movie_o, *user_o, *vecs, *zero;
    int *deg_u, *deg_m, *offU, *offM, *curU, *curM, *csrU, *csrM, *partU, *partM;
    cudaGetSymbolAddress((void**)&movie_x, g_movie_x);
    cudaGetSymbolAddress((void**)&movie_h, g_movie_h);
    cudaGetSymbolAddress((void**)&P1,      g_P1);
    cudaGetSymbolAddress((void**)&P2,      g_P2);
    cudaGetSymbolAddress((void**)&user_h,  g_user_h);
    cudaGetSymbolAddress((void**)&aggP2,   g_aggP2);
    cudaGetSymbolAddress((void**)&aggM2,   g_aggM2);
    cudaGetSymbolAddress((void**)&movie_o, g_movie_o);
    cudaGetSymbolAddress((void**)&user_o,  g_user_o);
    cudaGetSymbolAddress((void**)&vecs,    g_vecs);
    cudaGetSymbolAddress((void**)&zero,    g_zero);
    cudaGetSymbolAddress((void**)&deg_u,   g_deg_u);
    cudaGetSymbolAddress((void**)&deg_m,   g_deg_m);
    cudaGetSymbolAddress((void**)&offU,    g_offU);
    cudaGetSymbolAddress((void**)&offM,    g_offM);
    cudaGetSymbolAddress((void**)&curU,    g_curU);
    cudaGetSymbolAddress((void**)&curM,    g_curM);
    cudaGetSymbolAddress((void**)&csrU,    g_csrU);
    cudaGetSymbolAddress((void**)&csrM,    g_csrM);
    cudaGetSymbolAddress((void**)&partU,   g_partU);
    cudaGetSymbolAddress((void**)&partM,   g_partM);

    const int GM = (cNM + 127) / 128;   // 625
    const int GU = (cNU + 127) / 128;   // 1563

    // 1) zero degree counters
    zero2_kernel<<<384, 256>>>(deg_u, cNU, deg_m, cNM);

    // 2) fusedA: GEMM4 || deg || vec
    const int DEGB = 2048;
    fusedA_kernel<<<GM + DEGB + 1, 256>>>(movie_feats, Wm, bm, movie_x,
                                          edge_src, edge_dst, deg_u, deg_m,
                                          user_init, Wl1_um, Wr1_mu, bl1_mu, vecs,
                                          GM, DEGB);

    // 3) CSR offsets
    partial_kernel<<<TU + TM, 256>>>(deg_u, deg_m, partU, partM);
    scanpart_kernel<<<2, 256>>>(partU, partM);
    phase3_kernel<<<TU + TM, 256>>>(deg_u, deg_m, partU, partM, offU, curU, offM, curM);

    // 4) fusedB: GEMM5 || P1 || scatter
    {
        const int GA = 2 * GM;            // 1250 gemm virtual blocks
        const int grid = 4 * GA;          // 5000
        const int SCB = grid - GA;        // 3750 scatter virtual blocks
        fusedB_kernel<<<grid, 256>>>(movie_x, Wr1_um, Wl1_mu, movie_h, P1,
                                     bl1_um, vecs, deg_m, zero,
                                     edge_src, edge_dst, curU, curM, csrU, csrM,
                                     GM, GA, SCB);
    }

    // 5) P2 = movie_h @ Wl2_mu
    gemm128_kernel<false, false, false><<<GM, 256>>>(
        movie_h, nullptr, Wl2_mu, nullptr, P2, zero, nullptr, nullptr, nullptr, cNM, cH / BK, 0);

    // 6) user-side aggregation: user_h = relu(meanP1 + cb1), aggP2 = meanP2
    agg_user_kernel<<<4736, 256>>>(offU, csrU, P1, P2, vecs, user_h, aggP2, cNU);

    // 7) fusedC: GEMM10' (user_o) || agg_movie
    {
        const int gridC = 2 * GU;
        const int AGB = gridC - GU;
        fusedC_kernel<<<gridC, 256>>>(user_h, Wr2_mu, user_o, bl2_mu, aggP2,
                                      offM, csrM, aggM2, GU, AGB);
    }

    // 8) GEMM9: movie_o = aggM2 @ Wl2_um + bl2_um + movie_h @ Wr2_um
    gemm128_kernel<false, false, false><<<GM, 256>>>(
        aggM2, movie_h, Wl2_um, Wr2_um, movie_o, bl2_um, nullptr, nullptr, nullptr,
        cNM, cH / BK, cH / BK);

    // 9) final dot products
    dot_kernel<<<4736, 256>>>(lbl_user, lbl_movie, user_o, movie_o, out, cEL);

    (void)in_sizes; (void)out_size;
}

// round 13
// speedup vs baseline: 1.1459x; 1.0257x over previous
#include <cuda_runtime.h>
#include <cuda_bf16.h>
#include <cstddef>
#include <cstdint>

// Problem constants
#define cH   128
#define cNU  200000
#define cNM  80000
#define cE   2000000
#define cEL  500000
#define cFD  512

#define TILE 1024
#define TU   ((cNU + TILE - 1) / TILE)   // 196
#define TM   ((cNM + TILE - 1) / TILE)   // 79

// ---------------- scratch (device globals) ----------------
__device__ float g_movie_x[(size_t)cNM * cH];
__device__ float g_movie_h[(size_t)cNM * cH];
__device__ float g_P1[(size_t)cNM * cH];      // movie_x @ Wl1_mu
__device__ float g_user_h [(size_t)cNU * cH];
__device__ float g_aggH2 [(size_t)cNU * cH];  // per-user mean of movie_h
__device__ float g_aggM2 [(size_t)cNM * cH];
__device__ float g_movie_o[(size_t)cNM * cH];
__device__ float g_user_o [(size_t)cNU * cH];
__device__ int   g_deg_u[cNU];
__device__ int   g_deg_m[cNM];
__device__ int   g_offU[cNU + 1];
__device__ int   g_offM[cNM + 1];
__device__ int   g_curU[cNU];
__device__ int   g_curM[cNM];
__device__ int   g_csrU[cE];
__device__ int   g_csrM[cE];
__device__ int   g_partU[TU];
__device__ int   g_partM[TM];
__device__ float g_vecs[2 * cH];
__device__ float g_zero[cH];

// ---------------- utility ----------------
__global__ void zero2_kernel(int* p1, int n1, int* p2, int n2) {
    int i = blockIdx.x * blockDim.x + threadIdx.x;
    int stride = gridDim.x * blockDim.x;
    for (int k = i; k < n1; k += stride) p1[k] = 0;
    for (int k = i; k < n2; k += stride) p2[k] = 0;
}

// ---- device bodies ----
__device__ __forceinline__ void deg_body(const int* __restrict__ src, const int* __restrict__ dst,
                                         int* __restrict__ du, int* __restrict__ dm,
                                         int E, int vbid, int vgrid) {
    int i = vbid * 256 + threadIdx.x;
    int stride = vgrid * 256;
    for (; i < E; i += stride) {
        atomicAdd(&du[src[i]], 1);
        atomicAdd(&dm[dst[i]], 1);
    }
}

__device__ __forceinline__ void scatter_body(const int* __restrict__ src, const int* __restrict__ dst,
                                             int* __restrict__ curU, int* __restrict__ curM,
                                             int* __restrict__ csrU, int* __restrict__ csrM,
                                             int E, int vbid, int vgrid) {
    int i = vbid * 256 + threadIdx.x;
    int stride = vgrid * 256;
    for (; i < E; i += stride) {
        int s = src[i];
        int d = dst[i];
        int p = atomicAdd(&curU[s], 1);
        csrU[p] = d;
        int q = atomicAdd(&curM[d], 1);
        csrM[q] = s;
    }
}

__device__ __forceinline__ void vec_body(const float* __restrict__ user_init,
                                         const float* __restrict__ Wl1_um,
                                         const float* __restrict__ Wr1_mu,
                                         const float* __restrict__ bl1_mu,
                                         float* __restrict__ vecs) {
    int j = threadIdx.x;
    if (j >= cH) return;
    float s1 = 0.f, s2 = 0.f;
    for (int k = 0; k < cH; k++) {
        float u = user_init[k];
        s1 = fmaf(u, Wl1_um[k * cH + j], s1);
        s2 = fmaf(u, Wr1_mu[k * cH + j], s2);
    }
    vecs[j]      = s1;
    vecs[cH + j] = bl1_mu[j] + s2;
}

__device__ __forceinline__ void agg_movie_body(const int* __restrict__ off, const int* __restrict__ csr,
                                               const float* __restrict__ uh,
                                               float* __restrict__ aM2, int NM, int vbid, int vgrid) {
    int w    = vbid * 8 + (threadIdx.x >> 5);
    int lane = threadIdx.x & 31;
    int nw   = vgrid * 8;
    for (int m = w; m < NM; m += nw) {
        int s = off[m], e = off[m + 1];
        float4 a1 = make_float4(0.f, 0.f, 0.f, 0.f);
        float4 a2 = make_float4(0.f, 0.f, 0.f, 0.f);
        int i = s;
        for (; i + 1 < e; i += 2) {
            int d0 = csr[i];
            int d1 = csr[i + 1];
            float4 v0 = ((const float4*)(uh + (size_t)d0 * 128))[lane];
            float4 v1 = ((const float4*)(uh + (size_t)d1 * 128))[lane];
            a1.x += v0.x; a1.y += v0.y; a1.z += v0.z; a1.w += v0.w;
            a2.x += v1.x; a2.y += v1.y; a2.z += v1.z; a2.w += v1.w;
        }
        if (i < e) {
            int d0 = csr[i];
            float4 v0 = ((const float4*)(uh + (size_t)d0 * 128))[lane];
            a1.x += v0.x; a1.y += v0.y; a1.z += v0.z; a1.w += v0.w;
        }
        float sc = (e > s) ? 1.f / (float)(e - s) : 0.f;
        float4 o = make_float4((a1.x + a2.x) * sc, (a1.y + a2.y) * sc, (a1.z + a2.z) * sc, (a1.w + a2.w) * sc);
        ((float4*)(aM2 + (size_t)m * 128))[lane] = o;
    }
}

// ---- parallel scan ----
__global__ void partial_kernel(const int* __restrict__ degU, const int* __restrict__ degM,
                               int* __restrict__ partU, int* __restrict__ partM) {
    int b = blockIdx.x;
    const int* deg; int* part; int n, tile;
    if (b < TU) { deg = degU; part = partU; n = cNU; tile = b; }
    else        { deg = degM; part = partM; n = cNM; tile = b - TU; }

    int tid = threadIdx.x;
    int base = tile * TILE + tid * 4;
    int s = 0;
    #pragma unroll
    for (int j = 0; j < 4; j++) {
        int i = base + j;
        if (i < n) s += deg[i];
    }
    __shared__ int wsum[8];
    int lane = tid & 31, wid = tid >> 5;
    #pragma unroll
    for (int o = 16; o > 0; o >>= 1) s += __shfl_down_sync(0xffffffffu, s, o);
    if (lane == 0) wsum[wid] = s;
    __syncthreads();
    if (tid == 0) {
        int t = 0;
        #pragma unroll
        for (int w = 0; w < 8; w++) t += wsum[w];
        part[tile] = t;
    }
}

__global__ void scanpart_kernel(int* __restrict__ partU, int* __restrict__ partM) {
    int* part = (blockIdx.x == 0) ? partU : partM;
    int cnt   = (blockIdx.x == 0) ? TU : TM;
    int tid = threadIdx.x, lane = tid & 31, wid = tid >> 5;
    __shared__ int wsum[8];
    int v = (tid < cnt) ? part[tid] : 0;
    int x = v;
    #pragma unroll
    for (int o = 1; o < 32; o <<= 1) {
        int t = __shfl_up_sync(0xffffffffu, x, o);
        if (lane >= o) x += t;
    }
    if (lane == 31) wsum[wid] = x;
    __syncthreads();
    if (wid == 0) {
        int s = (lane < 8) ? wsum[lane] : 0;
        #pragma unroll
        for (int o = 1; o < 8; o <<= 1) {
            int t = __shfl_up_sync(0xffffffffu, s, o);
            if (lane >= o) s += t;
        }
        if (lane < 8) wsum[lane] = s;
    }
    __syncthreads();
    int incl = x + ((wid > 0) ? wsum[wid - 1] : 0);
    if (tid < cnt) part[tid] = incl - v;
}

__global__ void phase3_kernel(const int* __restrict__ degU, const int* __restrict__ degM,
                              const int* __restrict__ partU, const int* __restrict__ partM,
                              int* __restrict__ offU, int* __restrict__ curU,
                              int* __restrict__ offM, int* __restrict__ curM) {
    int b = blockIdx.x;
    const int* deg; const int* part; int* off; int* cur; int n, tile;
    if (b < TU) { deg = degU; part = partU; off = offU; cur = curU; n = cNU; tile = b; }
    else        { deg = degM; part = partM; off = offM; cur = curM; n = cNM; tile = b - TU; }

    int tid = threadIdx.x, lane = tid & 31, wid = tid >> 5;
    if (b == 0 && tid == 0) { offU[cNU] = cE; offM[cNM] = cE; }

    int base = tile * TILE + tid * 4;
    int v[4];
    int s = 0;
    #pragma unroll
    for (int j = 0; j < 4; j++) {
        int i = base + j;
        v[j] = (i < n) ? deg[i] : 0;
        s += v[j];
    }
    __shared__ int wsum[8];
    int x = s;
    #pragma unroll
    for (int o = 1; o < 32; o <<= 1) {
        int t = __shfl_up_sync(0xffffffffu, x, o);
        if (lane >= o) x += t;
    }
    if (lane == 31) wsum[wid] = x;
    __syncthreads();
    if (wid == 0) {
        int t = (lane < 8) ? wsum[lane] : 0;
        #pragma unroll
        for (int o = 1; o < 8; o <<= 1) {
            int u = __shfl_up_sync(0xffffffffu, t, o);
            if (lane >= o) t += u;
        }
        if (lane < 8) wsum[lane] = t;
    }
    __syncthreads();
    int excl = x - s + ((wid > 0) ? wsum[wid - 1] : 0);
    int run = part[tile] + excl;
    #pragma unroll
    for (int j = 0; j < 4; j++) {
        int i = base + j;
        if (i < n) { off[i] = run; cur[i] = run; run += v[j]; }
    }
}

// ---------------- user-side aggregation: gather P1 + movie_h ----------------
// user_h = relu(mean P1[d] + cb1) ; aggH2 = mean movie_h[d]
__global__ void agg_user_kernel(const int* __restrict__ off, const int* __restrict__ csr,
                                const float* __restrict__ P1, const float* __restrict__ MH,
                                const float* __restrict__ vecs,
                                float* __restrict__ user_h, float* __restrict__ aggH2, int NU) {
    int w    = (blockIdx.x * blockDim.x + threadIdx.x) >> 5;
    int lane = threadIdx.x & 31;
    int nw   = (gridDim.x * blockDim.x) >> 5;
    float4 c1 = ((const float4*)(vecs + cH))[lane];
    for (int u = w; u < NU; u += nw) {
        int s = off[u], e = off[u + 1];
        float4 a1 = make_float4(0.f, 0.f, 0.f, 0.f);
        float4 a2 = make_float4(0.f, 0.f, 0.f, 0.f);
        float4 a3 = make_float4(0.f, 0.f, 0.f, 0.f);
        float4 a4 = make_float4(0.f, 0.f, 0.f, 0.f);
        int i = s;
        for (; i + 1 < e; i += 2) {
            int d0 = csr[i];
            int d1 = csr[i + 1];
            float4 v0 = ((const float4*)(P1 + (size_t)d0 * 128))[lane];
            float4 w0 = ((const float4*)(MH + (size_t)d0 * 128))[lane];
            float4 v1 = ((const float4*)(P1 + (size_t)d1 * 128))[lane];
            float4 w1 = ((const float4*)(MH + (size_t)d1 * 128))[lane];
            a1.x += v0.x; a1.y += v0.y; a1.z += v0.z; a1.w += v0.w;
            a2.x += w0.x; a2.y += w0.y; a2.z += w0.z; a2.w += w0.w;
            a3.x += v1.x; a3.y += v1.y; a3.z += v1.z; a3.w += v1.w;
            a4.x += w1.x; a4.y += w1.y; a4.z += w1.z; a4.w += w1.w;
        }
        if (i < e) {
            int d0 = csr[i];
            float4 v0 = ((const float4*)(P1 + (size_t)d0 * 128))[lane];
            float4 w0 = ((const float4*)(MH + (size_t)d0 * 128))[lane];
            a1.x += v0.x; a1.y += v0.y; a1.z += v0.z; a1.w += v0.w;
            a2.x += w0.x; a2.y += w0.y; a2.z += w0.z; a2.w += w0.w;
        }
        float sc = (e > s) ? 1.f / (float)(e - s) : 0.f;
        float4 o1 = make_float4(fmaxf((a1.x + a3.x) * sc + c1.x, 0.f),
                                fmaxf((a1.y + a3.y) * sc + c1.y, 0.f),
                                fmaxf((a1.z + a3.z) * sc + c1.z, 0.f),
                                fmaxf((a1.w + a3.w) * sc + c1.w, 0.f));
        float4 o2 = make_float4((a2.x + a4.x) * sc, (a2.y + a4.y) * sc, (a2.z + a4.z) * sc, (a2.w + a4.w) * sc);
        ((float4*)(user_h + (size_t)u * 128))[lane] = o1;
        ((float4*)(aggH2 + (size_t)u * 128))[lane] = o2;
    }
}

// ---------------- tensor-core SGEMM via split-bf16 ----------------
#define BK   16
#define ASTR 24
#define BSTR 136

__device__ __forceinline__ unsigned pack_bf16(__nv_bfloat16 a, __nv_bfloat16 b) {
    __nv_bfloat162 t = __halves2bfloat162(a, b);
    return reinterpret_cast<unsigned&>(t);
}
__device__ __forceinline__ void split_f32(float x, __nv_bfloat16& h, __nv_bfloat16& l) {
    h = __float2bfloat16(x);
    l = __float2bfloat16(x - __bfloat162float(h));
}
__device__ __forceinline__ void ldsm_x4(uint32_t* r, uint32_t addr) {
    asm volatile("ldmatrix.sync.aligned.m8n8.x4.shared.b16 {%0,%1,%2,%3}, [%4];"
                 : "=r"(r[0]), "=r"(r[1]), "=r"(r[2]), "=r"(r[3]) : "r"(addr));
}
__device__ __forceinline__ void ldsm_x4_t(uint32_t* r, uint32_t addr) {
    asm volatile("ldmatrix.sync.aligned.m8n8.x4.trans.shared.b16 {%0,%1,%2,%3}, [%4];"
                 : "=r"(r[0]), "=r"(r[1]), "=r"(r[2]), "=r"(r[3]) : "r"(addr));
}
__device__ __forceinline__ void mma_bf16(float* d, const uint32_t* a, const uint32_t* b) {
    asm volatile("mma.sync.aligned.m16n8k16.row.col.f32.bf16.bf16.f32 "
                 "{%0,%1,%2,%3}, {%4,%5,%6,%7}, {%8,%9}, {%0,%1,%2,%3};"
                 : "+f"(d[0]), "+f"(d[1]), "+f"(d[2]), "+f"(d[3])
                 : "r"(a[0]), "r"(a[1]), "r"(a[2]), "r"(a[3]), "r"(b[0]), "r"(b[1]));
}

template<bool BIAS_SEL, bool RELU, bool ADD_D>
__device__ __forceinline__ void gemm128_body(
    const float* __restrict__ A1, const float* __restrict__ A2,
    const float* __restrict__ B1, const float* __restrict__ B2,
    float* __restrict__ C,
    const float* __restrict__ bias, const float* __restrict__ vsel,
    const int* __restrict__ deg, const float* __restrict__ Dm,
    int M, int KT1, int KT2, int bid) {
    __shared__ __nv_bfloat16 Ah[2][128][ASTR];
    __shared__ __nv_bfloat16 Al[2][128][ASTR];
    __shared__ __nv_bfloat16 Bh[2][BK][BSTR];
    __shared__ __nv_bfloat16 Bl[2][BK][BSTR];
    __shared__ float sBias[128];
    __shared__ float sVsel[128];

    const int tid  = threadIdx.x;
    const int lane = tid & 31;
    const int wid  = tid >> 5;
    const int wm   = wid & 3;
    const int wn   = wid >> 2;
    const int m0   = bid * 128;
    const int lda1 = KT1 * BK;
    const int lda2 = KT2 * BK;
    const int KT   = KT1 + KT2;

    if (tid < 128) {
        sBias[tid] = bias[tid];
        if (BIAS_SEL) sVsel[tid] = vsel[tid];
    }

    const int arow0 = tid >> 2;
    const int ac4   = (tid & 3) << 2;
    const int brow0 = tid >> 5;
    const int bn4   = (tid & 31) << 2;

    float4 rA[2], rB[2];

    auto loadTile = [&](int t) {
        const bool first = (t < KT1);
        #pragma unroll
        for (int i = 0; i < 2; i++) {
            int row = arow0 + i * 64;
            int m = m0 + row;
            float4 v = make_float4(0.f, 0.f, 0.f, 0.f);
            if (m < M) {
                const float* p = first ? (A1 + (size_t)m * lda1 + t * BK + ac4)
                                       : (A2 + (size_t)m * lda2 + (t - KT1) * BK + ac4);
                v = *(const float4*)p;
            }
            rA[i] = v;
        }
        #pragma unroll
        for (int i = 0; i < 2; i++) {
            int row = brow0 + i * 8;
            const float* p = first ? (B1 + (size_t)(t * BK + row) * 128 + bn4)
                                   : (B2 + (size_t)((t - KT1) * BK + row) * 128 + bn4);
            rB[i] = *(const float4*)p;
        }
    };
    auto storeTile = [&](int buf) {
        #pragma unroll
        for (int i = 0; i < 2; i++) {
            int row = arow0 + i * 64;
            const float* v = &rA[i].x;
            __nv_bfloat16 h[4], l[4];
            #pragma unroll
            for (int j = 0; j < 4; j++) split_f32(v[j], h[j], l[j]);
            *(uint2*)&Ah[buf][row][ac4] = make_uint2(pack_bf16(h[0], h[1]), pack_bf16(h[2], h[3]));
            *(uint2*)&Al[buf][row][ac4] = make_uint2(pack_bf16(l[0], l[1]), pack_bf16(l[2], l[3]));
        }
        #pragma unroll
        for (int i = 0; i < 2; i++) {
            int row = brow0 + i * 8;
            const float* v = &rB[i].x;
            __nv_bfloat16 h[4], l[4];
            #pragma unroll
            for (int j = 0; j < 4; j++) split_f32(v[j], h[j], l[j]);
            *(uint2*)&Bh[buf][row][bn4] = make_uint2(pack_bf16(h[0], h[1]), pack_bf16(h[2], h[3]));
            *(uint2*)&Bl[buf][row][bn4] = make_uint2(pack_bf16(l[0], l[1]), pack_bf16(l[2], l[3]));
        }
    };

    float d[2][8][4];
    #pragma unroll
    for (int mt = 0; mt < 2; mt++)
        #pragma unroll
        for (int nt = 0; nt < 8; nt++)
            #pragma unroll
            for (int j = 0; j < 4; j++) d[mt][nt][j] = 0.f;

    const int ar = lane & 15;
    const int ac = (lane >> 4) << 3;
    const int br = lane & 15;
    const int bc = wn * 64 + ((lane >> 4) << 3);

    loadTile(0);
    storeTile(0);
    __syncthreads();

    for (int t = 0; t < KT; t++) {
        const int cb = t & 1;
        if (t + 1 < KT) loadTile(t + 1);

        uint32_t fah[2][4], fal[2][4];
        #pragma unroll
        for (int mt = 0; mt < 2; mt++) {
            int row = wm * 32 + mt * 16 + ar;
            ldsm_x4(fah[mt], (uint32_t)__cvta_generic_to_shared(&Ah[cb][row][ac]));
            ldsm_x4(fal[mt], (uint32_t)__cvta_generic_to_shared(&Al[cb][row][ac]));
        }
        #pragma unroll
        for (int ntp = 0; ntp < 4; ntp++) {
            uint32_t fbh[4], fbl[4];
            ldsm_x4_t(fbh, (uint32_t)__cvta_generic_to_shared(&Bh[cb][br][bc + ntp * 16]));
            ldsm_x4_t(fbl, (uint32_t)__cvta_generic_to_shared(&Bl[cb][br][bc + ntp * 16]));
            #pragma unroll
            for (int mt = 0; mt < 2; mt++) {
                mma_bf16(d[mt][2 * ntp],     fah[mt], fbh);
                mma_bf16(d[mt][2 * ntp],     fal[mt], fbh);
                mma_bf16(d[mt][2 * ntp],     fah[mt], fbl);
                mma_bf16(d[mt][2 * ntp + 1], fah[mt], fbh + 2);
                mma_bf16(d[mt][2 * ntp + 1], fal[mt], fbh + 2);
                mma_bf16(d[mt][2 * ntp + 1], fah[mt], fbl + 2);
            }
        }
        if (t + 1 < KT) storeTile((t + 1) & 1);
        __syncthreads();
    }

    const int rb  = m0 + wm * 32 + (lane >> 2);
    const int cb0 = wn * 64 + (lane & 3) * 2;
    #pragma unroll
    for (int mt = 0; mt < 2; mt++) {
        #pragma unroll
        for (int h = 0; h < 2; h++) {
            int m = rb + mt * 16 + h * 8;
            if (m >= M) continue;
            float sel = 0.f;
            if (BIAS_SEL) sel = (deg[m] > 0) ? 1.f : 0.f;
            #pragma unroll
            for (int nt = 0; nt < 8; nt++) {
                int col = cb0 + nt * 8;
                float x = d[mt][nt][h * 2 + 0] + sBias[col];
                float y = d[mt][nt][h * 2 + 1] + sBias[col + 1];
                if (BIAS_SEL) { x += sel * sVsel[col]; y += sel * sVsel[col + 1]; }
                if (ADD_D) {
                    float2 dv = *(const float2*)&Dm[(size_t)m * 128 + col];
                    x += dv.x; y += dv.y;
                }
                if (RELU) { x = fmaxf(x, 0.f); y = fmaxf(y, 0.f); }
                *(float2*)&C[(size_t)m * 128 + col] = make_float2(x, y);
            }
        }
    }
}

template<bool BIAS_SEL, bool RELU, bool ADD_D>
__global__ void __launch_bounds__(256)
gemm128_kernel(const float* A1, const float* A2, const float* B1, const float* B2,
               float* C, const float* bias, const float* vsel, const int* deg,
               const float* Dm, int M, int KT1, int KT2) {
    gemm128_body<BIAS_SEL, RELU, ADD_D>(A1, A2, B1, B2, C, bias, vsel, deg, Dm, M, KT1, KT2, blockIdx.x);
}

// ---------------- fused kernels ----------------
// fusedA: GEMM4 (movie_x) || deg || vec.
__global__ void __launch_bounds__(256)
fusedA_kernel(const float* __restrict__ movie_feats, const float* __restrict__ Wm, const float* __restrict__ bm,
              float* __restrict__ movie_x,
              const int* __restrict__ src, const int* __restrict__ dst,
              int* __restrict__ du, int* __restrict__ dm,
              const float* __restrict__ user_init, const float* __restrict__ Wl1_um,
              const float* __restrict__ Wr1_mu, const float* __restrict__ bl1_mu,
              float* __restrict__ vecs,
              int GA, int DEGB) {
    int bid = blockIdx.x;
    int q = bid >> 2, r = bid & 3;
    if (r == 0 && q < GA) {
        gemm128_body<false, false, false>(movie_feats, nullptr, Wm, nullptr, movie_x,
                                          bm, nullptr, nullptr, nullptr, cNM, cFD / BK, 0, q);
    } else {
        int before = min((bid + 3) >> 2, GA);
        int did = bid - before;
        if (did < DEGB) deg_body(src, dst, du, dm, cE, did, DEGB);
        else            vec_body(user_init, Wl1_um, Wr1_mu, bl1_mu, vecs);
    }
}

// fusedB: GEMM5 (movie_h) || P1 || scatter.
__global__ void __launch_bounds__(256)
fusedB_kernel(const float* __restrict__ movie_x,
              const float* __restrict__ Wr1_um, const float* __restrict__ Wl1_mu,
              float* __restrict__ movie_h, float* __restrict__ P1,
              const float* __restrict__ bl1_um, const float* __restrict__ vsel, const int* __restrict__ deg_m,
              const float* __restrict__ zero,
              const int* __restrict__ src, const int* __restrict__ dst,
              int* __restrict__ curU, int* __restrict__ curM,
              int* __restrict__ csrU, int* __restrict__ csrM,
              int GM_, int GA, int SCB) {
    int bid = blockIdx.x;
    int q = bid >> 2, r = bid & 3;
    if (r == 0 && q < GA) {
        if (q < GM_) {
            gemm128_body<true, true, false>(movie_x, nullptr, Wr1_um, nullptr, movie_h,
                                            bl1_um, vsel, deg_m, nullptr, cNM, cH / BK, 0, q);
        } else {
            gemm128_body<false, false, false>(movie_x, nullptr, Wl1_mu, nullptr, P1,
                                              zero, nullptr, nullptr, nullptr, cNM, cH / BK, 0, q - GM_);
        }
    } else {
        int before = min((bid + 3) >> 2, GA);
        int did = bid - before;
        if (did < SCB) scatter_body(src, dst, curU, curM, csrU, csrM, cE, did, SCB);
    }
}

// fusedC: GEMM10 (user_o = aggH2@Wl2_mu + bl2_mu + user_h@Wr2_mu, K=256 concat) || agg_movie.
__global__ void __launch_bounds__(256)
fusedC_kernel(const float* __restrict__ aggH2, const float* __restrict__ user_h,
              const float* __restrict__ Wl2_mu, const float* __restrict__ Wr2_mu,
              float* __restrict__ user_o, const float* __restrict__ bl2_mu,
              const int* __restrict__ offM, const int* __restrict__ csrM,
              float* __restrict__ aggM2,
              int GA, int AGB) {
    int bid = blockIdx.x;
    int q = bid >> 1, r = bid & 1;
    if (r == 0 && q < GA) {
        gemm128_body<false, false, false>(aggH2, user_h, Wl2_mu, Wr2_mu, user_o,
                                          bl2_mu, nullptr, nullptr, nullptr, cNU, cH / BK, cH / BK, q);
    } else {
        int before = min((bid + 1) >> 1, GA);
        int aid = bid - before;
        if (aid < AGB) agg_movie_body(offM, csrM, user_h, aggM2, cNM, aid, AGB);
    }
}

// ---------------- final edge dot products ----------------
__global__ void dot_kernel(const int* __restrict__ lu, const int* __restrict__ lm,
                           const float* __restrict__ U, const float* __restrict__ Mo,
                           float* __restrict__ out, int EL) {
    int w    = (blockIdx.x * blockDim.x + threadIdx.x) >> 5;
    int lane = threadIdx.x & 31;
    int nw   = (gridDim.x * blockDim.x) >> 5;
    for (int i = w; i < EL; i += nw) {
        int u = lu[i];
        int m = lm[i];
        float4 a = ((const float4*)(U  + (size_t)u * 128))[lane];
        float4 b = ((const float4*)(Mo + (size_t)m * 128))[lane];
        float p = a.x * b.x + a.y * b.y + a.z * b.z + a.w * b.w;
        #pragma unroll
        for (int off = 16; off > 0; off >>= 1)
            p += __shfl_xor_sync(0xFFFFFFFFu, p, off);
        if (lane == 0) out[i] = p;
    }
}

// ---------------- launch ----------------
extern "C" void kernel_launch(void* const* d_in, const int* in_sizes, int n_in,
                              void* d_out, int out_size) {
    const float* movie_feats = (const float*)d_in[0];
    const float* user_init   = (const float*)d_in[1];
    const int*   edge_src    = (const int*)d_in[2];
    const int*   edge_dst    = (const int*)d_in[3];
    const int*   lbl_user    = (const int*)d_in[4];
    const int*   lbl_movie   = (const int*)d_in[5];
    const int wi = (n_in >= 21) ? 7 : 6;
    const float* Wm     = (const float*)d_in[wi + 0];
    const float* bm     = (const float*)d_in[wi + 1];
    const float* Wl1_um = (const float*)d_in[wi + 2];
    const float* bl1_um = (const float*)d_in[wi + 3];
    const float* Wr1_um = (const float*)d_in[wi + 4];
    const float* Wl1_mu = (const float*)d_in[wi + 5];
    const float* bl1_mu = (const float*)d_in[wi + 6];
    const float* Wr1_mu = (const float*)d_in[wi + 7];
    const float* Wl2_um = (const float*)d_in[wi + 8];
    const float* bl2_um = (const float*)d_in[wi + 9];
    const float* Wr2_um = (const float*)d_in[wi + 10];
    const float* Wl2_mu = (const float*)d_in[wi + 11];
    const float* bl2_mu = (const float*)d_in[wi + 12];
    const float* Wr2_mu = (const float*)d_in[wi + 13];
    float* out = (float*)d_out;

    float *movie_x, *movie_h, *P1, *user_h, *aggH2, *aggM2, *movie_o, *user_o, *vecs, *zero;
    int *deg_u, *deg_m, *offU, *offM, *curU, *curM, *csrU, *csrM, *partU, *partM;
    cudaGetSymbolAddress((void**)&movie_x, g_movie_x);
    cudaGetSymbolAddress((void**)&movie_h, g_movie_h);
    cudaGetSymbolAddress((void**)&P1,      g_P1);
    cudaGetSymbolAddress((void**)&user_h,  g_user_h);
    cudaGetSymbolAddress((void**)&aggH2,   g_aggH2);
    cudaGetSymbolAddress((void**)&aggM2,   g_aggM2);
    cudaGetSymbolAddress((void**)&movie_o, g_movie_o);
    cudaGetSymbolAddress((void**)&user_o,  g_user_o);
    cudaGetSymbolAddress((void**)&vecs,    g_vecs);
    cudaGetSymbolAddress((void**)&zero,    g_zero);
    cudaGetSymbolAddress((void**)&deg_u,   g_deg_u);
    cudaGetSymbolAddress((void**)&deg_m,   g_deg_m);
    cudaGetSymbolAddress((void**)&offU,    g_offU);
    cudaGetSymbolAddress((void**)&offM,    g_offM);
    cudaGetSymbolAddress((void**)&curU,    g_curU);
    cudaGetSymbolAddress((void**)&curM,    g_curM);
    cudaGetSymbolAddress((void**)&csrU,    g_csrU);
    cudaGetSymbolAddress((void**)&csrM,    g_csrM);
    cudaGetSymbolAddress((void**)&partU,   g_partU);
    cudaGetSymbolAddress((void**)&partM,   g_partM);

    const int GM = (cNM + 127) / 128;   // 625
    const int GU = (cNU + 127) / 128;   // 1563

    // 1) zero degree counters
    zero2_kernel<<<384, 256>>>(deg_u, cNU, deg_m, cNM);

    // 2) fusedA: GEMM4 || deg || vec
    const int DEGB = 2048;
    fusedA_kernel<<<GM + DEGB + 1, 256>>>(movie_feats, Wm, bm, movie_x,
                                          edge_src, edge_dst, deg_u, deg_m,
                                          user_init, Wl1_um, Wr1_mu, bl1_mu, vecs,
                                          GM, DEGB);

    // 3) CSR offsets
    partial_kernel<<<TU + TM, 256>>>(deg_u, deg_m, partU, partM);
    scanpart_kernel<<<2, 256>>>(partU, partM);
    phase3_kernel<<<TU + TM, 256>>>(deg_u, deg_m, partU, partM, offU, curU, offM, curM);

    // 4) fusedB: GEMM5 || P1 || scatter
    {
        const int GA = 2 * GM;            // 1250 gemm virtual blocks
        const int grid = 4 * GA;          // 5000
        const int SCB = grid - GA;        // 3750 scatter virtual blocks
        fusedB_kernel<<<grid, 256>>>(movie_x, Wr1_um, Wl1_mu, movie_h, P1,
                                     bl1_um, vecs, deg_m, zero,
                                     edge_src, edge_dst, curU, curM, csrU, csrM,
                                     GM, GA, SCB);
    }

    // 5) user-side aggregation: user_h = relu(meanP1 + cb1), aggH2 = mean movie_h
    agg_user_kernel<<<4736, 256>>>(offU, csrU, P1, movie_h, vecs, user_h, aggH2, cNU);

    // 6) fusedC: GEMM10 (user_o, K=256 concat) || agg_movie
    {
        const int gridC = 2 * GU;
        const int AGB = gridC - GU;
        fusedC_kernel<<<gridC, 256>>>(aggH2, user_h, Wl2_mu, Wr2_mu, user_o, bl2_mu,
                                      offM, csrM, aggM2, GU, AGB);
    }

    // 7) GEMM9: movie_o = aggM2 @ Wl2_um + bl2_um + movie_h @ Wr2_um
    gemm128_kernel<false, false, false><<<GM, 256>>>(
        aggM2, movie_h, Wl2_um, Wr2_um, movie_o, bl2_um, nullptr, nullptr, nullptr,
        cNM, cH / BK, cH / BK);

    // 8) final dot products
    dot_kernel<<<4736, 256>>>(lbl_user, lbl_movie, user_o, movie_o, out, cEL);

    (void)in_sizes; (void)out_size;
}

// round 14
// speedup vs baseline: 1.2773x; 1.1147x over previous
#include <cuda_runtime.h>
#include <cuda_bf16.h>
#include <cuda_fp16.h>
#include <cstddef>
#include <cstdint>

// Problem constants
#define cH   128
#define cNU  200000
#define cNM  80000
#define cE   2000000
#define cEL  500000
#define cFD  512

#define TILE 1024
#define TU   ((cNU + TILE - 1) / TILE)   // 196
#define TM   ((cNM + TILE - 1) / TILE)   // 79

// ---------------- scratch (device globals) ----------------
__device__ float  g_movie_x[(size_t)cNM * cH];
__device__ float  g_movie_h[(size_t)cNM * cH];
__device__ __half g_movie_hh[(size_t)cNM * cH];  // fp16 copy of movie_h (gather source)
__device__ __half g_P1h[(size_t)cNM * cH];       // movie_x @ Wl1_mu, fp16 (gather source only)
__device__ float  g_user_h [(size_t)cNU * cH];
__device__ __half g_user_hh[(size_t)cNU * cH];   // fp16 copy of user_h (gather source)
__device__ float  g_aggH2 [(size_t)cNU * cH];
__device__ float  g_aggM2 [(size_t)cNM * cH];
__device__ float  g_movie_o[(size_t)cNM * cH];
__device__ float  g_user_o [(size_t)cNU * cH];
__device__ int    g_deg_u[cNU];
__device__ int    g_deg_m[cNM];
__device__ int    g_offU[cNU + 1];
__device__ int    g_offM[cNM + 1];
__device__ int    g_curU[cNU];
__device__ int    g_curM[cNM];
__device__ int    g_csrU[cE];
__device__ int    g_csrM[cE];
__device__ int    g_partU[TU];
__device__ int    g_partM[TM];
__device__ float  g_vecs[2 * cH];
__device__ float  g_zero[cH];

// ---------------- utility ----------------
__global__ void zero2_kernel(int* p1, int n1, int* p2, int n2) {
    int i = blockIdx.x * blockDim.x + threadIdx.x;
    int stride = gridDim.x * blockDim.x;
    for (int k = i; k < n1; k += stride) p1[k] = 0;
    for (int k = i; k < n2; k += stride) p2[k] = 0;
}

// ---- device bodies ----
__device__ __forceinline__ void deg_body(const int* __restrict__ src, const int* __restrict__ dst,
                                         int* __restrict__ du, int* __restrict__ dm,
                                         int E, int vbid, int vgrid) {
    int i = vbid * 256 + threadIdx.x;
    int stride = vgrid * 256;
    for (; i < E; i += stride) {
        atomicAdd(&du[src[i]], 1);
        atomicAdd(&dm[dst[i]], 1);
    }
}

__device__ __forceinline__ void scatter_body(const int* __restrict__ src, const int* __restrict__ dst,
                                             int* __restrict__ curU, int* __restrict__ curM,
                                             int* __restrict__ csrU, int* __restrict__ csrM,
                                             int E, int vbid, int vgrid) {
    int i = vbid * 256 + threadIdx.x;
    int stride = vgrid * 256;
    for (; i < E; i += stride) {
        int s = src[i];
        int d = dst[i];
        int p = atomicAdd(&curU[s], 1);
        csrU[p] = d;
        int q = atomicAdd(&curM[d], 1);
        csrM[q] = s;
    }
}

__device__ __forceinline__ void vec_body(const float* __restrict__ user_init,
                                         const float* __restrict__ Wl1_um,
                                         const float* __restrict__ Wr1_mu,
                                         const float* __restrict__ bl1_mu,
                                         float* __restrict__ vecs) {
    int j = threadIdx.x;
    if (j >= cH) return;
    float s1 = 0.f, s2 = 0.f;
    for (int k = 0; k < cH; k++) {
        float u = user_init[k];
        s1 = fmaf(u, Wl1_um[k * cH + j], s1);
        s2 = fmaf(u, Wr1_mu[k * cH + j], s2);
    }
    vecs[j]      = s1;
    vecs[cH + j] = bl1_mu[j] + s2;
}

// movie-side aggregation over fp16 user_h rows
__device__ __forceinline__ void agg_movie_body(const int* __restrict__ off, const int* __restrict__ csr,
                                               const __half* __restrict__ uhh,
                                               float* __restrict__ aM2, int NM, int vbid, int vgrid) {
    int w    = vbid * 8 + (threadIdx.x >> 5);
    int lane = threadIdx.x & 31;
    int nw   = vgrid * 8;
    for (int m = w; m < NM; m += nw) {
        int s = off[m], e = off[m + 1];
        float4 a1 = make_float4(0.f, 0.f, 0.f, 0.f);
        float4 a2 = make_float4(0.f, 0.f, 0.f, 0.f);
        int i = s;
        for (; i + 1 < e; i += 2) {
            int d0 = csr[i];
            int d1 = csr[i + 1];
            uint2 u0 = ((const uint2*)(uhh + (size_t)d0 * 128))[lane];
            uint2 u1 = ((const uint2*)(uhh + (size_t)d1 * 128))[lane];
            float2 f0 = __half22float2(*(const __half2*)&u0.x);
            float2 f1 = __half22float2(*(const __half2*)&u0.y);
            float2 g0 = __half22float2(*(const __half2*)&u1.x);
            float2 g1 = __half22float2(*(const __half2*)&u1.y);
            a1.x += f0.x; a1.y += f0.y; a1.z += f1.x; a1.w += f1.y;
            a2.x += g0.x; a2.y += g0.y; a2.z += g1.x; a2.w += g1.y;
        }
        if (i < e) {
            int d0 = csr[i];
            uint2 u0 = ((const uint2*)(uhh + (size_t)d0 * 128))[lane];
            float2 f0 = __half22float2(*(const __half2*)&u0.x);
            float2 f1 = __half22float2(*(const __half2*)&u0.y);
            a1.x += f0.x; a1.y += f0.y; a1.z += f1.x; a1.w += f1.y;
        }
        float sc = (e > s) ? 1.f / (float)(e - s) : 0.f;
        float4 o = make_float4((a1.x + a2.x) * sc, (a1.y + a2.y) * sc, (a1.z + a2.z) * sc, (a1.w + a2.w) * sc);
        ((float4*)(aM2 + (size_t)m * 128))[lane] = o;
    }
}

// ---- parallel scan ----
__global__ void partial_kernel(const int* __restrict__ degU, const int* __restrict__ degM,
                               int* __restrict__ partU, int* __restrict__ partM) {
    int b = blockIdx.x;
    const int* deg; int* part; int n, tile;
    if (b < TU) { deg = degU; part = partU; n = cNU; tile = b; }
    else        { deg = degM; part = partM; n = cNM; tile = b - TU; }

    int tid = threadIdx.x;
    int base = tile * TILE + tid * 4;
    int s = 0;
    #pragma unroll
    for (int j = 0; j < 4; j++) {
        int i = base + j;
        if (i < n) s += deg[i];
    }
    __shared__ int wsum[8];
    int lane = tid & 31, wid = tid >> 5;
    #pragma unroll
    for (int o = 16; o > 0; o >>= 1) s += __shfl_down_sync(0xffffffffu, s, o);
    if (lane == 0) wsum[wid] = s;
    __syncthreads();
    if (tid == 0) {
        int t = 0;
        #pragma unroll
        for (int w = 0; w < 8; w++) t += wsum[w];
        part[tile] = t;
    }
}

__global__ void scanpart_kernel(int* __restrict__ partU, int* __restrict__ partM) {
    int* part = (blockIdx.x == 0) ? partU : partM;
    int cnt   = (blockIdx.x == 0) ? TU : TM;
    int tid = threadIdx.x, lane = tid & 31, wid = tid >> 5;
    __shared__ int wsum[8];
    int v = (tid < cnt) ? part[tid] : 0;
    int x = v;
    #pragma unroll
    for (int o = 1; o < 32; o <<= 1) {
        int t = __shfl_up_sync(0xffffffffu, x, o);
        if (lane >= o) x += t;
    }
    if (lane == 31) wsum[wid] = x;
    __syncthreads();
    if (wid == 0) {
        int s = (lane < 8) ? wsum[lane] : 0;
        #pragma unroll
        for (int o = 1; o < 8; o <<= 1) {
            int t = __shfl_up_sync(0xffffffffu, s, o);
            if (lane >= o) s += t;
        }
        if (lane < 8) wsum[lane] = s;
    }
    __syncthreads();
    int incl = x + ((wid > 0) ? wsum[wid - 1] : 0);
    if (tid < cnt) part[tid] = incl - v;
}

__global__ void phase3_kernel(const int* __restrict__ degU, const int* __restrict__ degM,
                              const int* __restrict__ partU, const int* __restrict__ partM,
                              int* __restrict__ offU, int* __restrict__ curU,
                              int* __restrict__ offM, int* __restrict__ curM) {
    int b = blockIdx.x;
    const int* deg; const int* part; int* off; int* cur; int n, tile;
    if (b < TU) { deg = degU; part = partU; off = offU; cur = curU; n = cNU; tile = b; }
    else        { deg = degM; part = partM; off = offM; cur = curM; n = cNM; tile = b - TU; }

    int tid = threadIdx.x, lane = tid & 31, wid = tid >> 5;
    if (b == 0 && tid == 0) { offU[cNU] = cE; offM[cNM] = cE; }

    int base = tile * TILE + tid * 4;
    int v[4];
    int s = 0;
    #pragma unroll
    for (int j = 0; j < 4; j++) {
        int i = base + j;
        v[j] = (i < n) ? deg[i] : 0;
        s += v[j];
    }
    __shared__ int wsum[8];
    int x = s;
    #pragma unroll
    for (int o = 1; o < 32; o <<= 1) {
        int t = __shfl_up_sync(0xffffffffu, x, o);
        if (lane >= o) x += t;
    }
    if (lane == 31) wsum[wid] = x;
    __syncthreads();
    if (wid == 0) {
        int t = (lane < 8) ? wsum[lane] : 0;
        #pragma unroll
        for (int o = 1; o < 8; o <<= 1) {
            int u = __shfl_up_sync(0xffffffffu, t, o);
            if (lane >= o) t += u;
        }
        if (lane < 8) wsum[lane] = t;
    }
    __syncthreads();
    int excl = x - s + ((wid > 0) ? wsum[wid - 1] : 0);
    int run = part[tile] + excl;
    #pragma unroll
    for (int j = 0; j < 4; j++) {
        int i = base + j;
        if (i < n) { off[i] = run; cur[i] = run; run += v[j]; }
    }
}

// ---------------- user-side aggregation: gather fp16 P1 + movie_h ----------------
// user_h = relu(mean P1[d] + cb1)  (fp32 + fp16 copies) ; aggH2 = mean movie_h[d]
__global__ void agg_user_kernel(const int* __restrict__ off, const int* __restrict__ csr,
                                const __half* __restrict__ P1h, const __half* __restrict__ MHh,
                                const float* __restrict__ vecs,
                                float* __restrict__ user_h, __half* __restrict__ user_hh,
                                float* __restrict__ aggH2, int NU) {
    int w    = (blockIdx.x * blockDim.x + threadIdx.x) >> 5;
    int lane = threadIdx.x & 31;
    int nw   = (gridDim.x * blockDim.x) >> 5;
    float4 c1 = ((const float4*)(vecs + cH))[lane];
    for (int u = w; u < NU; u += nw) {
        int s = off[u], e = off[u + 1];
        float4 a1 = make_float4(0.f, 0.f, 0.f, 0.f);
        float4 a2 = make_float4(0.f, 0.f, 0.f, 0.f);
        float4 a3 = make_float4(0.f, 0.f, 0.f, 0.f);
        float4 a4 = make_float4(0.f, 0.f, 0.f, 0.f);
        int i = s;
        for (; i + 1 < e; i += 2) {
            int d0 = csr[i];
            int d1 = csr[i + 1];
            uint2 x0 = ((const uint2*)(P1h + (size_t)d0 * 128))[lane];
            uint2 h0 = ((const uint2*)(MHh + (size_t)d0 * 128))[lane];
            uint2 x1 = ((const uint2*)(P1h + (size_t)d1 * 128))[lane];
            uint2 h1 = ((const uint2*)(MHh + (size_t)d1 * 128))[lane];
            float2 p, q;
            p = __half22float2(*(const __half2*)&x0.x); q = __half22float2(*(const __half2*)&x0.y);
            a1.x += p.x; a1.y += p.y; a1.z += q.x; a1.w += q.y;
            p = __half22float2(*(const __half2*)&h0.x); q = __half22float2(*(const __half2*)&h0.y);
            a2.x += p.x; a2.y += p.y; a2.z += q.x; a2.w += q.y;
            p = __half22float2(*(const __half2*)&x1.x); q = __half22float2(*(const __half2*)&x1.y);
            a3.x += p.x; a3.y += p.y; a3.z += q.x; a3.w += q.y;
            p = __half22float2(*(const __half2*)&h1.x); q = __half22float2(*(const __half2*)&h1.y);
            a4.x += p.x; a4.y += p.y; a4.z += q.x; a4.w += q.y;
        }
        if (i < e) {
            int d0 = csr[i];
            uint2 x0 = ((const uint2*)(P1h + (size_t)d0 * 128))[lane];
            uint2 h0 = ((const uint2*)(MHh + (size_t)d0 * 128))[lane];
            float2 p, q;
            p = __half22float2(*(const __half2*)&x0.x); q = __half22float2(*(const __half2*)&x0.y);
            a1.x += p.x; a1.y += p.y; a1.z += q.x; a1.w += q.y;
            p = __half22float2(*(const __half2*)&h0.x); q = __half22float2(*(const __half2*)&h0.y);
            a2.x += p.x; a2.y += p.y; a2.z += q.x; a2.w += q.y;
        }
        float sc = (e > s) ? 1.f / (float)(e - s) : 0.f;
        float4 o1 = make_float4(fmaxf((a1.x + a3.x) * sc + c1.x, 0.f),
                                fmaxf((a1.y + a3.y) * sc + c1.y, 0.f),
                                fmaxf((a1.z + a3.z) * sc + c1.z, 0.f),
                                fmaxf((a1.w + a3.w) * sc + c1.w, 0.f));
        float4 o2 = make_float4((a2.x + a4.x) * sc, (a2.y + a4.y) * sc, (a2.z + a4.z) * sc, (a2.w + a4.w) * sc);
        ((float4*)(user_h + (size_t)u * 128))[lane] = o1;
        ((float4*)(aggH2 + (size_t)u * 128))[lane] = o2;
        uint2 hh;
        *(__half2*)&hh.x = __floats2half2_rn(o1.x, o1.y);
        *(__half2*)&hh.y = __floats2half2_rn(o1.z, o1.w);
        ((uint2*)(user_hh + (size_t)u * 128))[lane] = hh;
    }
}

// ---------------- tensor-core SGEMM via split-bf16 ----------------
#define BK   16
#define ASTR 24
#define BSTR 136

__device__ __forceinline__ unsigned pack_bf16(__nv_bfloat16 a, __nv_bfloat16 b) {
    __nv_bfloat162 t = __halves2bfloat162(a, b);
    return reinterpret_cast<unsigned&>(t);
}
__device__ __forceinline__ void split_f32(float x, __nv_bfloat16& h, __nv_bfloat16& l) {
    h = __float2bfloat16(x);
    l = __float2bfloat16(x - __bfloat162float(h));
}
__device__ __forceinline__ void ldsm_x4(uint32_t* r, uint32_t addr) {
    asm volatile("ldmatrix.sync.aligned.m8n8.x4.shared.b16 {%0,%1,%2,%3}, [%4];"
                 : "=r"(r[0]), "=r"(r[1]), "=r"(r[2]), "=r"(r[3]) : "r"(addr));
}
__device__ __forceinline__ void ldsm_x4_t(uint32_t* r, uint32_t addr) {
    asm volatile("ldmatrix.sync.aligned.m8n8.x4.trans.shared.b16 {%0,%1,%2,%3}, [%4];"
                 : "=r"(r[0]), "=r"(r[1]), "=r"(r[2]), "=r"(r[3]) : "r"(addr));
}
__device__ __forceinline__ void mma_bf16(float* d, const uint32_t* a, const uint32_t* b) {
    asm volatile("mma.sync.aligned.m16n8k16.row.col.f32.bf16.bf16.f32 "
                 "{%0,%1,%2,%3}, {%4,%5,%6,%7}, {%8,%9}, {%0,%1,%2,%3};"
                 : "+f"(d[0]), "+f"(d[1]), "+f"(d[2]), "+f"(d[3])
                 : "r"(a[0]), "r"(a[1]), "r"(a[2]), "r"(a[3]), "r"(b[0]), "r"(b[1]));
}

template<bool BIAS_SEL, bool RELU, bool ADD_D, bool WF, bool WH>
__device__ __forceinline__ void gemm128_body(
    const float* __restrict__ A1, const float* __restrict__ A2,
    const float* __restrict__ B1, const float* __restrict__ B2,
    float* __restrict__ C, __half* __restrict__ Ch,
    const float* __restrict__ bias, const float* __restrict__ vsel,
    const int* __restrict__ deg, const float* __restrict__ Dm,
    int M, int KT1, int KT2, int bid) {
    __shared__ __nv_bfloat16 Ah[2][128][ASTR];
    __shared__ __nv_bfloat16 Al[2][128][ASTR];
    __shared__ __nv_bfloat16 Bh[2][BK][BSTR];
    __shared__ __nv_bfloat16 Bl[2][BK][BSTR];
    __shared__ float sBias[128];
    __shared__ float sVsel[128];

    const int tid  = threadIdx.x;
    const int lane = tid & 31;
    const int wid  = tid >> 5;
    const int wm   = wid & 3;
    const int wn   = wid >> 2;
    const int m0   = bid * 128;
    const int lda1 = KT1 * BK;
    const int lda2 = KT2 * BK;
    const int KT   = KT1 + KT2;

    if (tid < 128) {
        sBias[tid] = bias[tid];
        if (BIAS_SEL) sVsel[tid] = vsel[tid];
    }

    const int arow0 = tid >> 2;
    const int ac4   = (tid & 3) << 2;
    const int brow0 = tid >> 5;
    const int bn4   = (tid & 31) << 2;

    float4 rA[2], rB[2];

    auto loadTile = [&](int t) {
        const bool first = (t < KT1);
        #pragma unroll
        for (int i = 0; i < 2; i++) {
            int row = arow0 + i * 64;
            int m = m0 + row;
            float4 v = make_float4(0.f, 0.f, 0.f, 0.f);
            if (m < M) {
                const float* p = first ? (A1 + (size_t)m * lda1 + t * BK + ac4)
                                       : (A2 + (size_t)m * lda2 + (t - KT1) * BK + ac4);
                v = *(const float4*)p;
            }
            rA[i] = v;
        }
        #pragma unroll
        for (int i = 0; i < 2; i++) {
            int row = brow0 + i * 8;
            const float* p = first ? (B1 + (size_t)(t * BK + row) * 128 + bn4)
                                   : (B2 + (size_t)((t - KT1) * BK + row) * 128 + bn4);
            rB[i] = *(const float4*)p;
        }
    };
    auto storeTile = [&](int buf) {
        #pragma unroll
        for (int i = 0; i < 2; i++) {
            int row = arow0 + i * 64;
            const float* v = &rA[i].x;
            __nv_bfloat16 h[4], l[4];
            #pragma unroll
            for (int j = 0; j < 4; j++) split_f32(v[j], h[j], l[j]);
            *(uint2*)&Ah[buf][row][ac4] = make_uint2(pack_bf16(h[0], h[1]), pack_bf16(h[2], h[3]));
            *(uint2*)&Al[buf][row][ac4] = make_uint2(pack_bf16(l[0], l[1]), pack_bf16(l[2], l[3]));
        }
        #pragma unroll
        for (int i = 0; i < 2; i++) {
            int row = brow0 + i * 8;
            const float* v = &rB[i].x;
            __nv_bfloat16 h[4], l[4];
            #pragma unroll
            for (int j = 0; j < 4; j++) split_f32(v[j], h[j], l[j]);
            *(uint2*)&Bh[buf][row][bn4] = make_uint2(pack_bf16(h[0], h[1]), pack_bf16(h[2], h[3]));
            *(uint2*)&Bl[buf][row][bn4] = make_uint2(pack_bf16(l[0], l[1]), pack_bf16(l[2], l[3]));
        }
    };

    float d[2][8][4];
    #pragma unroll
    for (int mt = 0; mt < 2; mt++)
        #pragma unroll
        for (int nt = 0; nt < 8; nt++)
            #pragma unroll
            for (int j = 0; j < 4; j++) d[mt][nt][j] = 0.f;

    const int ar = lane & 15;
    const int ac = (lane >> 4) << 3;
    const int br = lane & 15;
    const int bc = wn * 64 + ((lane >> 4) << 3);

    loadTile(0);
    storeTile(0);
    __syncthreads();

    for (int t = 0; t < KT; t++) {
        const int cb = t & 1;
        if (t + 1 < KT) loadTile(t + 1);

        uint32_t fah[2][4], fal[2][4];
        #pragma unroll
        for (int mt = 0; mt < 2; mt++) {
            int row = wm * 32 + mt * 16 + ar;
            ldsm_x4(fah[mt], (uint32_t)__cvta_generic_to_shared(&Ah[cb][row][ac]));
            ldsm_x4(fal[mt], (uint32_t)__cvta_generic_to_shared(&Al[cb][row][ac]));
        }
        #pragma unroll
        for (int ntp = 0; ntp < 4; ntp++) {
            uint32_t fbh[4], fbl[4];
            ldsm_x4_t(fbh, (uint32_t)__cvta_generic_to_shared(&Bh[cb][br][bc + ntp * 16]));
            ldsm_x4_t(fbl, (uint32_t)__cvta_generic_to_shared(&Bl[cb][br][bc + ntp * 16]));
            #pragma unroll
            for (int mt = 0; mt < 2; mt++) {
                mma_bf16(d[mt][2 * ntp],     fah[mt], fbh);
                mma_bf16(d[mt][2 * ntp],     fal[mt], fbh);
                mma_bf16(d[mt][2 * ntp],     fah[mt], fbl);
                mma_bf16(d[mt][2 * ntp + 1], fah[mt], fbh + 2);
                mma_bf16(d[mt][2 * ntp + 1], fal[mt], fbh + 2);
                mma_bf16(d[mt][2 * ntp + 1], fah[mt], fbl + 2);
            }
        }
        if (t + 1 < KT) storeTile((t + 1) & 1);
        __syncthreads();
    }

    const int rb  = m0 + wm * 32 + (lane >> 2);
    const int cb0 = wn * 64 + (lane & 3) * 2;
    #pragma unroll
    for (int mt = 0; mt < 2; mt++) {
        #pragma unroll
        for (int h = 0; h < 2; h++) {
            int m = rb + mt * 16 + h * 8;
            if (m >= M) continue;
            float sel = 0.f;
            if (BIAS_SEL) sel = (deg[m] > 0) ? 1.f : 0.f;
            #pragma unroll
            for (int nt = 0; nt < 8; nt++) {
                int col = cb0 + nt * 8;
                float x = d[mt][nt][h * 2 + 0] + sBias[col];
                float y = d[mt][nt][h * 2 + 1] + sBias[col + 1];
                if (BIAS_SEL) { x += sel * sVsel[col]; y += sel * sVsel[col + 1]; }
                if (ADD_D) {
                    float2 dv = *(const float2*)&Dm[(size_t)m * 128 + col];
                    x += dv.x; y += dv.y;
                }
                if (RELU) { x = fmaxf(x, 0.f); y = fmaxf(y, 0.f); }
                if (WF) *(float2*)&C[(size_t)m * 128 + col] = make_float2(x, y);
                if (WH) *(__half2*)&Ch[(size_t)m * 128 + col] = __floats2half2_rn(x, y);
            }
        }
    }
}

template<bool BIAS_SEL, bool RELU, bool ADD_D>
__global__ void __launch_bounds__(256)
gemm128_kernel(const float* A1, const float* A2, const float* B1, const float* B2,
               float* C, const float* bias, const float* vsel, const int* deg,
               const float* Dm, int M, int KT1, int KT2) {
    gemm128_body<BIAS_SEL, RELU, ADD_D, true, false>(A1, A2, B1, B2, C, nullptr,
                                                     bias, vsel, deg, Dm, M, KT1, KT2, blockIdx.x);
}

// ---------------- fused kernels ----------------
// fusedA: GEMM4 (movie_x) || deg || vec.
__global__ void __launch_bounds__(256)
fusedA_kernel(const float* __restrict__ movie_feats, const float* __restrict__ Wm, const float* __restrict__ bm,
              float* __restrict__ movie_x,
              const int* __restrict__ src, const int* __restrict__ dst,
              int* __restrict__ du, int* __restrict__ dm,
              const float* __restrict__ user_init, const float* __restrict__ Wl1_um,
              const float* __restrict__ Wr1_mu, const float* __restrict__ bl1_mu,
              float* __restrict__ vecs,
              int GA, int DEGB) {
    int bid = blockIdx.x;
    int q = bid >> 2, r = bid & 3;
    if (r == 0 && q < GA) {
        gemm128_body<false, false, false, true, false>(movie_feats, nullptr, Wm, nullptr, movie_x, nullptr,
                                                       bm, nullptr, nullptr, nullptr, cNM, cFD / BK, 0, q);
    } else {
        int before = min((bid + 3) >> 2, GA);
        int did = bid - before;
        if (did < DEGB) deg_body(src, dst, du, dm, cE, did, DEGB);
        else            vec_body(user_init, Wl1_um, Wr1_mu, bl1_mu, vecs);
    }
}

// fusedB: GEMM5 (movie_h fp32+fp16) || P1 (fp16 only) || scatter.
__global__ void __launch_bounds__(256)
fusedB_kernel(const float* __restrict__ movie_x,
              const float* __restrict__ Wr1_um, const float* __restrict__ Wl1_mu,
              float* __restrict__ movie_h, __half* __restrict__ movie_hh, __half* __restrict__ P1h,
              const float* __restrict__ bl1_um, const float* __restrict__ vsel, const int* __restrict__ deg_m,
              const float* __restrict__ zero,
              const int* __restrict__ src, const int* __restrict__ dst,
              int* __restrict__ curU, int* __restrict__ curM,
              int* __restrict__ csrU, int* __restrict__ csrM,
              int GM_, int GA, int SCB) {
    int bid = blockIdx.x;
    int q = bid >> 2, r = bid & 3;
    if (r == 0 && q < GA) {
        if (q < GM_) {
            gemm128_body<true, true, false, true, true>(movie_x, nullptr, Wr1_um, nullptr, movie_h, movie_hh,
                                                        bl1_um, vsel, deg_m, nullptr, cNM, cH / BK, 0, q);
        } else {
            gemm128_body<false, false, false, false, true>(movie_x, nullptr, Wl1_mu, nullptr, nullptr, P1h,
                                                           zero, nullptr, nullptr, nullptr, cNM, cH / BK, 0, q - GM_);
        }
    } else {
        int before = min((bid + 3) >> 2, GA);
        int did = bid - before;
        if (did < SCB) scatter_body(src, dst, curU, curM, csrU, csrM, cE, did, SCB);
    }
}

// fusedC: GEMM10 (user_o = aggH2@Wl2_mu + bl2_mu + user_h@Wr2_mu, K=256) || agg_movie (fp16 gather).
__global__ void __launch_bounds__(256)
fusedC_kernel(const float* __restrict__ aggH2, const float* __restrict__ user_h,
              const float* __restrict__ Wl2_mu, const float* __restrict__ Wr2_mu,
              float* __restrict__ user_o, const float* __restrict__ bl2_mu,
              const int* __restrict__ offM, const int* __restrict__ csrM,
              const __half* __restrict__ user_hh, float* __restrict__ aggM2,
              int GA, int AGB) {
    int bid = blockIdx.x;
    int q = bid >> 1, r = bid & 1;
    if (r == 0 && q < GA) {
        gemm128_body<false, false, false, true, false>(aggH2, user_h, Wl2_mu, Wr2_mu, user_o, nullptr,
                                                       bl2_mu, nullptr, nullptr, nullptr, cNU, cH / BK, cH / BK, q);
    } else {
        int before = min((bid + 1) >> 1, GA);
        int aid = bid - before;
        if (aid < AGB) agg_movie_body(offM, csrM, user_hh, aggM2, cNM, aid, AGB);
    }
}

// ---------------- final edge dot products ----------------
__global__ void dot_kernel(const int* __restrict__ lu, const int* __restrict__ lm,
                           const float* __restrict__ U, const float* __restrict__ Mo,
                           float* __restrict__ out, int EL) {
    int w    = (blockIdx.x * blockDim.x + threadIdx.x) >> 5;
    int lane = threadIdx.x & 31;
    int nw   = (gridDim.x * blockDim.x) >> 5;
    for (int i = w; i < EL; i += nw) {
        int u = lu[i];
        int m = lm[i];
        float4 a = ((const float4*)(U  + (size_t)u * 128))[lane];
        float4 b = ((const float4*)(Mo + (size_t)m * 128))[lane];
        float p = a.x * b.x + a.y * b.y + a.z * b.z + a.w * b.w;
        #pragma unroll
        for (int off = 16; off > 0; off >>= 1)
            p += __shfl_xor_sync(0xFFFFFFFFu, p, off);
        if (lane == 0) out[i] = p;
    }
}

// ---------------- launch ----------------
extern "C" void kernel_launch(void* const* d_in, const int* in_sizes, int n_in,
                              void* d_out, int out_size) {
    const float* movie_feats = (const float*)d_in[0];
    const float* user_init   = (const float*)d_in[1];
    const int*   edge_src    = (const int*)d_in[2];
    const int*   edge_dst    = (const int*)d_in[3];
    const int*   lbl_user    = (const int*)d_in[4];
    const int*   lbl_movie   = (const int*)d_in[5];
    const int wi = (n_in >= 21) ? 7 : 6;
    const float* Wm     = (const float*)d_in[wi + 0];
    const float* bm     = (const float*)d_in[wi + 1];
    const float* Wl1_um = (const float*)d_in[wi + 2];
    const float* bl1_um = (const float*)d_in[wi + 3];
    const float* Wr1_um = (const float*)d_in[wi + 4];
    const float* Wl1_mu = (const float*)d_in[wi + 5];
    const float* bl1_mu = (const float*)d_in[wi + 6];
    const float* Wr1_mu = (const float*)d_in[wi + 7];
    const float* Wl2_um = (const float*)d_in[wi + 8];
    const float* bl2_um = (const float*)d_in[wi + 9];
    const float* Wr2_um = (const float*)d_in[wi + 10];
    const float* Wl2_mu = (const float*)d_in[wi + 11];
    const float* bl2_mu = (const float*)d_in[wi + 12];
    const float* Wr2_mu = (const float*)d_in[wi + 13];
    float* out = (float*)d_out;

    float *movie_x, *movie_h, *user_h, *aggH2, *aggM2, *movie_o, *user_o, *vecs, *zero;
    __half *movie_hh, *P1h, *user_hh;
    int *deg_u, *deg_m, *offU, *offM, *curU, *curM, *csrU, *csrM, *partU, *partM;
    cudaGetSymbolAddress((void**)&movie_x,  g_movie_x);
    cudaGetSymbolAddress((void**)&movie_h,  g_movie_h);
    cudaGetSymbolAddress((void**)&movie_hh, g_movie_hh);
    cudaGetSymbolAddress((void**)&P1h,      g_P1h);
    cudaGetSymbolAddress((void**)&user_h,   g_user_h);
    cudaGetSymbolAddress((void**)&user_hh,  g_user_hh);
    cudaGetSymbolAddress((void**)&aggH2,    g_aggH2);
    cudaGetSymbolAddress((void**)&aggM2,    g_aggM2);
    cudaGetSymbolAddress((void**)&movie_o,  g_movie_o);
    cudaGetSymbolAddress((void**)&user_o,   g_user_o);
    cudaGetSymbolAddress((void**)&vecs,     g_vecs);
    cudaGetSymbolAddress((void**)&zero,     g_zero);
    cudaGetSymbolAddress((void**)&deg_u,    g_deg_u);
    cudaGetSymbolAddress((void**)&deg_m,    g_deg_m);
    cudaGetSymbolAddress((void**)&offU,     g_offU);
    cudaGetSymbolAddress((void**)&offM,     g_offM);
    cudaGetSymbolAddress((void**)&curU,     g_curU);
    cudaGetSymbolAddress((void**)&curM,     g_curM);
    cudaGetSymbolAddress((void**)&csrU,     g_csrU);
    cudaGetSymbolAddress((void**)&csrM,     g_csrM);
    cudaGetSymbolAddress((void**)&partU,    g_partU);
    cudaGetSymbolAddress((void**)&partM,    g_partM);

    const int GM = (cNM + 127) / 128;   // 625
    const int GU = (cNU + 127) / 128;   // 1563

    // 1) zero degree counters
    zero2_kernel<<<384, 256>>>(deg_u, cNU, deg_m, cNM);

    // 2) fusedA: GEMM4 || deg || vec
    const int DEGB = 2048;
    fusedA_kernel<<<GM + DEGB + 1, 256>>>(movie_feats, Wm, bm, movie_x,
                                          edge_src, edge_dst, deg_u, deg_m,
                                          user_init, Wl1_um, Wr1_mu, bl1_mu, vecs,
                                          GM, DEGB);

    // 3) CSR offsets
    partial_kernel<<<TU + TM, 256>>>(deg_u, deg_m, partU, partM);
    scanpart_kernel<<<2, 256>>>(partU, partM);
    phase3_kernel<<<TU + TM, 256>>>(deg_u, deg_m, partU, partM, offU, curU, offM, curM);

    // 4) fusedB: GEMM5 (fp32+fp16) || P1 (fp16) || scatter
    {
        const int GA = 2 * GM;            // 1250 gemm virtual blocks
        const int grid = 4 * GA;          // 5000
        const int SCB = grid - GA;        // 3750 scatter virtual blocks
        fusedB_kernel<<<grid, 256>>>(movie_x, Wr1_um, Wl1_mu, movie_h, movie_hh, P1h,
                                     bl1_um, vecs, deg_m, zero,
                                     edge_src, edge_dst, curU, curM, csrU, csrM,
                                     GM, GA, SCB);
    }

    // 5) user-side aggregation (fp16 gathers): user_h (+fp16 copy), aggH2
    agg_user_kernel<<<4736, 256>>>(offU, csrU, P1h, movie_hh, vecs, user_h, user_hh, aggH2, cNU);

    // 6) fusedC: GEMM10 (user_o, K=256 concat) || agg_movie (fp16 gather)
    {
        const int gridC = 2 * GU;
        const int AGB = gridC - GU;
        fusedC_kernel<<<gridC, 256>>>(aggH2, user_h, Wl2_mu, Wr2_mu, user_o, bl2_mu,
                                      offM, csrM, user_hh, aggM2, GU, AGB);
    }

    // 7) GEMM9: movie_o = aggM2 @ Wl2_um + bl2_um + movie_h @ Wr2_um
    gemm128_kernel<false, false, false><<<GM, 256>>>(
        aggM2, movie_h, Wl2_um, Wr2_um, movie_o, bl2_um, nullptr, nullptr, nullptr,
        cNM, cH / BK, cH / BK);

    // 8) final dot products
    dot_kernel<<<4736, 256>>>(lbl_user, lbl_movie, user_o, movie_o, out, cEL);

    (void)in_sizes; (void)out_size;
}

// round 15
// speedup vs baseline: 1.3512x; 1.0578x over previous
#include <cuda_runtime.h>
#include <cuda_bf16.h>
#include <cuda_fp16.h>
#include <cstddef>
#include <cstdint>

// Problem constants
#define cH   128
#define cNU  200000
#define cNM  80000
#define cE   2000000
#define cEL  500000
#define cFD  512

#define TILE 1024
#define TU   ((cNU + TILE - 1) / TILE)   // 196
#define TM   ((cNM + TILE - 1) / TILE)   // 79

// ---------------- scratch (device globals) ----------------
__device__ float  g_movie_x[(size_t)cNM * cH];
__device__ float  g_movie_h[(size_t)cNM * cH];
__device__ __half g_movie_hh[(size_t)cNM * cH];  // fp16 copy of movie_h (gather source)
__device__ __half g_P1h[(size_t)cNM * cH];       // movie_x @ Wl1_mu, fp16 (gather source only)
__device__ float  g_user_h [(size_t)cNU * cH];
__device__ __half g_user_hh[(size_t)cNU * cH];   // fp16 copy of user_h (gather source)
__device__ float  g_aggH2 [(size_t)cNU * cH];
__device__ float  g_aggM2 [(size_t)cNM * cH];
__device__ __half g_movie_oh[(size_t)cNM * cH];  // fp16 final movie embeddings (dot source)
__device__ __half g_user_oh [(size_t)cNU * cH];  // fp16 final user embeddings (dot source)
__device__ int    g_deg_u[cNU];
__device__ int    g_deg_m[cNM];
__device__ int    g_offU[cNU + 1];
__device__ int    g_offM[cNM + 1];
__device__ int    g_curU[cNU];
__device__ int    g_curM[cNM];
__device__ int    g_csrU[cE];
__device__ int    g_csrM[cE];
__device__ int    g_partU[TU];
__device__ int    g_partM[TM];
__device__ float  g_vecs[2 * cH];
__device__ float  g_zero[cH];

// ---------------- utility ----------------
__global__ void zero2_kernel(int* p1, int n1, int* p2, int n2) {
    int i = blockIdx.x * blockDim.x + threadIdx.x;
    int stride = gridDim.x * blockDim.x;
    for (int k = i; k < n1; k += stride) p1[k] = 0;
    for (int k = i; k < n2; k += stride) p2[k] = 0;
}

// ---- device bodies ----
__device__ __forceinline__ void deg_body(const int* __restrict__ src, const int* __restrict__ dst,
                                         int* __restrict__ du, int* __restrict__ dm,
                                         int E, int vbid, int vgrid) {
    int i = vbid * 256 + threadIdx.x;
    int stride = vgrid * 256;
    for (; i < E; i += stride) {
        atomicAdd(&du[src[i]], 1);
        atomicAdd(&dm[dst[i]], 1);
    }
}

__device__ __forceinline__ void scatter_body(const int* __restrict__ src, const int* __restrict__ dst,
                                             int* __restrict__ curU, int* __restrict__ curM,
                                             int* __restrict__ csrU, int* __restrict__ csrM,
                                             int E, int vbid, int vgrid) {
    int i = vbid * 256 + threadIdx.x;
    int stride = vgrid * 256;
    for (; i < E; i += stride) {
        int s = src[i];
        int d = dst[i];
        int p = atomicAdd(&curU[s], 1);
        csrU[p] = d;
        int q = atomicAdd(&curM[d], 1);
        csrM[q] = s;
    }
}

__device__ __forceinline__ void vec_body(const float* __restrict__ user_init,
                                         const float* __restrict__ Wl1_um,
                                         const float* __restrict__ Wr1_mu,
                                         const float* __restrict__ bl1_mu,
                                         float* __restrict__ vecs) {
    int j = threadIdx.x;
    if (j >= cH) return;
    float s1 = 0.f, s2 = 0.f;
    for (int k = 0; k < cH; k++) {
        float u = user_init[k];
        s1 = fmaf(u, Wl1_um[k * cH + j], s1);
        s2 = fmaf(u, Wr1_mu[k * cH + j], s2);
    }
    vecs[j]      = s1;
    vecs[cH + j] = bl1_mu[j] + s2;
}

// movie-side aggregation over fp16 user_h rows
__device__ __forceinline__ void agg_movie_body(const int* __restrict__ off, const int* __restrict__ csr,
                                               const __half* __restrict__ uhh,
                                               float* __restrict__ aM2, int NM, int vbid, int vgrid) {
    int w    = vbid * 8 + (threadIdx.x >> 5);
    int lane = threadIdx.x & 31;
    int nw   = vgrid * 8;
    for (int m = w; m < NM; m += nw) {
        int s = off[m], e = off[m + 1];
        float4 a1 = make_float4(0.f, 0.f, 0.f, 0.f);
        float4 a2 = make_float4(0.f, 0.f, 0.f, 0.f);
        int i = s;
        for (; i + 1 < e; i += 2) {
            int d0 = csr[i];
            int d1 = csr[i + 1];
            uint2 u0 = ((const uint2*)(uhh + (size_t)d0 * 128))[lane];
            uint2 u1 = ((const uint2*)(uhh + (size_t)d1 * 128))[lane];
            float2 f0 = __half22float2(*(const __half2*)&u0.x);
            float2 f1 = __half22float2(*(const __half2*)&u0.y);
            float2 g0 = __half22float2(*(const __half2*)&u1.x);
            float2 g1 = __half22float2(*(const __half2*)&u1.y);
            a1.x += f0.x; a1.y += f0.y; a1.z += f1.x; a1.w += f1.y;
            a2.x += g0.x; a2.y += g0.y; a2.z += g1.x; a2.w += g1.y;
        }
        if (i < e) {
            int d0 = csr[i];
            uint2 u0 = ((const uint2*)(uhh + (size_t)d0 * 128))[lane];
            float2 f0 = __half22float2(*(const __half2*)&u0.x);
            float2 f1 = __half22float2(*(const __half2*)&u0.y);
            a1.x += f0.x; a1.y += f0.y; a1.z += f1.x; a1.w += f1.y;
        }
        float sc = (e > s) ? 1.f / (float)(e - s) : 0.f;
        float4 o = make_float4((a1.x + a2.x) * sc, (a1.y + a2.y) * sc, (a1.z + a2.z) * sc, (a1.w + a2.w) * sc);
        ((float4*)(aM2 + (size_t)m * 128))[lane] = o;
    }
}

// ---- parallel scan ----
__global__ void partial_kernel(const int* __restrict__ degU, const int* __restrict__ degM,
                               int* __restrict__ partU, int* __restrict__ partM) {
    int b = blockIdx.x;
    const int* deg; int* part; int n, tile;
    if (b < TU) { deg = degU; part = partU; n = cNU; tile = b; }
    else        { deg = degM; part = partM; n = cNM; tile = b - TU; }

    int tid = threadIdx.x;
    int base = tile * TILE + tid * 4;
    int s = 0;
    #pragma unroll
    for (int j = 0; j < 4; j++) {
        int i = base + j;
        if (i < n) s += deg[i];
    }
    __shared__ int wsum[8];
    int lane = tid & 31, wid = tid >> 5;
    #pragma unroll
    for (int o = 16; o > 0; o >>= 1) s += __shfl_down_sync(0xffffffffu, s, o);
    if (lane == 0) wsum[wid] = s;
    __syncthreads();
    if (tid == 0) {
        int t = 0;
        #pragma unroll
        for (int w = 0; w < 8; w++) t += wsum[w];
        part[tile] = t;
    }
}

__global__ void scanpart_kernel(int* __restrict__ partU, int* __restrict__ partM) {
    int* part = (blockIdx.x == 0) ? partU : partM;
    int cnt   = (blockIdx.x == 0) ? TU : TM;
    int tid = threadIdx.x, lane = tid & 31, wid = tid >> 5;
    __shared__ int wsum[8];
    int v = (tid < cnt) ? part[tid] : 0;
    int x = v;
    #pragma unroll
    for (int o = 1; o < 32; o <<= 1) {
        int t = __shfl_up_sync(0xffffffffu, x, o);
        if (lane >= o) x += t;
    }
    if (lane == 31) wsum[wid] = x;
    __syncthreads();
    if (wid == 0) {
        int s = (lane < 8) ? wsum[lane] : 0;
        #pragma unroll
        for (int o = 1; o < 8; o <<= 1) {
            int t = __shfl_up_sync(0xffffffffu, s, o);
            if (lane >= o) s += t;
        }
        if (lane < 8) wsum[lane] = s;
    }
    __syncthreads();
    int incl = x + ((wid > 0) ? wsum[wid - 1] : 0);
    if (tid < cnt) part[tid] = incl - v;
}

__global__ void phase3_kernel(const int* __restrict__ degU, const int* __restrict__ degM,
                              const int* __restrict__ partU, const int* __restrict__ partM,
                              int* __restrict__ offU, int* __restrict__ curU,
                              int* __restrict__ offM, int* __restrict__ curM) {
    int b = blockIdx.x;
    const int* deg; const int* part; int* off; int* cur; int n, tile;
    if (b < TU) { deg = degU; part = partU; off = offU; cur = curU; n = cNU; tile = b; }
    else        { deg = degM; part = partM; off = offM; cur = curM; n = cNM; tile = b - TU; }

    int tid = threadIdx.x, lane = tid & 31, wid = tid >> 5;
    if (b == 0 && tid == 0) { offU[cNU] = cE; offM[cNM] = cE; }

    int base = tile * TILE + tid * 4;
    int v[4];
    int s = 0;
    #pragma unroll
    for (int j = 0; j < 4; j++) {
        int i = base + j;
        v[j] = (i < n) ? deg[i] : 0;
        s += v[j];
    }
    __shared__ int wsum[8];
    int x = s;
    #pragma unroll
    for (int o = 1; o < 32; o <<= 1) {
        int t = __shfl_up_sync(0xffffffffu, x, o);
        if (lane >= o) x += t;
    }
    if (lane == 31) wsum[wid] = x;
    __syncthreads();
    if (wid == 0) {
        int t = (lane < 8) ? wsum[lane] : 0;
        #pragma unroll
        for (int o = 1; o < 8; o <<= 1) {
            int u = __shfl_up_sync(0xffffffffu, t, o);
            if (lane >= o) t += u;
        }
        if (lane < 8) wsum[lane] = t;
    }
    __syncthreads();
    int excl = x - s + ((wid > 0) ? wsum[wid - 1] : 0);
    int run = part[tile] + excl;
    #pragma unroll
    for (int j = 0; j < 4; j++) {
        int i = base + j;
        if (i < n) { off[i] = run; cur[i] = run; run += v[j]; }
    }
}

// ---------------- user-side aggregation: gather fp16 P1 + movie_h ----------------
__global__ void agg_user_kernel(const int* __restrict__ off, const int* __restrict__ csr,
                                const __half* __restrict__ P1h, const __half* __restrict__ MHh,
                                const float* __restrict__ vecs,
                                float* __restrict__ user_h, __half* __restrict__ user_hh,
                                float* __restrict__ aggH2, int NU) {
    int w    = (blockIdx.x * blockDim.x + threadIdx.x) >> 5;
    int lane = threadIdx.x & 31;
    int nw   = (gridDim.x * blockDim.x) >> 5;
    float4 c1 = ((const float4*)(vecs + cH))[lane];
    for (int u = w; u < NU; u += nw) {
        int s = off[u], e = off[u + 1];
        float4 a1 = make_float4(0.f, 0.f, 0.f, 0.f);
        float4 a2 = make_float4(0.f, 0.f, 0.f, 0.f);
        float4 a3 = make_float4(0.f, 0.f, 0.f, 0.f);
        float4 a4 = make_float4(0.f, 0.f, 0.f, 0.f);
        int i = s;
        for (; i + 1 < e; i += 2) {
            int d0 = csr[i];
            int d1 = csr[i + 1];
            uint2 x0 = ((const uint2*)(P1h + (size_t)d0 * 128))[lane];
            uint2 h0 = ((const uint2*)(MHh + (size_t)d0 * 128))[lane];
            uint2 x1 = ((const uint2*)(P1h + (size_t)d1 * 128))[lane];
            uint2 h1 = ((const uint2*)(MHh + (size_t)d1 * 128))[lane];
            float2 p, q;
            p = __half22float2(*(const __half2*)&x0.x); q = __half22float2(*(const __half2*)&x0.y);
            a1.x += p.x; a1.y += p.y; a1.z += q.x; a1.w += q.y;
            p = __half22float2(*(const __half2*)&h0.x); q = __half22float2(*(const __half2*)&h0.y);
            a2.x += p.x; a2.y += p.y; a2.z += q.x; a2.w += q.y;
            p = __half22float2(*(const __half2*)&x1.x); q = __half22float2(*(const __half2*)&x1.y);
            a3.x += p.x; a3.y += p.y; a3.z += q.x; a3.w += q.y;
            p = __half22float2(*(const __half2*)&h1.x); q = __half22float2(*(const __half2*)&h1.y);
            a4.x += p.x; a4.y += p.y; a4.z += q.x; a4.w += q.y;
        }
        if (i < e) {
            int d0 = csr[i];
            uint2 x0 = ((const uint2*)(P1h + (size_t)d0 * 128))[lane];
            uint2 h0 = ((const uint2*)(MHh + (size_t)d0 * 128))[lane];
            float2 p, q;
            p = __half22float2(*(const __half2*)&x0.x); q = __half22float2(*(const __half2*)&x0.y);
            a1.x += p.x; a1.y += p.y; a1.z += q.x; a1.w += q.y;
            p = __half22float2(*(const __half2*)&h0.x); q = __half22float2(*(const __half2*)&h0.y);
            a2.x += p.x; a2.y += p.y; a2.z += q.x; a2.w += q.y;
        }
        float sc = (e > s) ? 1.f / (float)(e - s) : 0.f;
        float4 o1 = make_float4(fmaxf((a1.x + a3.x) * sc + c1.x, 0.f),
                                fmaxf((a1.y + a3.y) * sc + c1.y, 0.f),
                                fmaxf((a1.z + a3.z) * sc + c1.z, 0.f),
                                fmaxf((a1.w + a3.w) * sc + c1.w, 0.f));
        float4 o2 = make_float4((a2.x + a4.x) * sc, (a2.y + a4.y) * sc, (a2.z + a4.z) * sc, (a2.w + a4.w) * sc);
        ((float4*)(user_h + (size_t)u * 128))[lane] = o1;
        ((float4*)(aggH2 + (size_t)u * 128))[lane] = o2;
        uint2 hh;
        *(__half2*)&hh.x = __floats2half2_rn(o1.x, o1.y);
        *(__half2*)&hh.y = __floats2half2_rn(o1.z, o1.w);
        ((uint2*)(user_hh + (size_t)u * 128))[lane] = hh;
    }
}

// ---------------- tensor-core SGEMM via split-bf16 ----------------
#define BK   16
#define ASTR 24
#define BSTR 136

__device__ __forceinline__ unsigned pack_bf16(__nv_bfloat16 a, __nv_bfloat16 b) {
    __nv_bfloat162 t = __halves2bfloat162(a, b);
    return reinterpret_cast<unsigned&>(t);
}
__device__ __forceinline__ void split_f32(float x, __nv_bfloat16& h, __nv_bfloat16& l) {
    h = __float2bfloat16(x);
    l = __float2bfloat16(x - __bfloat162float(h));
}
__device__ __forceinline__ void ldsm_x4(uint32_t* r, uint32_t addr) {
    asm volatile("ldmatrix.sync.aligned.m8n8.x4.shared.b16 {%0,%1,%2,%3}, [%4];"
                 : "=r"(r[0]), "=r"(r[1]), "=r"(r[2]), "=r"(r[3]) : "r"(addr));
}
__device__ __forceinline__ void ldsm_x4_t(uint32_t* r, uint32_t addr) {
    asm volatile("ldmatrix.sync.aligned.m8n8.x4.trans.shared.b16 {%0,%1,%2,%3}, [%4];"
                 : "=r"(r[0]), "=r"(r[1]), "=r"(r[2]), "=r"(r[3]) : "r"(addr));
}
__device__ __forceinline__ void mma_bf16(float* d, const uint32_t* a, const uint32_t* b) {
    asm volatile("mma.sync.aligned.m16n8k16.row.col.f32.bf16.bf16.f32 "
                 "{%0,%1,%2,%3}, {%4,%5,%6,%7}, {%8,%9}, {%0,%1,%2,%3};"
                 : "+f"(d[0]), "+f"(d[1]), "+f"(d[2]), "+f"(d[3])
                 : "r"(a[0]), "r"(a[1]), "r"(a[2]), "r"(a[3]), "r"(b[0]), "r"(b[1]));
}

template<bool BIAS_SEL, bool RELU, bool ADD_D, bool WF, bool WH>
__device__ __forceinline__ void gemm128_body(
    const float* __restrict__ A1, const float* __restrict__ A2,
    const float* __restrict__ B1, const float* __restrict__ B2,
    float* __restrict__ C, __half* __restrict__ Ch,
    const float* __restrict__ bias, const float* __restrict__ vsel,
    const int* __restrict__ deg, const float* __restrict__ Dm,
    int M, int KT1, int KT2, int bid) {
    __shared__ __nv_bfloat16 Ah[2][128][ASTR];
    __shared__ __nv_bfloat16 Al[2][128][ASTR];
    __shared__ __nv_bfloat16 Bh[2][BK][BSTR];
    __shared__ __nv_bfloat16 Bl[2][BK][BSTR];
    __shared__ float sBias[128];
    __shared__ float sVsel[128];

    const int tid  = threadIdx.x;
    const int lane = tid & 31;
    const int wid  = tid >> 5;
    const int wm   = wid & 3;
    const int wn   = wid >> 2;
    const int m0   = bid * 128;
    const int lda1 = KT1 * BK;
    const int lda2 = KT2 * BK;
    const int KT   = KT1 + KT2;

    if (tid < 128) {
        sBias[tid] = bias[tid];
        if (BIAS_SEL) sVsel[tid] = vsel[tid];
    }

    const int arow0 = tid >> 2;
    const int ac4   = (tid & 3) << 2;
    const int brow0 = tid >> 5;
    const int bn4   = (tid & 31) << 2;

    float4 rA[2], rB[2];

    auto loadTile = [&](int t) {
        const bool first = (t < KT1);
        #pragma unroll
        for (int i = 0; i < 2; i++) {
            int row = arow0 + i * 64;
            int m = m0 + row;
            float4 v = make_float4(0.f, 0.f, 0.f, 0.f);
            if (m < M) {
                const float* p = first ? (A1 + (size_t)m * lda1 + t * BK + ac4)
                                       : (A2 + (size_t)m * lda2 + (t - KT1) * BK + ac4);
                v = *(const float4*)p;
            }
            rA[i] = v;
        }
        #pragma unroll
        for (int i = 0; i < 2; i++) {
            int row = brow0 + i * 8;
            const float* p = first ? (B1 + (size_t)(t * BK + row) * 128 + bn4)
                                   : (B2 + (size_t)((t - KT1) * BK + row) * 128 + bn4);
            rB[i] = *(const float4*)p;
        }
    };
    auto storeTile = [&](int buf) {
        #pragma unroll
        for (int i = 0; i < 2; i++) {
            int row = arow0 + i * 64;
            const float* v = &rA[i].x;
            __nv_bfloat16 h[4], l[4];
            #pragma unroll
            for (int j = 0; j < 4; j++) split_f32(v[j], h[j], l[j]);
            *(uint2*)&Ah[buf][row][ac4] = make_uint2(pack_bf16(h[0], h[1]), pack_bf16(h[2], h[3]));
            *(uint2*)&Al[buf][row][ac4] = make_uint2(pack_bf16(l[0], l[1]), pack_bf16(l[2], l[3]));
        }
        #pragma unroll
        for (int i = 0; i < 2; i++) {
            int row = brow0 + i * 8;
            const float* v = &rB[i].x;
            __nv_bfloat16 h[4], l[4];
            #pragma unroll
            for (int j = 0; j < 4; j++) split_f32(v[j], h[j], l[j]);
            *(uint2*)&Bh[buf][row][bn4] = make_uint2(pack_bf16(h[0], h[1]), pack_bf16(h[2], h[3]));
            *(uint2*)&Bl[buf][row][bn4] = make_uint2(pack_bf16(l[0], l[1]), pack_bf16(l[2], l[3]));
        }
    };

    float d[2][8][4];
    #pragma unroll
    for (int mt = 0; mt < 2; mt++)
        #pragma unroll
        for (int nt = 0; nt < 8; nt++)
            #pragma unroll
            for (int j = 0; j < 4; j++) d[mt][nt][j] = 0.f;

    const int ar = lane & 15;
    const int ac = (lane >> 4) << 3;
    const int br = lane & 15;
    const int bc = wn * 64 + ((lane >> 4) << 3);

    loadTile(0);
    storeTile(0);
    __syncthreads();

    for (int t = 0; t < KT; t++) {
        const int cb = t & 1;
        if (t + 1 < KT) loadTile(t + 1);

        uint32_t fah[2][4], fal[2][4];
        #pragma unroll
        for (int mt = 0; mt < 2; mt++) {
            int row = wm * 32 + mt * 16 + ar;
            ldsm_x4(fah[mt], (uint32_t)__cvta_generic_to_shared(&Ah[cb][row][ac]));
            ldsm_x4(fal[mt], (uint32_t)__cvta_generic_to_shared(&Al[cb][row][ac]));
        }
        #pragma unroll
        for (int ntp = 0; ntp < 4; ntp++) {
            uint32_t fbh[4], fbl[4];
            ldsm_x4_t(fbh, (uint32_t)__cvta_generic_to_shared(&Bh[cb][br][bc + ntp * 16]));
            ldsm_x4_t(fbl, (uint32_t)__cvta_generic_to_shared(&Bl[cb][br][bc + ntp * 16]));
            #pragma unroll
            for (int mt = 0; mt < 2; mt++) {
                mma_bf16(d[mt][2 * ntp],     fah[mt], fbh);
                mma_bf16(d[mt][2 * ntp],     fal[mt], fbh);
                mma_bf16(d[mt][2 * ntp],     fah[mt], fbl);
                mma_bf16(d[mt][2 * ntp + 1], fah[mt], fbh + 2);
                mma_bf16(d[mt][2 * ntp + 1], fal[mt], fbh + 2);
                mma_bf16(d[mt][2 * ntp + 1], fah[mt], fbl + 2);
            }
        }
        if (t + 1 < KT) storeTile((t + 1) & 1);
        __syncthreads();
    }

    const int rb  = m0 + wm * 32 + (lane >> 2);
    const int cb0 = wn * 64 + (lane & 3) * 2;
    #pragma unroll
    for (int mt = 0; mt < 2; mt++) {
        #pragma unroll
        for (int h = 0; h < 2; h++) {
            int m = rb + mt * 16 + h * 8;
            if (m >= M) continue;
            float sel = 0.f;
            if (BIAS_SEL) sel = (deg[m] > 0) ? 1.f : 0.f;
            #pragma unroll
            for (int nt = 0; nt < 8; nt++) {
                int col = cb0 + nt * 8;
                float x = d[mt][nt][h * 2 + 0] + sBias[col];
                float y = d[mt][nt][h * 2 + 1] + sBias[col + 1];
                if (BIAS_SEL) { x += sel * sVsel[col]; y += sel * sVsel[col + 1]; }
                if (ADD_D) {
                    float2 dv = *(const float2*)&Dm[(size_t)m * 128 + col];
                    x += dv.x; y += dv.y;
                }
                if (RELU) { x = fmaxf(x, 0.f); y = fmaxf(y, 0.f); }
                if (WF) *(float2*)&C[(size_t)m * 128 + col] = make_float2(x, y);
                if (WH) *(__half2*)&Ch[(size_t)m * 128 + col] = __floats2half2_rn(x, y);
            }
        }
    }
}

template<bool BIAS_SEL, bool RELU, bool ADD_D, bool WF, bool WH>
__global__ void __launch_bounds__(256)
gemm128_kernel(const float* A1, const float* A2, const float* B1, const float* B2,
               float* C, __half* Ch, const float* bias, const float* vsel, const int* deg,
               const float* Dm, int M, int KT1, int KT2) {
    gemm128_body<BIAS_SEL, RELU, ADD_D, WF, WH>(A1, A2, B1, B2, C, Ch,
                                                bias, vsel, deg, Dm, M, KT1, KT2, blockIdx.x);
}

// ---------------- fused kernels ----------------
// fusedA: GEMM4 (movie_x) || deg || vec.
__global__ void __launch_bounds__(256)
fusedA_kernel(const float* __restrict__ movie_feats, const float* __restrict__ Wm, const float* __restrict__ bm,
              float* __restrict__ movie_x,
              const int* __restrict__ src, const int* __restrict__ dst,
              int* __restrict__ du, int* __restrict__ dm,
              const float* __restrict__ user_init, const float* __restrict__ Wl1_um,
              const float* __restrict__ Wr1_mu, const float* __restrict__ bl1_mu,
              float* __restrict__ vecs,
              int GA, int DEGB) {
    int bid = blockIdx.x;
    int q = bid >> 2, r = bid & 3;
    if (r == 0 && q < GA) {
        gemm128_body<false, false, false, true, false>(movie_feats, nullptr, Wm, nullptr, movie_x, nullptr,
                                                       bm, nullptr, nullptr, nullptr, cNM, cFD / BK, 0, q);
    } else {
        int before = min((bid + 3) >> 2, GA);
        int did = bid - before;
        if (did < DEGB) deg_body(src, dst, du, dm, cE, did, DEGB);
        else            vec_body(user_init, Wl1_um, Wr1_mu, bl1_mu, vecs);
    }
}

// fusedB: GEMM5 (movie_h fp32+fp16) || P1 (fp16 only) || scatter.
__global__ void __launch_bounds__(256)
fusedB_kernel(const float* __restrict__ movie_x,
              const float* __restrict__ Wr1_um, const float* __restrict__ Wl1_mu,
              float* __restrict__ movie_h, __half* __restrict__ movie_hh, __half* __restrict__ P1h,
              const float* __restrict__ bl1_um, const float* __restrict__ vsel, const int* __restrict__ deg_m,
              const float* __restrict__ zero,
              const int* __restrict__ src, const int* __restrict__ dst,
              int* __restrict__ curU, int* __restrict__ curM,
              int* __restrict__ csrU, int* __restrict__ csrM,
              int GM_, int GA, int SCB) {
    int bid = blockIdx.x;
    int q = bid >> 2, r = bid & 3;
    if (r == 0 && q < GA) {
        if (q < GM_) {
            gemm128_body<true, true, false, true, true>(movie_x, nullptr, Wr1_um, nullptr, movie_h, movie_hh,
                                                        bl1_um, vsel, deg_m, nullptr, cNM, cH / BK, 0, q);
        } else {
            gemm128_body<false, false, false, false, true>(movie_x, nullptr, Wl1_mu, nullptr, nullptr, P1h,
                                                           zero, nullptr, nullptr, nullptr, cNM, cH / BK, 0, q - GM_);
        }
    } else {
        int before = min((bid + 3) >> 2, GA);
        int did = bid - before;
        if (did < SCB) scatter_body(src, dst, curU, curM, csrU, csrM, cE, did, SCB);
    }
}

// fusedC: GEMM10 (user_o fp16, K=256) || agg_movie (fp16 gather).
__global__ void __launch_bounds__(256)
fusedC_kernel(const float* __restrict__ aggH2, const float* __restrict__ user_h,
              const float* __restrict__ Wl2_mu, const float* __restrict__ Wr2_mu,
              __half* __restrict__ user_oh, const float* __restrict__ bl2_mu,
              const int* __restrict__ offM, const int* __restrict__ csrM,
              const __half* __restrict__ user_hh, float* __restrict__ aggM2,
              int GA, int AGB) {
    int bid = blockIdx.x;
    int q = bid >> 1, r = bid & 1;
    if (r == 0 && q < GA) {
        gemm128_body<false, false, false, false, true>(aggH2, user_h, Wl2_mu, Wr2_mu, nullptr, user_oh,
                                                       bl2_mu, nullptr, nullptr, nullptr, cNU, cH / BK, cH / BK, q);
    } else {
        int before = min((bid + 1) >> 1, GA);
        int aid = bid - before;
        if (aid < AGB) agg_movie_body(offM, csrM, user_hh, aggM2, cNM, aid, AGB);
    }
}

// ---------------- final edge dot products (fp16 inputs, fp32 accumulate) ----------------
__global__ void dot_kernel(const int* __restrict__ lu, const int* __restrict__ lm,
                           const __half* __restrict__ U, const __half* __restrict__ Mo,
                           float* __restrict__ out, int EL) {
    int w    = (blockIdx.x * blockDim.x + threadIdx.x) >> 5;
    int lane = threadIdx.x & 31;
    int nw   = (gridDim.x * blockDim.x) >> 5;
    for (int i = w; i < EL; i += nw) {
        int u = lu[i];
        int m = lm[i];
        uint2 a = ((const uint2*)(U  + (size_t)u * 128))[lane];
        uint2 b = ((const uint2*)(Mo + (size_t)m * 128))[lane];
        float2 a0 = __half22float2(*(const __half2*)&a.x);
        float2 a1 = __half22float2(*(const __half2*)&a.y);
        float2 b0 = __half22float2(*(const __half2*)&b.x);
        float2 b1 = __half22float2(*(const __half2*)&b.y);
        float p = a0.x * b0.x + a0.y * b0.y + a1.x * b1.x + a1.y * b1.y;
        #pragma unroll
        for (int off = 16; off > 0; off >>= 1)
            p += __shfl_xor_sync(0xFFFFFFFFu, p, off);
        if (lane == 0) out[i] = p;
    }
}

// ---------------- launch ----------------
extern "C" void kernel_launch(void* const* d_in, const int* in_sizes, int n_in,
                              void* d_out, int out_size) {
    const float* movie_feats = (const float*)d_in[0];
    const float* user_init   = (const float*)d_in[1];
    const int*   edge_src    = (const int*)d_in[2];
    const int*   edge_dst    = (const int*)d_in[3];
    const int*   lbl_user    = (const int*)d_in[4];
    const int*   lbl_movie   = (const int*)d_in[5];
    const int wi = (n_in >= 21) ? 7 : 6;
    const float* Wm     = (const float*)d_in[wi + 0];
    const float* bm     = (const float*)d_in[wi + 1];
    const float* Wl1_um = (const float*)d_in[wi + 2];
    const float* bl1_um = (const float*)d_in[wi + 3];
    const float* Wr1_um = (const float*)d_in[wi + 4];
    const float* Wl1_mu = (const float*)d_in[wi + 5];
    const float* bl1_mu = (const float*)d_in[wi + 6];
    const float* Wr1_mu = (const float*)d_in[wi + 7];
    const float* Wl2_um = (const float*)d_in[wi + 8];
    const float* bl2_um = (const float*)d_in[wi + 9];
    const float* Wr2_um = (const float*)d_in[wi + 10];
    const float* Wl2_mu = (const float*)d_in[wi + 11];
    const float* bl2_mu = (const float*)d_in[wi + 12];
    const float* Wr2_mu = (const float*)d_in[wi + 13];
    float* out = (float*)d_out;

    float *movie_x, *movie_h, *user_h, *aggH2, *aggM2, *vecs, *zero;
    __half *movie_hh, *P1h, *user_hh, *movie_oh, *user_oh;
    int *deg_u, *deg_m, *offU, *offM, *curU, *curM, *csrU, *csrM, *partU, *partM;
    cudaGetSymbolAddress((void**)&movie_x,  g_movie_x);
    cudaGetSymbolAddress((void**)&movie_h,  g_movie_h);
    cudaGetSymbolAddress((void**)&movie_hh, g_movie_hh);
    cudaGetSymbolAddress((void**)&P1h,      g_P1h);
    cudaGetSymbolAddress((void**)&user_h,   g_user_h);
    cudaGetSymbolAddress((void**)&user_hh,  g_user_hh);
    cudaGetSymbolAddress((void**)&aggH2,    g_aggH2);
    cudaGetSymbolAddress((void**)&aggM2,    g_aggM2);
    cudaGetSymbolAddress((void**)&movie_oh, g_movie_oh);
    cudaGetSymbolAddress((void**)&user_oh,  g_user_oh);
    cudaGetSymbolAddress((void**)&vecs,     g_vecs);
    cudaGetSymbolAddress((void**)&zero,     g_zero);
    cudaGetSymbolAddress((void**)&deg_u,    g_deg_u);
    cudaGetSymbolAddress((void**)&deg_m,    g_deg_m);
    cudaGetSymbolAddress((void**)&offU,     g_offU);
    cudaGetSymbolAddress((void**)&offM,     g_offM);
    cudaGetSymbolAddress((void**)&curU,     g_curU);
    cudaGetSymbolAddress((void**)&curM,     g_curM);
    cudaGetSymbolAddress((void**)&csrU,     g_csrU);
    cudaGetSymbolAddress((void**)&csrM,     g_csrM);
    cudaGetSymbolAddress((void**)&partU,    g_partU);
    cudaGetSymbolAddress((void**)&partM,    g_partM);

    const int GM = (cNM + 127) / 128;   // 625
    const int GU = (cNU + 127) / 128;   // 1563

    // 1) zero degree counters
    zero2_kernel<<<384, 256>>>(deg_u, cNU, deg_m, cNM);

    // 2) fusedA: GEMM4 || deg || vec
    const int DEGB = 2048;
    fusedA_kernel<<<GM + DEGB + 1, 256>>>(movie_feats, Wm, bm, movie_x,
                                          edge_src, edge_dst, deg_u, deg_m,
                                          user_init, Wl1_um, Wr1_mu, bl1_mu, vecs,
                                          GM, DEGB);

    // 3) CSR offsets
    partial_kernel<<<TU + TM, 256>>>(deg_u, deg_m, partU, partM);
    scanpart_kernel<<<2, 256>>>(partU, partM);
    phase3_kernel<<<TU + TM, 256>>>(deg_u, deg_m, partU, partM, offU, curU, offM, curM);

    // 4) fusedB: GEMM5 (fp32+fp16) || P1 (fp16) || scatter
    {
        const int GA = 2 * GM;            // 1250 gemm virtual blocks
        const int grid = 4 * GA;          // 5000
        const int SCB = grid - GA;        // 3750 scatter virtual blocks
        fusedB_kernel<<<grid, 256>>>(movie_x, Wr1_um, Wl1_mu, movie_h, movie_hh, P1h,
                                     bl1_um, vecs, deg_m, zero,
                                     edge_src, edge_dst, curU, curM, csrU, csrM,
                                     GM, GA, SCB);
    }

    // 5) user-side aggregation (fp16 gathers): user_h (+fp16 copy), aggH2
    agg_user_kernel<<<4736, 256>>>(offU, csrU, P1h, movie_hh, vecs, user_h, user_hh, aggH2, cNU);

    // 6) fusedC: GEMM10 (user_o fp16, K=256 concat) || agg_movie (fp16 gather)
    {
        const int gridC = 2 * GU;
        const int AGB = gridC - GU;
        fusedC_kernel<<<gridC, 256>>>(aggH2, user_h, Wl2_mu, Wr2_mu, user_oh, bl2_mu,
                                      offM, csrM, user_hh, aggM2, GU, AGB);
    }

    // 7) GEMM9: movie_o (fp16) = aggM2 @ Wl2_um + bl2_um + movie_h @ Wr2_um
    gemm128_kernel<false, false, false, false, true><<<GM, 256>>>(
        aggM2, movie_h, Wl2_um, Wr2_um, nullptr, movie_oh, bl2_um, nullptr, nullptr, nullptr,
        cNM, cH / BK, cH / BK);

    // 8) final dot products (fp16 gathers, fp32 accumulate)
    dot_kernel<<<4736, 256>>>(lbl_user, lbl_movie, user_oh, movie_oh, out, cEL);

    (void)in_sizes; (void)out_size;
}

// round 16
// speedup vs baseline: 1.3835x; 1.0239x over previous
#include <cuda_runtime.h>
#include <cuda_bf16.h>
#include <cuda_fp16.h>
#include <cstddef>
#include <cstdint>

// Problem constants
#define cH   128
#define cNU  200000
#define cNM  80000
#define cE   2000000
#define cEL  500000
#define cFD  512

#define TILE 1024
#define TU   ((cNU + TILE - 1) / TILE)   // 196
#define TM   ((cNM + TILE - 1) / TILE)   // 79

// ---------------- scratch (device globals) ----------------
__device__ float  g_movie_x[(size_t)cNM * cH];
__device__ __half g_movie_hh[(size_t)cNM * cH];  // fp16 movie_h (gather + GEMM9 A2)
__device__ __half g_P1h[(size_t)cNM * cH];       // movie_x @ Wl1_mu, fp16
__device__ __half g_user_hh[(size_t)cNU * cH];   // fp16 user_h (gather + fusedC A2)
__device__ float  g_aggH2 [(size_t)cNU * cH];
__device__ float  g_aggM2 [(size_t)cNM * cH];
__device__ __half g_movie_oh[(size_t)cNM * cH];  // fp16 final movie embeddings
__device__ __half g_user_oh [(size_t)cNU * cH];  // fp16 final user embeddings
__device__ int    g_deg_u[cNU];
__device__ int    g_deg_m[cNM];
__device__ int    g_offU[cNU + 1];
__device__ int    g_offM[cNM + 1];
__device__ int    g_curU[cNU];
__device__ int    g_curM[cNM];
__device__ int    g_csrU[cE];
__device__ int    g_csrM[cE];
__device__ int    g_partU[TU];
__device__ int    g_partM[TM];
__device__ float  g_vecs[2 * cH];
__device__ float  g_zero[cH];

// ---------------- utility ----------------
__global__ void zero2_kernel(int* p1, int n1, int* p2, int n2) {
    int i = blockIdx.x * blockDim.x + threadIdx.x;
    int stride = gridDim.x * blockDim.x;
    for (int k = i; k < n1; k += stride) p1[k] = 0;
    for (int k = i; k < n2; k += stride) p2[k] = 0;
}

// ---- device bodies ----
__device__ __forceinline__ void deg_body(const int* __restrict__ src, const int* __restrict__ dst,
                                         int* __restrict__ du, int* __restrict__ dm,
                                         int E, int vbid, int vgrid) {
    int i = vbid * 256 + threadIdx.x;
    int stride = vgrid * 256;
    for (; i < E; i += stride) {
        atomicAdd(&du[src[i]], 1);
        atomicAdd(&dm[dst[i]], 1);
    }
}

__device__ __forceinline__ void scatter_body(const int* __restrict__ src, const int* __restrict__ dst,
                                             int* __restrict__ curU, int* __restrict__ curM,
                                             int* __restrict__ csrU, int* __restrict__ csrM,
                                             int E, int vbid, int vgrid) {
    int i = vbid * 256 + threadIdx.x;
    int stride = vgrid * 256;
    for (; i < E; i += stride) {
        int s = src[i];
        int d = dst[i];
        int p = atomicAdd(&curU[s], 1);
        csrU[p] = d;
        int q = atomicAdd(&curM[d], 1);
        csrM[q] = s;
    }
}

__device__ __forceinline__ void vec_body(const float* __restrict__ user_init,
                                         const float* __restrict__ Wl1_um,
                                         const float* __restrict__ Wr1_mu,
                                         const float* __restrict__ bl1_mu,
                                         float* __restrict__ vecs) {
    int j = threadIdx.x;
    if (j >= cH) return;
    float s1 = 0.f, s2 = 0.f;
    for (int k = 0; k < cH; k++) {
        float u = user_init[k];
        s1 = fmaf(u, Wl1_um[k * cH + j], s1);
        s2 = fmaf(u, Wr1_mu[k * cH + j], s2);
    }
    vecs[j]      = s1;
    vecs[cH + j] = bl1_mu[j] + s2;
}

// movie-side aggregation over fp16 user_h rows
__device__ __forceinline__ void agg_movie_body(const int* __restrict__ off, const int* __restrict__ csr,
                                               const __half* __restrict__ uhh,
                                               float* __restrict__ aM2, int NM, int vbid, int vgrid) {
    int w    = vbid * 8 + (threadIdx.x >> 5);
    int lane = threadIdx.x & 31;
    int nw   = vgrid * 8;
    for (int m = w; m < NM; m += nw) {
        int s = off[m], e = off[m + 1];
        float4 a1 = make_float4(0.f, 0.f, 0.f, 0.f);
        float4 a2 = make_float4(0.f, 0.f, 0.f, 0.f);
        int i = s;
        for (; i + 1 < e; i += 2) {
            int d0 = csr[i];
            int d1 = csr[i + 1];
            uint2 u0 = ((const uint2*)(uhh + (size_t)d0 * 128))[lane];
            uint2 u1 = ((const uint2*)(uhh + (size_t)d1 * 128))[lane];
            float2 f0 = __half22float2(*(const __half2*)&u0.x);
            float2 f1 = __half22float2(*(const __half2*)&u0.y);
            float2 g0 = __half22float2(*(const __half2*)&u1.x);
            float2 g1 = __half22float2(*(const __half2*)&u1.y);
            a1.x += f0.x; a1.y += f0.y; a1.z += f1.x; a1.w += f1.y;
            a2.x += g0.x; a2.y += g0.y; a2.z += g1.x; a2.w += g1.y;
        }
        if (i < e) {
            int d0 = csr[i];
            uint2 u0 = ((const uint2*)(uhh + (size_t)d0 * 128))[lane];
            float2 f0 = __half22float2(*(const __half2*)&u0.x);
            float2 f1 = __half22float2(*(const __half2*)&u0.y);
            a1.x += f0.x; a1.y += f0.y; a1.z += f1.x; a1.w += f1.y;
        }
        float sc = (e > s) ? 1.f / (float)(e - s) : 0.f;
        float4 o = make_float4((a1.x + a2.x) * sc, (a1.y + a2.y) * sc, (a1.z + a2.z) * sc, (a1.w + a2.w) * sc);
        ((float4*)(aM2 + (size_t)m * 128))[lane] = o;
    }
}

// ---- parallel scan ----
__global__ void partial_kernel(const int* __restrict__ degU, const int* __restrict__ degM,
                               int* __restrict__ partU, int* __restrict__ partM) {
    int b = blockIdx.x;
    const int* deg; int* part; int n, tile;
    if (b < TU) { deg = degU; part = partU; n = cNU; tile = b; }
    else        { deg = degM; part = partM; n = cNM; tile = b - TU; }

    int tid = threadIdx.x;
    int base = tile * TILE + tid * 4;
    int s = 0;
    #pragma unroll
    for (int j = 0; j < 4; j++) {
        int i = base + j;
        if (i < n) s += deg[i];
    }
    __shared__ int wsum[8];
    int lane = tid & 31, wid = tid >> 5;
    #pragma unroll
    for (int o = 16; o > 0; o >>= 1) s += __shfl_down_sync(0xffffffffu, s, o);
    if (lane == 0) wsum[wid] = s;
    __syncthreads();
    if (tid == 0) {
        int t = 0;
        #pragma unroll
        for (int w = 0; w < 8; w++) t += wsum[w];
        part[tile] = t;
    }
}

__global__ void scanpart_kernel(int* __restrict__ partU, int* __restrict__ partM) {
    int* part = (blockIdx.x == 0) ? partU : partM;
    int cnt   = (blockIdx.x == 0) ? TU : TM;
    int tid = threadIdx.x, lane = tid & 31, wid = tid >> 5;
    __shared__ int wsum[8];
    int v = (tid < cnt) ? part[tid] : 0;
    int x = v;
    #pragma unroll
    for (int o = 1; o < 32; o <<= 1) {
        int t = __shfl_up_sync(0xffffffffu, x, o);
        if (lane >= o) x += t;
    }
    if (lane == 31) wsum[wid] = x;
    __syncthreads();
    if (wid == 0) {
        int s = (lane < 8) ? wsum[lane] : 0;
        #pragma unroll
        for (int o = 1; o < 8; o <<= 1) {
            int t = __shfl_up_sync(0xffffffffu, s, o);
            if (lane >= o) s += t;
        }
        if (lane < 8) wsum[lane] = s;
    }
    __syncthreads();
    int incl = x + ((wid > 0) ? wsum[wid - 1] : 0);
    if (tid < cnt) part[tid] = incl - v;
}

__global__ void phase3_kernel(const int* __restrict__ degU, const int* __restrict__ degM,
                              const int* __restrict__ partU, const int* __restrict__ partM,
                              int* __restrict__ offU, int* __restrict__ curU,
                              int* __restrict__ offM, int* __restrict__ curM) {
    int b = blockIdx.x;
    const int* deg; const int* part; int* off; int* cur; int n, tile;
    if (b < TU) { deg = degU; part = partU; off = offU; cur = curU; n = cNU; tile = b; }
    else        { deg = degM; part = partM; off = offM; cur = curM; n = cNM; tile = b - TU; }

    int tid = threadIdx.x, lane = tid & 31, wid = tid >> 5;
    if (b == 0 && tid == 0) { offU[cNU] = cE; offM[cNM] = cE; }

    int base = tile * TILE + tid * 4;
    int v[4];
    int s = 0;
    #pragma unroll
    for (int j = 0; j < 4; j++) {
        int i = base + j;
        v[j] = (i < n) ? deg[i] : 0;
        s += v[j];
    }
    __shared__ int wsum[8];
    int x = s;
    #pragma unroll
    for (int o = 1; o < 32; o <<= 1) {
        int t = __shfl_up_sync(0xffffffffu, x, o);
        if (lane >= o) x += t;
    }
    if (lane == 31) wsum[wid] = x;
    __syncthreads();
    if (wid == 0) {
        int t = (lane < 8) ? wsum[lane] : 0;
        #pragma unroll
        for (int o = 1; o < 8; o <<= 1) {
            int u = __shfl_up_sync(0xffffffffu, t, o);
            if (lane >= o) t += u;
        }
        if (lane < 8) wsum[lane] = t;
    }
    __syncthreads();
    int excl = x - s + ((wid > 0) ? wsum[wid - 1] : 0);
    int run = part[tile] + excl;
    #pragma unroll
    for (int j = 0; j < 4; j++) {
        int i = base + j;
        if (i < n) { off[i] = run; cur[i] = run; run += v[j]; }
    }
}

// ---------------- user-side aggregation: gather fp16 P1 + movie_h ----------------
// user_hh = fp16(relu(mean P1[d] + cb1)) ; aggH2 = mean movie_h[d] (fp32)
__global__ void agg_user_kernel(const int* __restrict__ off, const int* __restrict__ csr,
                                const __half* __restrict__ P1h, const __half* __restrict__ MHh,
                                const float* __restrict__ vecs,
                                __half* __restrict__ user_hh, float* __restrict__ aggH2, int NU) {
    int w    = (blockIdx.x * blockDim.x + threadIdx.x) >> 5;
    int lane = threadIdx.x & 31;
    int nw   = (gridDim.x * blockDim.x) >> 5;
    float4 c1 = ((const float4*)(vecs + cH))[lane];
    for (int u = w; u < NU; u += nw) {
        int s = off[u], e = off[u + 1];
        float4 a1 = make_float4(0.f, 0.f, 0.f, 0.f);
        float4 a2 = make_float4(0.f, 0.f, 0.f, 0.f);
        float4 a3 = make_float4(0.f, 0.f, 0.f, 0.f);
        float4 a4 = make_float4(0.f, 0.f, 0.f, 0.f);
        int i = s;
        for (; i + 1 < e; i += 2) {
            int d0 = csr[i];
            int d1 = csr[i + 1];
            uint2 x0 = ((const uint2*)(P1h + (size_t)d0 * 128))[lane];
            uint2 h0 = ((const uint2*)(MHh + (size_t)d0 * 128))[lane];
            uint2 x1 = ((const uint2*)(P1h + (size_t)d1 * 128))[lane];
            uint2 h1 = ((const uint2*)(MHh + (size_t)d1 * 128))[lane];
            float2 p, q;
            p = __half22float2(*(const __half2*)&x0.x); q = __half22float2(*(const __half2*)&x0.y);
            a1.x += p.x; a1.y += p.y; a1.z += q.x; a1.w += q.y;
            p = __half22float2(*(const __half2*)&h0.x); q = __half22float2(*(const __half2*)&h0.y);
            a2.x += p.x; a2.y += p.y; a2.z += q.x; a2.w += q.y;
            p = __half22float2(*(const __half2*)&x1.x); q = __half22float2(*(const __half2*)&x1.y);
            a3.x += p.x; a3.y += p.y; a3.z += q.x; a3.w += q.y;
            p = __half22float2(*(const __half2*)&h1.x); q = __half22float2(*(const __half2*)&h1.y);
            a4.x += p.x; a4.y += p.y; a4.z += q.x; a4.w += q.y;
        }
        if (i < e) {
            int d0 = csr[i];
            uint2 x0 = ((const uint2*)(P1h + (size_t)d0 * 128))[lane];
            uint2 h0 = ((const uint2*)(MHh + (size_t)d0 * 128))[lane];
            float2 p, q;
            p = __half22float2(*(const __half2*)&x0.x); q = __half22float2(*(const __half2*)&x0.y);
            a1.x += p.x; a1.y += p.y; a1.z += q.x; a1.w += q.y;
            p = __half22float2(*(const __half2*)&h0.x); q = __half22float2(*(const __half2*)&h0.y);
            a2.x += p.x; a2.y += p.y; a2.z += q.x; a2.w += q.y;
        }
        float sc = (e > s) ? 1.f / (float)(e - s) : 0.f;
        float4 o1 = make_float4(fmaxf((a1.x + a3.x) * sc + c1.x, 0.f),
                                fmaxf((a1.y + a3.y) * sc + c1.y, 0.f),
                                fmaxf((a1.z + a3.z) * sc + c1.z, 0.f),
                                fmaxf((a1.w + a3.w) * sc + c1.w, 0.f));
        float4 o2 = make_float4((a2.x + a4.x) * sc, (a2.y + a4.y) * sc, (a2.z + a4.z) * sc, (a2.w + a4.w) * sc);
        ((float4*)(aggH2 + (size_t)u * 128))[lane] = o2;
        uint2 hh;
        *(__half2*)&hh.x = __floats2half2_rn(o1.x, o1.y);
        *(__half2*)&hh.y = __floats2half2_rn(o1.z, o1.w);
        ((uint2*)(user_hh + (size_t)u * 128))[lane] = hh;
    }
}

// ---------------- tensor-core SGEMM via split-bf16, fp32 or fp16 A-operands ----------------
#define BK   16
#define ASTR 24
#define BSTR 136

__device__ __forceinline__ unsigned pack_bf16(__nv_bfloat16 a, __nv_bfloat16 b) {
    __nv_bfloat162 t = __halves2bfloat162(a, b);
    return reinterpret_cast<unsigned&>(t);
}
__device__ __forceinline__ void split_f32(float x, __nv_bfloat16& h, __nv_bfloat16& l) {
    h = __float2bfloat16(x);
    l = __float2bfloat16(x - __bfloat162float(h));
}
__device__ __forceinline__ void ldsm_x4(uint32_t* r, uint32_t addr) {
    asm volatile("ldmatrix.sync.aligned.m8n8.x4.shared.b16 {%0,%1,%2,%3}, [%4];"
                 : "=r"(r[0]), "=r"(r[1]), "=r"(r[2]), "=r"(r[3]) : "r"(addr));
}
__device__ __forceinline__ void ldsm_x4_t(uint32_t* r, uint32_t addr) {
    asm volatile("ldmatrix.sync.aligned.m8n8.x4.trans.shared.b16 {%0,%1,%2,%3}, [%4];"
                 : "=r"(r[0]), "=r"(r[1]), "=r"(r[2]), "=r"(r[3]) : "r"(addr));
}
__device__ __forceinline__ void mma_bf16(float* d, const uint32_t* a, const uint32_t* b) {
    asm volatile("mma.sync.aligned.m16n8k16.row.col.f32.bf16.bf16.f32 "
                 "{%0,%1,%2,%3}, {%4,%5,%6,%7}, {%8,%9}, {%0,%1,%2,%3};"
                 : "+f"(d[0]), "+f"(d[1]), "+f"(d[2]), "+f"(d[3])
                 : "r"(a[0]), "r"(a[1]), "r"(a[2]), "r"(a[3]), "r"(b[0]), "r"(b[1]));
}

// A1H/A2H: A1/A2 are fp16 (else fp32). B always fp32.
template<bool BIAS_SEL, bool RELU, bool ADD_D, bool WF, bool WH, bool A1H, bool A2H>
__device__ __forceinline__ void gemm128_body(
    const void* __restrict__ A1, const void* __restrict__ A2,
    const float* __restrict__ B1, const float* __restrict__ B2,
    float* __restrict__ C, __half* __restrict__ Ch,
    const float* __restrict__ bias, const float* __restrict__ vsel,
    const int* __restrict__ deg, const float* __restrict__ Dm,
    int M, int KT1, int KT2, int bid) {
    __shared__ __nv_bfloat16 Ah[2][128][ASTR];
    __shared__ __nv_bfloat16 Al[2][128][ASTR];
    __shared__ __nv_bfloat16 Bh[2][BK][BSTR];
    __shared__ __nv_bfloat16 Bl[2][BK][BSTR];
    __shared__ float sBias[128];
    __shared__ float sVsel[128];

    const int tid  = threadIdx.x;
    const int lane = tid & 31;
    const int wid  = tid >> 5;
    const int wm   = wid & 3;
    const int wn   = wid >> 2;
    const int m0   = bid * 128;
    const int lda1 = KT1 * BK;
    const int lda2 = KT2 * BK;
    const int KT   = KT1 + KT2;

    if (tid < 128) {
        sBias[tid] = bias[tid];
        if (BIAS_SEL) sVsel[tid] = vsel[tid];
    }

    const int arow0 = tid >> 2;
    const int ac4   = (tid & 3) << 2;
    const int brow0 = tid >> 5;
    const int bn4   = (tid & 31) << 2;

    float4 rA[2], rB[2];

    auto loadTile = [&](int t) {
        const bool first = (t < KT1);
        #pragma unroll
        for (int i = 0; i < 2; i++) {
            int row = arow0 + i * 64;
            int m = m0 + row;
            float4 v = make_float4(0.f, 0.f, 0.f, 0.f);
            if (m < M) {
                if (first) {
                    if (A1H) {
                        uint2 u = *(const uint2*)((const __half*)A1 + (size_t)m * lda1 + t * BK + ac4);
                        float2 lo = __half22float2(*(const __half2*)&u.x);
                        float2 hi = __half22float2(*(const __half2*)&u.y);
                        v = make_float4(lo.x, lo.y, hi.x, hi.y);
                    } else {
                        v = *(const float4*)((const float*)A1 + (size_t)m * lda1 + t * BK + ac4);
                    }
                } else {
                    if (A2H) {
                        uint2 u = *(const uint2*)((const __half*)A2 + (size_t)m * lda2 + (t - KT1) * BK + ac4);
                        float2 lo = __half22float2(*(const __half2*)&u.x);
                        float2 hi = __half22float2(*(const __half2*)&u.y);
                        v = make_float4(lo.x, lo.y, hi.x, hi.y);
                    } else {
                        v = *(const float4*)((const float*)A2 + (size_t)m * lda2 + (t - KT1) * BK + ac4);
                    }
                }
            }
            rA[i] = v;
        }
        #pragma unroll
        for (int i = 0; i < 2; i++) {
            int row = brow0 + i * 8;
            const float* p = first ? (B1 + (size_t)(t * BK + row) * 128 + bn4)
                                   : (B2 + (size_t)((t - KT1) * BK + row) * 128 + bn4);
            rB[i] = *(const float4*)p;
        }
    };
    auto storeTile = [&](int buf) {
        #pragma unroll
        for (int i = 0; i < 2; i++) {
            int row = arow0 + i * 64;
            const float* v = &rA[i].x;
            __nv_bfloat16 h[4], l[4];
            #pragma unroll
            for (int j = 0; j < 4; j++) split_f32(v[j], h[j], l[j]);
            *(uint2*)&Ah[buf][row][ac4] = make_uint2(pack_bf16(h[0], h[1]), pack_bf16(h[2], h[3]));
            *(uint2*)&Al[buf][row][ac4] = make_uint2(pack_bf16(l[0], l[1]), pack_bf16(l[2], l[3]));
        }
        #pragma unroll
        for (int i = 0; i < 2; i++) {
            int row = brow0 + i * 8;
            const float* v = &rB[i].x;
            __nv_bfloat16 h[4], l[4];
            #pragma unroll
            for (int j = 0; j < 4; j++) split_f32(v[j], h[j], l[j]);
            *(uint2*)&Bh[buf][row][bn4] = make_uint2(pack_bf16(h[0], h[1]), pack_bf16(h[2], h[3]));
            *(uint2*)&Bl[buf][row][bn4] = make_uint2(pack_bf16(l[0], l[1]), pack_bf16(l[2], l[3]));
        }
    };

    float d[2][8][4];
    #pragma unroll
    for (int mt = 0; mt < 2; mt++)
        #pragma unroll
        for (int nt = 0; nt < 8; nt++)
            #pragma unroll
            for (int j = 0; j < 4; j++) d[mt][nt][j] = 0.f;

    const int ar = lane & 15;
    const int ac = (lane >> 4) << 3;
    const int br = lane & 15;
    const int bc = wn * 64 + ((lane >> 4) << 3);

    loadTile(0);
    storeTile(0);
    __syncthreads();

    for (int t = 0; t < KT; t++) {
        const int cb = t & 1;
        if (t + 1 < KT) loadTile(t + 1);

        uint32_t fah[2][4], fal[2][4];
        #pragma unroll
        for (int mt = 0; mt < 2; mt++) {
            int row = wm * 32 + mt * 16 + ar;
            ldsm_x4(fah[mt], (uint32_t)__cvta_generic_to_shared(&Ah[cb][row][ac]));
            ldsm_x4(fal[mt], (uint32_t)__cvta_generic_to_shared(&Al[cb][row][ac]));
        }
        #pragma unroll
        for (int ntp = 0; ntp < 4; ntp++) {
            uint32_t fbh[4], fbl[4];
            ldsm_x4_t(fbh, (uint32_t)__cvta_generic_to_shared(&Bh[cb][br][bc + ntp * 16]));
            ldsm_x4_t(fbl, (uint32_t)__cvta_generic_to_shared(&Bl[cb][br][bc + ntp * 16]));
            #pragma unroll
            for (int mt = 0; mt < 2; mt++) {
                mma_bf16(d[mt][2 * ntp],     fah[mt], fbh);
                mma_bf16(d[mt][2 * ntp],     fal[mt], fbh);
                mma_bf16(d[mt][2 * ntp],     fah[mt], fbl);
                mma_bf16(d[mt][2 * ntp + 1], fah[mt], fbh + 2);
                mma_bf16(d[mt][2 * ntp + 1], fal[mt], fbh + 2);
                mma_bf16(d[mt][2 * ntp + 1], fah[mt], fbl + 2);
            }
        }
        if (t + 1 < KT) storeTile((t + 1) & 1);
        __syncthreads();
    }

    const int rb  = m0 + wm * 32 + (lane >> 2);
    const int cb0 = wn * 64 + (lane & 3) * 2;
    #pragma unroll
    for (int mt = 0; mt < 2; mt++) {
        #pragma unroll
        for (int h = 0; h < 2; h++) {
            int m = rb + mt * 16 + h * 8;
            if (m >= M) continue;
            float sel = 0.f;
            if (BIAS_SEL) sel = (deg[m] > 0) ? 1.f : 0.f;
            #pragma unroll
            for (int nt = 0; nt < 8; nt++) {
                int col = cb0 + nt * 8;
                float x = d[mt][nt][h * 2 + 0] + sBias[col];
                float y = d[mt][nt][h * 2 + 1] + sBias[col + 1];
                if (BIAS_SEL) { x += sel * sVsel[col]; y += sel * sVsel[col + 1]; }
                if (ADD_D) {
                    float2 dv = *(const float2*)&Dm[(size_t)m * 128 + col];
                    x += dv.x; y += dv.y;
                }
                if (RELU) { x = fmaxf(x, 0.f); y = fmaxf(y, 0.f); }
                if (WF) *(float2*)&C[(size_t)m * 128 + col] = make_float2(x, y);
                if (WH) *(__half2*)&Ch[(size_t)m * 128 + col] = __floats2half2_rn(x, y);
            }
        }
    }
}

template<bool BIAS_SEL, bool RELU, bool ADD_D, bool WF, bool WH, bool A1H, bool A2H>
__global__ void __launch_bounds__(256)
gemm128_kernel(const void* A1, const void* A2, const float* B1, const float* B2,
               float* C, __half* Ch, const float* bias, const float* vsel, const int* deg,
               const float* Dm, int M, int KT1, int KT2) {
    gemm128_body<BIAS_SEL, RELU, ADD_D, WF, WH, A1H, A2H>(A1, A2, B1, B2, C, Ch,
                                                          bias, vsel, deg, Dm, M, KT1, KT2, blockIdx.x);
}

// ---------------- fused kernels ----------------
// fusedA: GEMM4 (movie_x) || deg || vec.
__global__ void __launch_bounds__(256)
fusedA_kernel(const float* __restrict__ movie_feats, const float* __restrict__ Wm, const float* __restrict__ bm,
              float* __restrict__ movie_x,
              const int* __restrict__ src, const int* __restrict__ dst,
              int* __restrict__ du, int* __restrict__ dm,
              const float* __restrict__ user_init, const float* __restrict__ Wl1_um,
              const float* __restrict__ Wr1_mu, const float* __restrict__ bl1_mu,
              float* __restrict__ vecs,
              int GA, int DEGB) {
    int bid = blockIdx.x;
    int q = bid >> 2, r = bid & 3;
    if (r == 0 && q < GA) {
        gemm128_body<false, false, false, true, false, false, false>(
            movie_feats, nullptr, Wm, nullptr, movie_x, nullptr,
            bm, nullptr, nullptr, nullptr, cNM, cFD / BK, 0, q);
    } else {
        int before = min((bid + 3) >> 2, GA);
        int did = bid - before;
        if (did < DEGB) deg_body(src, dst, du, dm, cE, did, DEGB);
        else            vec_body(user_init, Wl1_um, Wr1_mu, bl1_mu, vecs);
    }
}

// fusedB: GEMM5 (movie_hh fp16 only) || P1 (fp16) || scatter.
__global__ void __launch_bounds__(256)
fusedB_kernel(const float* __restrict__ movie_x,
              const float* __restrict__ Wr1_um, const float* __restrict__ Wl1_mu,
              __half* __restrict__ movie_hh, __half* __restrict__ P1h,
              const float* __restrict__ bl1_um, const float* __restrict__ vsel, const int* __restrict__ deg_m,
              const float* __restrict__ zero,
              const int* __restrict__ src, const int* __restrict__ dst,
              int* __restrict__ curU, int* __restrict__ curM,
              int* __restrict__ csrU, int* __restrict__ csrM,
              int GM_, int GA, int SCB) {
    int bid = blockIdx.x;
    int q = bid >> 2, r = bid & 3;
    if (r == 0 && q < GA) {
        if (q < GM_) {
            gemm128_body<true, true, false, false, true, false, false>(
                movie_x, nullptr, Wr1_um, nullptr, nullptr, movie_hh,
                bl1_um, vsel, deg_m, nullptr, cNM, cH / BK, 0, q);
        } else {
            gemm128_body<false, false, false, false, true, false, false>(
                movie_x, nullptr, Wl1_mu, nullptr, nullptr, P1h,
                zero, nullptr, nullptr, nullptr, cNM, cH / BK, 0, q - GM_);
        }
    } else {
        int before = min((bid + 3) >> 2, GA);
        int did = bid - before;
        if (did < SCB) scatter_body(src, dst, curU, curM, csrU, csrM, cE, did, SCB);
    }
}

// fusedC: GEMM10 (user_oh = aggH2@Wl2_mu + bl2_mu + user_hh@Wr2_mu, K=256, A2 fp16) || agg_movie.
__global__ void __launch_bounds__(256)
fusedC_kernel(const float* __restrict__ aggH2, const __half* __restrict__ user_hh,
              const float* __restrict__ Wl2_mu, const float* __restrict__ Wr2_mu,
              __half* __restrict__ user_oh, const float* __restrict__ bl2_mu,
              const int* __restrict__ offM, const int* __restrict__ csrM,
              float* __restrict__ aggM2,
              int GA, int AGB) {
    int bid = blockIdx.x;
    int q = bid >> 1, r = bid & 1;
    if (r == 0 && q < GA) {
        gemm128_body<false, false, false, false, true, false, true>(
            aggH2, user_hh, Wl2_mu, Wr2_mu, nullptr, user_oh,
            bl2_mu, nullptr, nullptr, nullptr, cNU, cH / BK, cH / BK, q);
    } else {
        int before = min((bid + 1) >> 1, GA);
        int aid = bid - before;
        if (aid < AGB) agg_movie_body(offM, csrM, user_hh, aggM2, cNM, aid, AGB);
    }
}

// ---------------- final edge dot products (fp16 inputs, fp32 accumulate) ----------------
__global__ void dot_kernel(const int* __restrict__ lu, const int* __restrict__ lm,
                           const __half* __restrict__ U, const __half* __restrict__ Mo,
                           float* __restrict__ out, int EL) {
    int w    = (blockIdx.x * blockDim.x + threadIdx.x) >> 5;
    int lane = threadIdx.x & 31;
    int nw   = (gridDim.x * blockDim.x) >> 5;
    for (int i = w; i < EL; i += nw) {
        int u = lu[i];
        int m = lm[i];
        uint2 a = ((const uint2*)(U  + (size_t)u * 128))[lane];
        uint2 b = ((const uint2*)(Mo + (size_t)m * 128))[lane];
        float2 a0 = __half22float2(*(const __half2*)&a.x);
        float2 a1 = __half22float2(*(const __half2*)&a.y);
        float2 b0 = __half22float2(*(const __half2*)&b.x);
        float2 b1 = __half22float2(*(const __half2*)&b.y);
        float p = a0.x * b0.x + a0.y * b0.y + a1.x * b1.x + a1.y * b1.y;
        #pragma unroll
        for (int off = 16; off > 0; off >>= 1)
            p += __shfl_xor_sync(0xFFFFFFFFu, p, off);
        if (lane == 0) out[i] = p;
    }
}

// ---------------- launch ----------------
extern "C" void kernel_launch(void* const* d_in, const int* in_sizes, int n_in,
                              void* d_out, int out_size) {
    const float* movie_feats = (const float*)d_in[0];
    const float* user_init   = (const float*)d_in[1];
    const int*   edge_src    = (const int*)d_in[2];
    const int*   edge_dst    = (const int*)d_in[3];
    const int*   lbl_user    = (const int*)d_in[4];
    const int*   lbl_movie   = (const int*)d_in[5];
    const int wi = (n_in >= 21) ? 7 : 6;
    const float* Wm     = (const float*)d_in[wi + 0];
    const float* bm     = (const float*)d_in[wi + 1];
    const float* Wl1_um = (const float*)d_in[wi + 2];
    const float* bl1_um = (const float*)d_in[wi + 3];
    const float* Wr1_um = (const float*)d_in[wi + 4];
    const float* Wl1_mu = (const float*)d_in[wi + 5];
    const float* bl1_mu = (const float*)d_in[wi + 6];
    const float* Wr1_mu = (const float*)d_in[wi + 7];
    const float* Wl2_um = (const float*)d_in[wi + 8];
    const float* bl2_um = (const float*)d_in[wi + 9];
    const float* Wr2_um = (const float*)d_in[wi + 10];
    const float* Wl2_mu = (const float*)d_in[wi + 11];
    const float* bl2_mu = (const float*)d_in[wi + 12];
    const float* Wr2_mu = (const float*)d_in[wi + 13];
    float* out = (float*)d_out;

    float *movie_x, *aggH2, *aggM2, *vecs, *zero;
    __half *movie_hh, *P1h, *user_hh, *movie_oh, *user_oh;
    int *deg_u, *deg_m, *offU, *offM, *curU, *curM, *csrU, *csrM, *partU, *partM;
    cudaGetSymbolAddress((void**)&movie_x,  g_movie_x);
    cudaGetSymbolAddress((void**)&movie_hh, g_movie_hh);
    cudaGetSymbolAddress((void**)&P1h,      g_P1h);
    cudaGetSymbolAddress((void**)&user_hh,  g_user_hh);
    cudaGetSymbolAddress((void**)&aggH2,    g_aggH2);
    cudaGetSymbolAddress((void**)&aggM2,    g_aggM2);
    cudaGetSymbolAddress((void**)&movie_oh, g_movie_oh);
    cudaGetSymbolAddress((void**)&user_oh,  g_user_oh);
    cudaGetSymbolAddress((void**)&vecs,     g_vecs);
    cudaGetSymbolAddress((void**)&zero,     g_zero);
    cudaGetSymbolAddress((void**)&deg_u,    g_deg_u);
    cudaGetSymbolAddress((void**)&deg_m,    g_deg_m);
    cudaGetSymbolAddress((void**)&offU,     g_offU);
    cudaGetSymbolAddress((void**)&offM,     g_offM);
    cudaGetSymbolAddress((void**)&curU,     g_curU);
    cudaGetSymbolAddress((void**)&curM,     g_curM);
    cudaGetSymbolAddress((void**)&csrU,     g_csrU);
    cudaGetSymbolAddress((void**)&csrM,     g_csrM);
    cudaGetSymbolAddress((void**)&partU,    g_partU);
    cudaGetSymbolAddress((void**)&partM,    g_partM);

    const int GM = (cNM + 127) / 128;   // 625
    const int GU = (cNU + 127) / 128;   // 1563

    // 1) zero degree counters
    zero2_kernel<<<384, 256>>>(deg_u, cNU, deg_m, cNM);

    // 2) fusedA: GEMM4 || deg || vec
    const int DEGB = 2048;
    fusedA_kernel<<<GM + DEGB + 1, 256>>>(movie_feats, Wm, bm, movie_x,
                                          edge_src, edge_dst, deg_u, deg_m,
                                          user_init, Wl1_um, Wr1_mu, bl1_mu, vecs,
                                          GM, DEGB);

    // 3) CSR offsets
    partial_kernel<<<TU + TM, 256>>>(deg_u, deg_m, partU, partM);
    scanpart_kernel<<<2, 256>>>(partU, partM);
    phase3_kernel<<<TU + TM, 256>>>(deg_u, deg_m, partU, partM, offU, curU, offM, curM);

    // 4) fusedB: GEMM5 (fp16 out) || P1 (fp16) || scatter
    {
        const int GA = 2 * GM;            // 1250 gemm virtual blocks
        const int grid = 4 * GA;          // 5000
        const int SCB = grid - GA;        // 3750 scatter virtual blocks
        fusedB_kernel<<<grid, 256>>>(movie_x, Wr1_um, Wl1_mu, movie_hh, P1h,
                                     bl1_um, vecs, deg_m, zero,
                                     edge_src, edge_dst, curU, curM, csrU, csrM,
                                     GM, GA, SCB);
    }

    // 5) user-side aggregation (fp16 gathers): user_hh (fp16), aggH2 (fp32)
    agg_user_kernel<<<4736, 256>>>(offU, csrU, P1h, movie_hh, vecs, user_hh, aggH2, cNU);

    // 6) fusedC: GEMM10 (user_oh, K=256, A2=fp16 user_hh) || agg_movie (fp16 gather)
    {
        const int gridC = 2 * GU;
        const int AGB = gridC - GU;
        fusedC_kernel<<<gridC, 256>>>(aggH2, user_hh, Wl2_mu, Wr2_mu, user_oh, bl2_mu,
                                      offM, csrM, aggM2, GU, AGB);
    }

    // 7) GEMM9: movie_oh = aggM2 @ Wl2_um + bl2_um + movie_hh(fp16) @ Wr2_um
    gemm128_kernel<false, false, false, false, true, false, true><<<GM, 256>>>(
        aggM2, movie_hh, Wl2_um, Wr2_um, nullptr, movie_oh, bl2_um, nullptr, nullptr, nullptr,
        cNM, cH / BK, cH / BK);

    // 8) final dot products (fp16 gathers, fp32 accumulate)
    dot_kernel<<<4736, 256>>>(lbl_user, lbl_movie, user_oh, movie_oh, out, cEL);

    (void)in_sizes; (void)out_size;
}